// round 4
// baseline (speedup 1.0000x reference)
#include <cuda_runtime.h>
#include <math.h>

#define NRES 512
#define CS   384
#define CZ   128
#define NH   12
#define OUTD 2112
#define HF   176

// ---------------- scratch ----------------
__device__ alignas(16) float g_q [NRES*192];
__device__ alignas(16) float g_k [NRES*192];
__device__ alignas(16) float g_v [NRES*192];
__device__ alignas(16) float g_qp[NRES*144];
__device__ alignas(16) float g_kp[NRES*144];
__device__ alignas(16) float g_vp[NRES*288];
__device__ alignas(16) float g_qg[NRES*144];
__device__ alignas(16) float g_kg[NRES*144];
__device__ alignas(16) float g_vg[NRES*288];
__device__ alignas(16) float g_attn[(size_t)NRES*NRES*NH];
__device__ alignas(16) float g_feats[(size_t)NRES*OUTD];
__device__ alignas(16) float g_part[(size_t)4*NRES*CS];

// ---------------- generic tiled SGEMM (64x64x16, 256 thr, 4x4 micro) ----------
__global__ void k_sgemm(const float* __restrict__ A, const float* __restrict__ B,
                        const float* __restrict__ bias, float* __restrict__ C,
                        int Nc, int K, int kLen)
{
    __shared__ alignas(16) float As[16][64];
    __shared__ alignas(16) float Bs[16][64];
    const int tid = threadIdx.x;
    const int tx = tid & 15, ty = tid >> 4;
    const int bm = blockIdx.y * 64, bn = blockIdx.x * 64;
    const int k0base = blockIdx.z * kLen;
    C += (size_t)blockIdx.z * (size_t)(gridDim.y * 64) * Nc;

    const int am  = tid >> 2, akq = tid & 3;
    const int bkk = tid >> 4, bn4 = tid & 15;

    float acc[4][4];
#pragma unroll
    for (int i = 0; i < 4; i++)
#pragma unroll
        for (int j = 0; j < 4; j++) acc[i][j] = 0.f;

    for (int kt = 0; kt < kLen; kt += 16) {
        const int k0 = k0base + kt;
        float4 av = *(const float4*)(A + (size_t)(bm + am) * K + k0 + akq * 4);
        As[akq*4+0][am] = av.x; As[akq*4+1][am] = av.y;
        As[akq*4+2][am] = av.z; As[akq*4+3][am] = av.w;
        float4 bv = make_float4(0.f,0.f,0.f,0.f);
        const int col = bn + bn4 * 4;
        if (col < Nc) bv = *(const float4*)(B + (size_t)(k0 + bkk) * Nc + col);
        *(float4*)&Bs[bkk][bn4*4] = bv;
        __syncthreads();
#pragma unroll
        for (int kk = 0; kk < 16; kk++) {
            float4 a = *(const float4*)&As[kk][ty*4];
            float4 b = *(const float4*)&Bs[kk][tx*4];
            acc[0][0]=fmaf(a.x,b.x,acc[0][0]); acc[0][1]=fmaf(a.x,b.y,acc[0][1]);
            acc[0][2]=fmaf(a.x,b.z,acc[0][2]); acc[0][3]=fmaf(a.x,b.w,acc[0][3]);
            acc[1][0]=fmaf(a.y,b.x,acc[1][0]); acc[1][1]=fmaf(a.y,b.y,acc[1][1]);
            acc[1][2]=fmaf(a.y,b.z,acc[1][2]); acc[1][3]=fmaf(a.y,b.w,acc[1][3]);
            acc[2][0]=fmaf(a.z,b.x,acc[2][0]); acc[2][1]=fmaf(a.z,b.y,acc[2][1]);
            acc[2][2]=fmaf(a.z,b.z,acc[2][2]); acc[2][3]=fmaf(a.z,b.w,acc[2][3]);
            acc[3][0]=fmaf(a.w,b.x,acc[3][0]); acc[3][1]=fmaf(a.w,b.y,acc[3][1]);
            acc[3][2]=fmaf(a.w,b.z,acc[3][2]); acc[3][3]=fmaf(a.w,b.w,acc[3][3]);
        }
        __syncthreads();
    }
#pragma unroll
    for (int i = 0; i < 4; i++) {
        const int row = bm + ty * 4 + i;
#pragma unroll
        for (int j = 0; j < 4; j++) {
            const int col = bn + tx * 4 + j;
            if (col < Nc) {
                float vv = acc[i][j];
                if (bias) vv += bias[col];
                C[(size_t)row * Nc + col] = vv;
            }
        }
    }
}

// ---------------- local -> global points ----------------
__global__ void k_points(const float* __restrict__ rot, const float* __restrict__ trans)
{
    const int n = blockIdx.x;
    __shared__ float R[9], T[3];
    if (threadIdx.x < 9) R[threadIdx.x] = rot[n*9 + threadIdx.x];
    if (threadIdx.x < 3) T[threadIdx.x] = trans[n*3 + threadIdx.x];
    __syncthreads();
    const int t = threadIdx.x;  // 0..191
    const float* src; float* dst;
    if (t < 48)       { src = g_qp + n*144 + t*3;      dst = g_qg + n*144 + t*3; }
    else if (t < 96)  { src = g_kp + n*144 + (t-48)*3; dst = g_kg + n*144 + (t-48)*3; }
    else              { src = g_vp + n*288 + (t-96)*3; dst = g_vg + n*288 + (t-96)*3; }
    const float p0 = src[0], p1 = src[1], p2 = src[2];
    dst[0] = fmaf(R[0],p0, fmaf(R[1],p1, fmaf(R[2],p2, T[0])));
    dst[1] = fmaf(R[3],p0, fmaf(R[4],p1, fmaf(R[5],p2, T[1])));
    dst[2] = fmaf(R[6],p0, fmaf(R[7],p1, fmaf(R[8],p2, T[2])));
}

// ---------------- fused logits ----------------
#define LO_WBT   0        // 1536
#define LO_EMB   1536     // 768
#define LO_PH    2304     // 36
#define LO_BB    2340     // 12
#define LO_HW    2352     // 12
#define LO_QS    2364     // 384
#define LO_QGS   2748     // 288
#define LO_TS    3036     // 8
#define LO_KS    3044     // 32*196
#define LO_KGS   9316     // 32*145
#define LO_KTS   13956    // 96
#define LO_ZS    14052    // 32*132
#define LO_END   18276
__global__ void k_logits(const float* __restrict__ z, const float* __restrict__ trans,
                         const float* __restrict__ Wb, const float* __restrict__ bb,
                         const float* __restrict__ emb, const float* __restrict__ sl,
                         const float* __restrict__ hw)
{
    extern __shared__ float sm[];
    const int tid = threadIdx.x;       // 192 threads
    const int n0 = blockIdx.y * 2;
    const int mh = blockIdx.x;

    for (int i = tid; i < 1536; i += 192) {
        const int h = i >> 7, c = i & 127;
        sm[LO_WBT + i] = Wb[c*NH + h];
    }
    for (int i = tid; i < 768; i += 192) sm[LO_EMB + i] = emb[i];
    if (tid < 12) {
        sm[LO_BB + tid] = bb[tid];
        sm[LO_HW + tid] = hw[tid];
        const float e0 = expf(sl[tid]), e1 = expf(sl[12+tid]), e2 = expf(sl[24+tid]);
        const float inv = 1.0f / (e0 + e1 + e2);
        sm[LO_PH + tid] = e0*inv; sm[LO_PH + 12 + tid] = e1*inv; sm[LO_PH + 24 + tid] = e2*inv;
    }
    for (int i = tid; i < 384; i += 192) sm[LO_QS  + i] = g_q [n0*192 + i];
    for (int i = tid; i < 288; i += 192) sm[LO_QGS + i] = g_qg[n0*144 + i];
    if (tid < 6) sm[LO_TS + tid] = trans[n0*3 + tid];
    __syncthreads();

    const int ml = tid & 31;
    const int hp = tid >> 5;
    const int h0 = hp * 2, h1 = h0 + 1;

    for (int mt = 0; mt < 8; mt++) {
        const int m0 = mh * 256 + mt * 32;
        for (int j = 0; j < 32; j++) sm[LO_KS + j*196 + tid] = g_k[(m0+j)*192 + tid];
        for (int i = tid; i < 32*144; i += 192) { const int mm = i/144, x = i%144; sm[LO_KGS + mm*145 + x] = g_kg[(m0+mm)*144 + x]; }
        for (int i = tid; i < 96; i += 192) sm[LO_KTS + i] = trans[m0*3 + i];
        __syncthreads();

        for (int ng = 0; ng < 2; ng++) {
            const int n = n0 + ng;
            const float* zsrc = z + ((size_t)n * NRES + m0) * CZ;
            for (int i = tid; i < 4096; i += 192) { const int mm = i >> 7, c = i & 127; sm[LO_ZS + mm*132 + c] = zsrc[i]; }
            __syncthreads();

            // pair bias: z . WbT (8 independent chains)
            const float4* zr = (const float4*)(sm + LO_ZS + ml*132);
            const float4* w0 = (const float4*)(sm + LO_WBT + h0*128);
            const float4* w1 = (const float4*)(sm + LO_WBT + h1*128);
            float p0x=0,p0y=0,p0z=0,p0w=0, p1x=0,p1y=0,p1z=0,p1w=0;
#pragma unroll 8
            for (int q2 = 0; q2 < 32; q2++) {
                const float4 zv = zr[q2], a = w0[q2], b = w1[q2];
                p0x=fmaf(zv.x,a.x,p0x); p0y=fmaf(zv.y,a.y,p0y);
                p0z=fmaf(zv.z,a.z,p0z); p0w=fmaf(zv.w,a.w,p0w);
                p1x=fmaf(zv.x,b.x,p1x); p1y=fmaf(zv.y,b.y,p1y);
                p1z=fmaf(zv.z,b.z,p1z); p1w=fmaf(zv.w,b.w,p1w);
            }
            float acc0 = sm[LO_BB + h0] + ((p0x + p0y) + (p0z + p0w));
            float acc1 = sm[LO_BB + h1] + ((p1x + p1y) + (p1z + p1w));

            // scalar logits
            const float4* q40 = (const float4*)(sm + LO_QS + ng*192 + h0*16);
            const float4* q41 = (const float4*)(sm + LO_QS + ng*192 + h1*16);
            const float4* k4  = (const float4*)(sm + LO_KS + ml*196);
            float s0 = 0.f, s1 = 0.f;
#pragma unroll
            for (int c4 = 0; c4 < 4; c4++) {
                const float4 qa = q40[c4], qb = q41[c4];
                const float4 ka = k4[h0*4 + c4], kb = k4[h1*4 + c4];
                s0 = fmaf(qa.x,ka.x, fmaf(qa.y,ka.y, fmaf(qa.z,ka.z, fmaf(qa.w,ka.w, s0))));
                s1 = fmaf(qb.x,kb.x, fmaf(qb.y,kb.y, fmaf(qb.z,kb.z, fmaf(qb.w,kb.w, s1))));
            }
            acc0 = fmaf(s0, 0.25f, acc0);
            acc1 = fmaf(s1, 0.25f, acc1);

            // point logits
            const float* qg0 = sm + LO_QGS + ng*144 + h0*12;
            const float* kgr = sm + LO_KGS + ml*145;
            float pd0 = 0.f, pd1 = 0.f;
#pragma unroll
            for (int u = 0; u < 12; u++) {
                const float d0 = qg0[u]      - kgr[h0*12 + u];
                const float d1 = qg0[12 + u] - kgr[h1*12 + u];
                pd0 = fmaf(d0, d0, pd0);
                pd1 = fmaf(d1, d1, pd1);
            }
            acc0 = fmaf(-0.5f * sm[LO_HW + h0], pd0, acc0);
            acc1 = fmaf(-0.5f * sm[LO_HW + h1], pd1, acc1);

            // distance bias + multiscale
            const float dx = sm[LO_TS + ng*3 + 0] - sm[LO_KTS + ml*3 + 0];
            const float dy = sm[LO_TS + ng*3 + 1] - sm[LO_KTS + ml*3 + 1];
            const float dz = sm[LO_TS + ng*3 + 2] - sm[LO_KTS + ml*3 + 2];
            const float dist = __fsqrt_rn(fmaf(dx,dx, fmaf(dy,dy, dz*dz)));
            int bin = (int)ceilf(dist * 2.0f) - 1;
            bin = max(0, min(63, bin));
            const float ms0 = (dist <= 5.0f) ? sm[LO_PH + h0]
                             : (dist <= 15.0f) ? sm[LO_PH + 12 + h0] : 0.f;
            const float ms1 = (dist <= 5.0f) ? sm[LO_PH + h1]
                             : (dist <= 15.0f) ? sm[LO_PH + 12 + h1] : 0.f;
            acc0 += sm[LO_EMB + bin*12 + h0] + sm[LO_PH + 24 + h0] + ms0;
            acc1 += sm[LO_EMB + bin*12 + h1] + sm[LO_PH + 24 + h1] + ms1;

            const int m = m0 + ml;
            g_attn[((size_t)n * NRES + m) * NH + h0] = acc0;
            g_attn[((size_t)n * NRES + m) * NH + h1] = acc1;
            __syncthreads();
        }
    }
}

// ---------------- softmax over m ----------------
__global__ void k_softmax()
{
    __shared__ float sh[NRES * NH];
    const int n = blockIdx.x, tid = threadIdx.x;  // 384 thr = 12 warps
    float* src = g_attn + (size_t)n * NRES * NH;
    for (int i = tid; i < NRES*NH; i += 384) sh[i] = src[i];
    __syncthreads();
    const int h = tid >> 5, lane = tid & 31;
    float mx = -1e30f;
    for (int m = lane; m < NRES; m += 32) mx = fmaxf(mx, sh[m*NH + h]);
#pragma unroll
    for (int o = 16; o; o >>= 1) mx = fmaxf(mx, __shfl_xor_sync(0xffffffffu, mx, o));
    float sum = 0.f;
    for (int m = lane; m < NRES; m += 32) {
        const float e = expf(sh[m*NH + h] - mx);
        sh[m*NH + h] = e;
        sum += e;
    }
#pragma unroll
    for (int o = 16; o; o >>= 1) sum += __shfl_xor_sync(0xffffffffu, sum, o);
    const float inv = 1.0f / sum;
    for (int m = lane; m < NRES; m += 32) sh[m*NH + h] *= inv;
    __syncthreads();
    for (int i = tid; i < NRES*NH; i += 384) src[i] = sh[i];
}

// ---------------- pair_feat ----------------
__global__ void k_pairfeat(const float* __restrict__ z)
{
    __shared__ alignas(16) float z_s[64 * 128];
    __shared__ float at_s[64 * NH];
    const int n = blockIdx.x, tid = threadIdx.x;  // 384 thr
    const int h = tid >> 5, cq = tid & 31;
    float a0=0.f, a1=0.f, a2=0.f, a3=0.f;
    for (int mc = 0; mc < 8; mc++) {
        const float* zsrc = z + ((size_t)n * NRES + mc * 64) * CZ;
        for (int i = tid; i < 8192; i += 384) z_s[i] = zsrc[i];
        const float* asrc = g_attn + ((size_t)n * NRES + mc * 64) * NH;
        for (int i = tid; i < 768; i += 384) at_s[i] = asrc[i];
        __syncthreads();
#pragma unroll 4
        for (int mm = 0; mm < 64; mm++) {
            const float w = at_s[mm*NH + h];
            const float4 zv = *(const float4*)(z_s + mm*128 + cq*4);
            a0 = fmaf(w, zv.x, a0); a1 = fmaf(w, zv.y, a1);
            a2 = fmaf(w, zv.z, a2); a3 = fmaf(w, zv.w, a3);
        }
        __syncthreads();
    }
    float* dst = g_feats + (size_t)n * OUTD + h * HF + 48 + cq * 4;
    dst[0]=a0; dst[1]=a1; dst[2]=a2; dst[3]=a3;
}

// ---------------- out_scalar + out_pts(local) + norms ----------------
__global__ void k_outv(const float* __restrict__ rot, const float* __restrict__ trans)
{
    __shared__ float at_s[16 * NH];
    __shared__ float v_s [16 * 192];
    __shared__ float vg_s[16 * 288];
    __shared__ float pg_s[NH * 24];
    const int n = blockIdx.x, tid = threadIdx.x;  // 480 thr
    float acc = 0.f;
    for (int mc = 0; mc < 32; mc++) {
        const int m0 = mc * 16;
        __syncthreads();
        for (int i = tid; i < 192;  i += 480) at_s[i] = g_attn[((size_t)n*NRES + m0)*NH + i];
        for (int i = tid; i < 3072; i += 480) v_s[i]  = g_v [m0*192 + i];
        for (int i = tid; i < 4608; i += 480) vg_s[i] = g_vg[m0*288 + i];
        __syncthreads();
        if (tid < 192) {
            const int h = tid >> 4, c = tid & 15;
#pragma unroll
            for (int mm = 0; mm < 16; mm++)
                acc = fmaf(at_s[mm*NH + h], v_s[mm*192 + h*16 + c], acc);
        } else if (tid < 480) {
            const int idx = tid - 192, h = idx / 24, u = idx % 24;
#pragma unroll
            for (int mm = 0; mm < 16; mm++)
                acc = fmaf(at_s[mm*NH + h], vg_s[mm*288 + h*24 + u], acc);
        }
    }
    if (tid < 192) {
        const int h = tid >> 4, c = tid & 15;
        g_feats[(size_t)n*OUTD + h*HF + c] = acc;
    } else {
        pg_s[tid - 192] = acc;
    }
    __syncthreads();
    if (tid < 96) {
        const int h = tid / 8, p = tid & 7;
        float R[9];
#pragma unroll
        for (int i = 0; i < 9; i++) R[i] = rot[n*9 + i];
        const float gx = pg_s[h*24 + p*3 + 0] - trans[n*3 + 0];
        const float gy = pg_s[h*24 + p*3 + 1] - trans[n*3 + 1];
        const float gz = pg_s[h*24 + p*3 + 2] - trans[n*3 + 2];
        const float lx = fmaf(R[0],gx, fmaf(R[3],gy, R[6]*gz));
        const float ly = fmaf(R[1],gx, fmaf(R[4],gy, R[7]*gz));
        const float lz = fmaf(R[2],gx, fmaf(R[5],gy, R[8]*gz));
        float* f = g_feats + (size_t)n*OUTD + h*HF;
        f[16 + p*3 + 0] = lx; f[16 + p*3 + 1] = ly; f[16 + p*3 + 2] = lz;
        f[40 + p] = __fsqrt_rn(fmaf(lx,lx, fmaf(ly,ly, lz*lz)));
    }
}

// ---------------- split-K reduce + bias ----------------
__global__ void k_reduce(const float* __restrict__ bout, float* __restrict__ out)
{
    const int i = blockIdx.x * 256 + threadIdx.x;  // 196608 total
    const int NE = NRES * CS;
    const float v = g_part[i] + g_part[NE + i] + g_part[2*NE + i] + g_part[3*NE + i];
    out[i] = v + bout[i % CS];
}

// ---------------- launch ----------------
static float* symaddr(const void* sym) {
    void* p = nullptr;
    cudaGetSymbolAddress(&p, sym);
    return (float*)p;
}

extern "C" void kernel_launch(void* const* d_in, const int* in_sizes, int n_in,
                              void* d_out, int out_size) {
    const float* s     = (const float*)d_in[0];
    const float* z     = (const float*)d_in[1];
    const float* trans = (const float*)d_in[2];
    const float* rot   = (const float*)d_in[3];
    const float* Wq    = (const float*)d_in[4];
    const float* bq    = (const float*)d_in[5];
    const float* Wk    = (const float*)d_in[6];
    const float* bk    = (const float*)d_in[7];
    const float* Wv    = (const float*)d_in[8];
    const float* bv    = (const float*)d_in[9];
    const float* Wqp   = (const float*)d_in[10];
    const float* bqp   = (const float*)d_in[11];
    const float* Wkp   = (const float*)d_in[12];
    const float* bkp   = (const float*)d_in[13];
    const float* Wvp   = (const float*)d_in[14];
    const float* bvp   = (const float*)d_in[15];
    const float* Wb    = (const float*)d_in[16];
    const float* bb    = (const float*)d_in[17];
    const float* emb   = (const float*)d_in[18];
    const float* sl    = (const float*)d_in[19];
    const float* hw    = (const float*)d_in[20];
    const float* Wout  = (const float*)d_in[21];
    const float* bout  = (const float*)d_in[22];
    float* out = (float*)d_out;

    float* pq  = symaddr(g_q);
    float* pk  = symaddr(g_k);
    float* pv  = symaddr(g_v);
    float* pqp = symaddr(g_qp);
    float* pkp = symaddr(g_kp);
    float* pvp = symaddr(g_vp);
    float* pf  = symaddr(g_feats);
    float* pp  = symaddr(g_part);

    static bool attr_done = false;
    if (!attr_done) {
        cudaFuncSetAttribute(k_logits, cudaFuncAttributeMaxDynamicSharedMemorySize,
                             LO_END * (int)sizeof(float));
        attr_done = true;
    }

    // projections
    k_sgemm<<<dim3(3,8,1), 256>>>(s, Wq,  bq,  pq,  192, CS, CS);
    k_sgemm<<<dim3(3,8,1), 256>>>(s, Wk,  bk,  pk,  192, CS, CS);
    k_sgemm<<<dim3(3,8,1), 256>>>(s, Wv,  bv,  pv,  192, CS, CS);
    k_sgemm<<<dim3(3,8,1), 256>>>(s, Wqp, bqp, pqp, 144, CS, CS);
    k_sgemm<<<dim3(3,8,1), 256>>>(s, Wkp, bkp, pkp, 144, CS, CS);
    k_sgemm<<<dim3(5,8,1), 256>>>(s, Wvp, bvp, pvp, 288, CS, CS);
    // frames
    k_points<<<NRES, 192>>>(rot, trans);
    // logits
    k_logits<<<dim3(2,256,1), 192, LO_END * sizeof(float)>>>(z, trans, Wb, bb, emb, sl, hw);
    // softmax
    k_softmax<<<NRES, 384>>>();
    // outputs
    k_pairfeat<<<NRES, 384>>>(z);
    k_outv<<<NRES, 480>>>(rot, trans);
    // final GEMM split-K=4 + reduce
    k_sgemm<<<dim3(6,8,4), 256>>>(pf, Wout, nullptr, pp, CS, OUTD, OUTD/4);
    k_reduce<<<(NRES*CS)/256, 256>>>(bout, out);
}

// round 6
// speedup vs baseline: 1.4904x; 1.4904x over previous
#include <cuda_runtime.h>
#include <math.h>

#define NRES 512
#define CS   384
#define CZ   128
#define NH   12
#define OUTD 2112
#define HF   176
#define PROJW 1152   // 192 q | 192 k | 192 v | 144 qp | 144 kp | 288 vp

// ---------------- scratch ----------------
__device__ alignas(16) float g_proj[NRES*PROJW];
__device__ alignas(16) float g_qg[NRES*144];
__device__ alignas(16) float g_kg[NRES*144];
__device__ alignas(16) float g_vg[NRES*288];
__device__ alignas(16) float g_attn[(size_t)NH*NRES*NRES];   // [h][n][m]
__device__ alignas(16) float g_feats[(size_t)NRES*OUTD];
__device__ alignas(16) float g_part[(size_t)4*NRES*CS];

// ---------------- cp.async helpers ----------------
__device__ __forceinline__ void cpa16(void* dst_smem, const void* src_gmem) {
    unsigned int d = (unsigned int)__cvta_generic_to_shared(dst_smem);
    asm volatile("cp.async.ca.shared.global [%0], [%1], 16;\n" :: "r"(d), "l"(src_gmem));
}
#define CP_COMMIT() asm volatile("cp.async.commit_group;\n" ::: "memory")
#define CP_WAIT(N)  asm volatile("cp.async.wait_group %0;\n" :: "n"(N) : "memory")

// ---------------- fused projection GEMM: g_proj[512][1152] = s @ [Wq|Wk|Wv|Wqp|Wkp|Wvp] + biases
__global__ void k_proj(const float* __restrict__ s,
    const float* __restrict__ Wq,  const float* __restrict__ bq,
    const float* __restrict__ Wk,  const float* __restrict__ bk,
    const float* __restrict__ Wv,  const float* __restrict__ bvs,
    const float* __restrict__ Wqp, const float* __restrict__ bqp,
    const float* __restrict__ Wkp, const float* __restrict__ bkp,
    const float* __restrict__ Wvp, const float* __restrict__ bvp)
{
    __shared__ alignas(16) float As[16][64];
    __shared__ alignas(16) float Bs[16][64];
    const int tid = threadIdx.x;
    const int tx = tid & 15, ty = tid >> 4;
    const int bm = blockIdx.y * 64, bn = blockIdx.x * 64;
    const int am  = tid >> 2, akq = tid & 3;
    const int bkk = tid >> 4, bn4 = tid & 15;

    // resolve this loader thread's weight segment (column fixed for whole kernel)
    const int gc = bn + bn4 * 4;
    const float* Bp; int bst;
    if (gc < 576)      { const int sg = gc / 192;
                         const float* Ws = (sg == 0) ? Wq : (sg == 1) ? Wk : Wv;
                         Bp = Ws + (gc - sg * 192); bst = 192; }
    else if (gc < 864) { const int sg = (gc - 576) / 144;
                         Bp = ((sg == 0) ? Wqp : Wkp) + (gc - 576 - sg * 144); bst = 144; }
    else               { Bp = Wvp + (gc - 864); bst = 288; }

    float acc[4][4];
#pragma unroll
    for (int i = 0; i < 4; i++)
#pragma unroll
        for (int j = 0; j < 4; j++) acc[i][j] = 0.f;

    for (int k0 = 0; k0 < CS; k0 += 16) {
        float4 av = *(const float4*)(s + (size_t)(bm + am) * CS + k0 + akq * 4);
        As[akq*4+0][am] = av.x; As[akq*4+1][am] = av.y;
        As[akq*4+2][am] = av.z; As[akq*4+3][am] = av.w;
        float4 wv4 = *(const float4*)(Bp + (size_t)(k0 + bkk) * bst);
        *(float4*)&Bs[bkk][bn4*4] = wv4;
        __syncthreads();
#pragma unroll
        for (int kk = 0; kk < 16; kk++) {
            float4 a = *(const float4*)&As[kk][ty*4];
            float4 b = *(const float4*)&Bs[kk][tx*4];
            acc[0][0]=fmaf(a.x,b.x,acc[0][0]); acc[0][1]=fmaf(a.x,b.y,acc[0][1]);
            acc[0][2]=fmaf(a.x,b.z,acc[0][2]); acc[0][3]=fmaf(a.x,b.w,acc[0][3]);
            acc[1][0]=fmaf(a.y,b.x,acc[1][0]); acc[1][1]=fmaf(a.y,b.y,acc[1][1]);
            acc[1][2]=fmaf(a.y,b.z,acc[1][2]); acc[1][3]=fmaf(a.y,b.w,acc[1][3]);
            acc[2][0]=fmaf(a.z,b.x,acc[2][0]); acc[2][1]=fmaf(a.z,b.y,acc[2][1]);
            acc[2][2]=fmaf(a.z,b.z,acc[2][2]); acc[2][3]=fmaf(a.z,b.w,acc[2][3]);
            acc[3][0]=fmaf(a.w,b.x,acc[3][0]); acc[3][1]=fmaf(a.w,b.y,acc[3][1]);
            acc[3][2]=fmaf(a.w,b.z,acc[3][2]); acc[3][3]=fmaf(a.w,b.w,acc[3][3]);
        }
        __syncthreads();
    }
    // bias segment for epilogue columns (4 consecutive cols, same segment)
    const int gc0 = bn + tx * 4;
    const float* bptr;
    if (gc0 < 576)      { const int sg = gc0 / 192;
                          bptr = ((sg == 0) ? bq : (sg == 1) ? bk : bvs) + (gc0 - sg * 192); }
    else if (gc0 < 864) { const int sg = (gc0 - 576) / 144;
                          bptr = ((sg == 0) ? bqp : bkp) + (gc0 - 576 - sg * 144); }
    else                { bptr = bvp + (gc0 - 864); }
#pragma unroll
    for (int i = 0; i < 4; i++) {
        const int row = bm + ty * 4 + i;
#pragma unroll
        for (int j = 0; j < 4; j++)
            g_proj[(size_t)row * PROJW + gc0 + j] = acc[i][j] + bptr[j];
    }
}

// ---------------- local -> global points ----------------
__global__ void k_points(const float* __restrict__ rot, const float* __restrict__ trans)
{
    const int n = blockIdx.x;
    __shared__ float R[9], T[3];
    if (threadIdx.x < 9) R[threadIdx.x] = rot[n*9 + threadIdx.x];
    if (threadIdx.x < 3) T[threadIdx.x] = trans[n*3 + threadIdx.x];
    __syncthreads();
    const int t = threadIdx.x;  // 0..191
    const float* src; float* dst;
    const float* row = g_proj + (size_t)n * PROJW;
    if (t < 48)       { src = row + 576 + t*3;      dst = g_qg + n*144 + t*3; }
    else if (t < 96)  { src = row + 720 + (t-48)*3; dst = g_kg + n*144 + (t-48)*3; }
    else              { src = row + 864 + (t-96)*3; dst = g_vg + n*288 + (t-96)*3; }
    const float p0 = src[0], p1 = src[1], p2 = src[2];
    dst[0] = fmaf(R[0],p0, fmaf(R[1],p1, fmaf(R[2],p2, T[0])));
    dst[1] = fmaf(R[3],p0, fmaf(R[4],p1, fmaf(R[5],p2, T[1])));
    dst[2] = fmaf(R[6],p0, fmaf(R[7],p1, fmaf(R[8],p2, T[2])));
}

// ---------------- fused logits ----------------
#define LO_WBT   0        // 1536
#define LO_EMB   1536     // 768
#define LO_PH    2304     // 36
#define LO_BB    2340     // 12
#define LO_HW    2352     // 12
#define LO_QS    2364     // 384
#define LO_QGS   2748     // 288
#define LO_TS    3036     // 8
#define LO_KS    3044     // 32*196
#define LO_KGS   9316     // 32*145
#define LO_KTS   13956    // 96
#define LO_ZS    14052    // 32*132
#define LO_END   18276
__global__ void k_logits(const float* __restrict__ z, const float* __restrict__ trans,
                         const float* __restrict__ Wb, const float* __restrict__ bb,
                         const float* __restrict__ emb, const float* __restrict__ sl,
                         const float* __restrict__ hw)
{
    extern __shared__ float sm[];
    const int tid = threadIdx.x;       // 192 threads
    const int n0 = blockIdx.y * 2;
    const int mh = blockIdx.x;

    for (int i = tid; i < 1536; i += 192) {
        const int h = i >> 7, c = i & 127;
        sm[LO_WBT + i] = Wb[c*NH + h];
    }
    for (int i = tid; i < 768; i += 192) sm[LO_EMB + i] = emb[i];
    if (tid < 12) {
        sm[LO_BB + tid] = bb[tid];
        sm[LO_HW + tid] = hw[tid];
        const float e0 = expf(sl[tid]), e1 = expf(sl[12+tid]), e2 = expf(sl[24+tid]);
        const float inv = 1.0f / (e0 + e1 + e2);
        sm[LO_PH + tid] = e0*inv; sm[LO_PH + 12 + tid] = e1*inv; sm[LO_PH + 24 + tid] = e2*inv;
    }
    for (int i = tid; i < 384; i += 192) sm[LO_QS  + i] = g_proj[(size_t)(n0 + i/192)*PROJW + (i%192)];
    for (int i = tid; i < 288; i += 192) sm[LO_QGS + i] = g_qg[n0*144 + i];
    if (tid < 6) sm[LO_TS + tid] = trans[n0*3 + tid];
    __syncthreads();

    const int ml = tid & 31;
    const int hp = tid >> 5;
    const int h0 = hp * 2, h1 = h0 + 1;

    for (int mt = 0; mt < 8; mt++) {
        const int m0 = mh * 256 + mt * 32;
        for (int j = 0; j < 32; j++) sm[LO_KS + j*196 + tid] = g_proj[(size_t)(m0+j)*PROJW + 192 + tid];
        for (int i = tid; i < 32*144; i += 192) { const int mm = i/144, x = i%144; sm[LO_KGS + mm*145 + x] = g_kg[(m0+mm)*144 + x]; }
        for (int i = tid; i < 96; i += 192) sm[LO_KTS + i] = trans[m0*3 + i];
        __syncthreads();

        for (int ng = 0; ng < 2; ng++) {
            const int n = n0 + ng;
            const float4* z4 = (const float4*)(z + ((size_t)n * NRES + m0) * CZ);
            for (int i = tid; i < 1024; i += 192) {
                const float4 v = z4[i];
                const int mm = i >> 5, c = (i & 31) * 4;
                float* d = sm + LO_ZS + mm*132 + c;
                d[0]=v.x; d[1]=v.y; d[2]=v.z; d[3]=v.w;
            }
            __syncthreads();

            // pair bias: z . WbT (8 independent chains)
            const float4* zr = (const float4*)(sm + LO_ZS + ml*132);
            const float4* w0 = (const float4*)(sm + LO_WBT + h0*128);
            const float4* w1 = (const float4*)(sm + LO_WBT + h1*128);
            float p0x=0,p0y=0,p0z=0,p0w=0, p1x=0,p1y=0,p1z=0,p1w=0;
#pragma unroll 8
            for (int q2 = 0; q2 < 32; q2++) {
                const float4 zv = zr[q2], a = w0[q2], b = w1[q2];
                p0x=fmaf(zv.x,a.x,p0x); p0y=fmaf(zv.y,a.y,p0y);
                p0z=fmaf(zv.z,a.z,p0z); p0w=fmaf(zv.w,a.w,p0w);
                p1x=fmaf(zv.x,b.x,p1x); p1y=fmaf(zv.y,b.y,p1y);
                p1z=fmaf(zv.z,b.z,p1z); p1w=fmaf(zv.w,b.w,p1w);
            }
            float acc0 = sm[LO_BB + h0] + ((p0x + p0y) + (p0z + p0w));
            float acc1 = sm[LO_BB + h1] + ((p1x + p1y) + (p1z + p1w));

            // scalar logits
            const float4* q40 = (const float4*)(sm + LO_QS + ng*192 + h0*16);
            const float4* q41 = (const float4*)(sm + LO_QS + ng*192 + h1*16);
            const float4* k4  = (const float4*)(sm + LO_KS + ml*196);
            float s0 = 0.f, s1 = 0.f;
#pragma unroll
            for (int c4 = 0; c4 < 4; c4++) {
                const float4 qa = q40[c4], qb = q41[c4];
                const float4 ka = k4[h0*4 + c4], kb = k4[h1*4 + c4];
                s0 = fmaf(qa.x,ka.x, fmaf(qa.y,ka.y, fmaf(qa.z,ka.z, fmaf(qa.w,ka.w, s0))));
                s1 = fmaf(qb.x,kb.x, fmaf(qb.y,kb.y, fmaf(qb.z,kb.z, fmaf(qb.w,kb.w, s1))));
            }
            acc0 = fmaf(s0, 0.25f, acc0);
            acc1 = fmaf(s1, 0.25f, acc1);

            // point logits
            const float* qg0 = sm + LO_QGS + ng*144 + h0*12;
            const float* kgr = sm + LO_KGS + ml*145;
            float pd0 = 0.f, pd1 = 0.f;
#pragma unroll
            for (int u = 0; u < 12; u++) {
                const float d0 = qg0[u]      - kgr[h0*12 + u];
                const float d1 = qg0[12 + u] - kgr[h1*12 + u];
                pd0 = fmaf(d0, d0, pd0);
                pd1 = fmaf(d1, d1, pd1);
            }
            acc0 = fmaf(-0.5f * sm[LO_HW + h0], pd0, acc0);
            acc1 = fmaf(-0.5f * sm[LO_HW + h1], pd1, acc1);

            // distance bias + multiscale
            const float dx = sm[LO_TS + ng*3 + 0] - sm[LO_KTS + ml*3 + 0];
            const float dy = sm[LO_TS + ng*3 + 1] - sm[LO_KTS + ml*3 + 1];
            const float dz = sm[LO_TS + ng*3 + 2] - sm[LO_KTS + ml*3 + 2];
            const float dist = __fsqrt_rn(fmaf(dx,dx, fmaf(dy,dy, dz*dz)));
            int bin = (int)ceilf(dist * 2.0f) - 1;
            bin = max(0, min(63, bin));
            const float ms0 = (dist <= 5.0f) ? sm[LO_PH + h0]
                             : (dist <= 15.0f) ? sm[LO_PH + 12 + h0] : 0.f;
            const float ms1 = (dist <= 5.0f) ? sm[LO_PH + h1]
                             : (dist <= 15.0f) ? sm[LO_PH + 12 + h1] : 0.f;
            acc0 += sm[LO_EMB + bin*12 + h0] + sm[LO_PH + 24 + h0] + ms0;
            acc1 += sm[LO_EMB + bin*12 + h1] + sm[LO_PH + 24 + h1] + ms1;

            const int m = m0 + ml;
            g_attn[(size_t)h0*NRES*NRES + (size_t)n*NRES + m] = acc0;
            g_attn[(size_t)h1*NRES*NRES + (size_t)n*NRES + m] = acc1;
            __syncthreads();
        }
    }
}

// ---------------- softmax over m (attn layout [h][n][m]) ----------------
__global__ void k_softmax()
{
    const int n = blockIdx.x;
    const int h = threadIdx.x >> 5, lane = threadIdx.x & 31;   // 384 thr
    float* p = g_attn + (size_t)h*NRES*NRES + (size_t)n*NRES;
    float v[16];
    float mx = -1e30f;
#pragma unroll
    for (int i = 0; i < 16; i++) { v[i] = p[lane + 32*i]; mx = fmaxf(mx, v[i]); }
#pragma unroll
    for (int o = 16; o; o >>= 1) mx = fmaxf(mx, __shfl_xor_sync(0xffffffffu, mx, o));
    float sum = 0.f;
#pragma unroll
    for (int i = 0; i < 16; i++) { v[i] = expf(v[i] - mx); sum += v[i]; }
#pragma unroll
    for (int o = 16; o; o >>= 1) sum += __shfl_xor_sync(0xffffffffu, sum, o);
    const float inv = 1.0f / sum;
#pragma unroll
    for (int i = 0; i < 16; i++) p[lane + 32*i] = v[i] * inv;
}

// ---------------- pair_feat (cp.async double-buffered z) ----------------
// dyn smem floats: Z0 0..8191, Z1 8192..16383, AT0 16384..17151, AT1 17152..17919
#define PF_END 17920
__global__ void k_pairfeat(const float* __restrict__ z)
{
    extern __shared__ float sm[];
    const int n = blockIdx.x, tid = threadIdx.x;  // 512 thr
    float* zb[2]  = { sm, sm + 8192 };
    float* atb[2] = { sm + 16384, sm + 17152 };

    const float4* zsrc = (const float4*)(z + (size_t)n * NRES * CZ);  // chunks of 64 m

    // prefetch chunk 0
    {
        const int buf = 0;
        for (int i = tid; i < 2048; i += 512) cpa16(zb[buf] + i*4, zsrc + i);
        if (tid < 192) {
            const int h = tid / 16, q = tid % 16;
            cpa16(atb[buf] + h*64 + q*4,
                  g_attn + (size_t)h*NRES*NRES + (size_t)n*NRES + q*4);
        }
        CP_COMMIT();
    }

    const int h = (tid < 384) ? (tid >> 5) : 0;
    const int cq = tid & 31;
    float a0=0.f, a1=0.f, a2=0.f, a3=0.f;

    for (int mc = 0; mc < 8; mc++) {
        if (mc + 1 < 8) {
            const int buf = (mc + 1) & 1;
            const int m0 = (mc + 1) * 64;
            for (int i = tid; i < 2048; i += 512) cpa16(zb[buf] + i*4, zsrc + 2048*(mc+1) + i);
            if (tid < 192) {
                const int hh = tid / 16, q = tid % 16;
                cpa16(atb[buf] + hh*64 + q*4,
                      g_attn + (size_t)hh*NRES*NRES + (size_t)n*NRES + m0 + q*4);
            }
            CP_COMMIT();
            CP_WAIT(1);
        } else {
            CP_WAIT(0);
        }
        __syncthreads();
        if (tid < 384) {
            const float* zc = zb[mc & 1];
            const float* ac = atb[mc & 1];
#pragma unroll 4
            for (int mm = 0; mm < 64; mm++) {
                const float w = ac[h*64 + mm];
                const float4 zv = *(const float4*)(zc + mm*128 + cq*4);
                a0 = fmaf(w, zv.x, a0); a1 = fmaf(w, zv.y, a1);
                a2 = fmaf(w, zv.z, a2); a3 = fmaf(w, zv.w, a3);
            }
        }
        __syncthreads();
    }
    if (tid < 384) {
        float* dst = g_feats + (size_t)n * OUTD + h * HF + 48 + cq * 4;
        dst[0]=a0; dst[1]=a1; dst[2]=a2; dst[3]=a3;
    }
}

// ---------------- out_scalar + out_pts(local) + norms; 4 n per block ----------------
// dyn smem floats: AT 0..1535 [ni][h][mm], V 1536..7679 [mm][192], VG 7680..16895 [mm][288], PG 16896..18047 [ni][288]
#define OV_AT 0
#define OV_V  1536
#define OV_VG 7680
#define OV_PG 16896
#define OV_END 18048
__global__ void k_outv(const float* __restrict__ rot, const float* __restrict__ trans)
{
    extern __shared__ float sm[];
    const int n0 = blockIdx.x * 4, tid = threadIdx.x;  // 480 thr, grid 128
    float acc0=0.f, acc1=0.f, acc2=0.f, acc3=0.f;

    for (int mc = 0; mc < 16; mc++) {
        const int m0 = mc * 32;
        __syncthreads();
        for (int i = tid; i < 1536; i += 480) {
            const int ni = i / 384, r = i - ni*384;
            const int hh = r >> 5, mm = r & 31;
            sm[OV_AT + i] = g_attn[(size_t)hh*NRES*NRES + (size_t)(n0+ni)*NRES + m0 + mm];
        }
        for (int i = tid; i < 6144; i += 480) {
            const int mm = i / 192, x = i - mm*192;
            sm[OV_V + i] = g_proj[(size_t)(m0+mm)*PROJW + 384 + x];
        }
        for (int i = tid; i < 9216; i += 480) sm[OV_VG + i] = g_vg[m0*288 + i];
        __syncthreads();

        if (tid < 192) {
            const int hh = tid >> 4, c = tid & 15;
            const float* vs = sm + OV_V + hh*16 + c;
            const float* as = sm + OV_AT + hh*32;
#pragma unroll
            for (int mm = 0; mm < 32; mm++) {
                const float vv = vs[mm*192];
                acc0 = fmaf(as[mm],       vv, acc0);
                acc1 = fmaf(as[384+mm],   vv, acc1);
                acc2 = fmaf(as[768+mm],   vv, acc2);
                acc3 = fmaf(as[1152+mm],  vv, acc3);
            }
        } else {
            const int idx = tid - 192, hh = idx / 24, u = idx - hh*24;
            const float* vs = sm + OV_VG + hh*24 + u;
            const float* as = sm + OV_AT + hh*32;
#pragma unroll
            for (int mm = 0; mm < 32; mm++) {
                const float vv = vs[mm*288];
                acc0 = fmaf(as[mm],       vv, acc0);
                acc1 = fmaf(as[384+mm],   vv, acc1);
                acc2 = fmaf(as[768+mm],   vv, acc2);
                acc3 = fmaf(as[1152+mm],  vv, acc3);
            }
        }
    }
    __syncthreads();
    if (tid < 192) {
        const int hh = tid >> 4, c = tid & 15;
        g_feats[(size_t)(n0+0)*OUTD + hh*HF + c] = acc0;
        g_feats[(size_t)(n0+1)*OUTD + hh*HF + c] = acc1;
        g_feats[(size_t)(n0+2)*OUTD + hh*HF + c] = acc2;
        g_feats[(size_t)(n0+3)*OUTD + hh*HF + c] = acc3;
    } else {
        const int idx = tid - 192;
        sm[OV_PG + 0*288 + idx] = acc0;
        sm[OV_PG + 1*288 + idx] = acc1;
        sm[OV_PG + 2*288 + idx] = acc2;
        sm[OV_PG + 3*288 + idx] = acc3;
    }
    __syncthreads();
    if (tid < 384) {
        const int ni = tid / 96, r = tid - ni*96;
        const int hh = r / 8, p = r - hh*8;
        const int n = n0 + ni;
        float R[9];
#pragma unroll
        for (int i = 0; i < 9; i++) R[i] = rot[n*9 + i];
        const float gx = sm[OV_PG + ni*288 + hh*24 + p*3 + 0] - trans[n*3 + 0];
        const float gy = sm[OV_PG + ni*288 + hh*24 + p*3 + 1] - trans[n*3 + 1];
        const float gz = sm[OV_PG + ni*288 + hh*24 + p*3 + 2] - trans[n*3 + 2];
        const float lx = fmaf(R[0],gx, fmaf(R[3],gy, R[6]*gz));
        const float ly = fmaf(R[1],gx, fmaf(R[4],gy, R[7]*gz));
        const float lz = fmaf(R[2],gx, fmaf(R[5],gy, R[8]*gz));
        float* f = g_feats + (size_t)n*OUTD + hh*HF;
        f[16 + p*3 + 0] = lx; f[16 + p*3 + 1] = ly; f[16 + p*3 + 2] = lz;
        f[40 + p] = __fsqrt_rn(fmaf(lx,lx, fmaf(ly,ly, lz*lz)));
    }
}

// ---------------- final GEMM (split-K) ----------------
__global__ void k_sgemm(const float* __restrict__ A, const float* __restrict__ B,
                        float* __restrict__ C, int Nc, int K, int kLen)
{
    __shared__ alignas(16) float As[16][64];
    __shared__ alignas(16) float Bs[16][64];
    const int tid = threadIdx.x;
    const int tx = tid & 15, ty = tid >> 4;
    const int bm = blockIdx.y * 64, bn = blockIdx.x * 64;
    const int k0base = blockIdx.z * kLen;
    C += (size_t)blockIdx.z * (size_t)(gridDim.y * 64) * Nc;

    const int am  = tid >> 2, akq = tid & 3;
    const int bkk = tid >> 4, bn4 = tid & 15;

    float acc[4][4];
#pragma unroll
    for (int i = 0; i < 4; i++)
#pragma unroll
        for (int j = 0; j < 4; j++) acc[i][j] = 0.f;

    for (int kt = 0; kt < kLen; kt += 16) {
        const int k0 = k0base + kt;
        float4 av = *(const float4*)(A + (size_t)(bm + am) * K + k0 + akq * 4);
        As[akq*4+0][am] = av.x; As[akq*4+1][am] = av.y;
        As[akq*4+2][am] = av.z; As[akq*4+3][am] = av.w;
        float4 bv = make_float4(0.f,0.f,0.f,0.f);
        const int col = bn + bn4 * 4;
        if (col < Nc) bv = *(const float4*)(B + (size_t)(k0 + bkk) * Nc + col);
        *(float4*)&Bs[bkk][bn4*4] = bv;
        __syncthreads();
#pragma unroll
        for (int kk = 0; kk < 16; kk++) {
            float4 a = *(const float4*)&As[kk][ty*4];
            float4 b = *(const float4*)&Bs[kk][tx*4];
            acc[0][0]=fmaf(a.x,b.x,acc[0][0]); acc[0][1]=fmaf(a.x,b.y,acc[0][1]);
            acc[0][2]=fmaf(a.x,b.z,acc[0][2]); acc[0][3]=fmaf(a.x,b.w,acc[0][3]);
            acc[1][0]=fmaf(a.y,b.x,acc[1][0]); acc[1][1]=fmaf(a.y,b.y,acc[1][1]);
            acc[1][2]=fmaf(a.y,b.z,acc[1][2]); acc[1][3]=fmaf(a.y,b.w,acc[1][3]);
            acc[2][0]=fmaf(a.z,b.x,acc[2][0]); acc[2][1]=fmaf(a.z,b.y,acc[2][1]);
            acc[2][2]=fmaf(a.z,b.z,acc[2][2]); acc[2][3]=fmaf(a.z,b.w,acc[2][3]);
            acc[3][0]=fmaf(a.w,b.x,acc[3][0]); acc[3][1]=fmaf(a.w,b.y,acc[3][1]);
            acc[3][2]=fmaf(a.w,b.z,acc[3][2]); acc[3][3]=fmaf(a.w,b.w,acc[3][3]);
        }
        __syncthreads();
    }
#pragma unroll
    for (int i = 0; i < 4; i++) {
        const int row = bm + ty * 4 + i;
#pragma unroll
        for (int j = 0; j < 4; j++) {
            const int col = bn + tx * 4 + j;
            if (col < Nc) C[(size_t)row * Nc + col] = acc[i][j];
        }
    }
}

// ---------------- split-K reduce + bias ----------------
__global__ void k_reduce(const float* __restrict__ bout, float* __restrict__ out)
{
    const int i = blockIdx.x * 256 + threadIdx.x;
    const int NE = NRES * CS;
    const float v = g_part[i] + g_part[NE + i] + g_part[2*NE + i] + g_part[3*NE + i];
    out[i] = v + bout[i % CS];
}

// ---------------- launch ----------------
static float* symaddr(const void* sym) {
    void* p = nullptr;
    cudaGetSymbolAddress(&p, sym);
    return (float*)p;
}

extern "C" void kernel_launch(void* const* d_in, const int* in_sizes, int n_in,
                              void* d_out, int out_size) {
    const float* s     = (const float*)d_in[0];
    const float* z     = (const float*)d_in[1];
    const float* trans = (const float*)d_in[2];
    const float* rot   = (const float*)d_in[3];
    const float* Wq    = (const float*)d_in[4];
    const float* bq    = (const float*)d_in[5];
    const float* Wk    = (const float*)d_in[6];
    const float* bk    = (const float*)d_in[7];
    const float* Wv    = (const float*)d_in[8];
    const float* bv    = (const float*)d_in[9];
    const float* Wqp   = (const float*)d_in[10];
    const float* bqp   = (const float*)d_in[11];
    const float* Wkp   = (const float*)d_in[12];
    const float* bkp   = (const float*)d_in[13];
    const float* Wvp   = (const float*)d_in[14];
    const float* bvp   = (const float*)d_in[15];
    const float* Wb    = (const float*)d_in[16];
    const float* bb    = (const float*)d_in[17];
    const float* emb   = (const float*)d_in[18];
    const float* sl    = (const float*)d_in[19];
    const float* hw    = (const float*)d_in[20];
    const float* Wout  = (const float*)d_in[21];
    const float* bout  = (const float*)d_in[22];
    float* out = (float*)d_out;

    float* pf = symaddr(g_feats);
    float* pp = symaddr(g_part);

    cudaFuncSetAttribute(k_logits,   cudaFuncAttributeMaxDynamicSharedMemorySize, LO_END * (int)sizeof(float));
    cudaFuncSetAttribute(k_pairfeat, cudaFuncAttributeMaxDynamicSharedMemorySize, PF_END * (int)sizeof(float));
    cudaFuncSetAttribute(k_outv,     cudaFuncAttributeMaxDynamicSharedMemorySize, OV_END * (int)sizeof(float));

    // fused projections (one launch)
    k_proj<<<dim3(18,8,1), 256>>>(s, Wq,bq, Wk,bk, Wv,bv, Wqp,bqp, Wkp,bkp, Wvp,bvp);
    // frames
    k_points<<<NRES, 192>>>(rot, trans);
    // logits
    k_logits<<<dim3(2,256,1), 192, LO_END * sizeof(float)>>>(z, trans, Wb, bb, emb, sl, hw);
    // softmax
    k_softmax<<<NRES, 384>>>();
    // outputs
    k_pairfeat<<<NRES, 512, PF_END * sizeof(float)>>>(z);
    k_outv<<<128, 480, OV_END * sizeof(float)>>>(rot, trans);
    // final GEMM split-K=4 + reduce
    k_sgemm<<<dim3(6,8,4), 256>>>(pf, Wout, pp, CS, OUTD, OUTD/4);
    k_reduce<<<(NRES*CS)/256, 256>>>(bout, out);
}

// round 7
// speedup vs baseline: 1.9138x; 1.2841x over previous
#include <cuda_runtime.h>
#include <math.h>

#define NRES 512
#define CS   384
#define CZ   128
#define NH   12
#define OUTD 2112
#define HF   176
#define PROJW 1152   // 192 q | 192 k | 192 v | 144 qp | 144 kp | 288 vp

// ---------------- scratch ----------------
__device__ alignas(16) float g_proj[NRES*PROJW];
__device__ alignas(16) float g_qg[NRES*144];
__device__ alignas(16) float g_kg[NRES*144];
__device__ alignas(16) float g_vg[NRES*288];
__device__ alignas(16) float g_attn[(size_t)NH*NRES*NRES];   // [h][n][m]
__device__ alignas(16) float g_feats[(size_t)NRES*OUTD];
__device__ alignas(16) float g_part[(size_t)4*NRES*CS];

// ---------------- cp.async helpers ----------------
__device__ __forceinline__ void cpa16(void* dst_smem, const void* src_gmem) {
    unsigned int d = (unsigned int)__cvta_generic_to_shared(dst_smem);
    asm volatile("cp.async.ca.shared.global [%0], [%1], 16;\n" :: "r"(d), "l"(src_gmem));
}
#define CP_COMMIT() asm volatile("cp.async.commit_group;\n" ::: "memory")
#define CP_WAIT0()  asm volatile("cp.async.wait_group 0;\n" ::: "memory")
#define CP_WAIT1()  asm volatile("cp.async.wait_group 1;\n" ::: "memory")

// ---------------- fused projection GEMM ----------------
__global__ void k_proj(const float* __restrict__ s,
    const float* __restrict__ Wq,  const float* __restrict__ bq,
    const float* __restrict__ Wk,  const float* __restrict__ bk,
    const float* __restrict__ Wv,  const float* __restrict__ bvs,
    const float* __restrict__ Wqp, const float* __restrict__ bqp,
    const float* __restrict__ Wkp, const float* __restrict__ bkp,
    const float* __restrict__ Wvp, const float* __restrict__ bvp)
{
    __shared__ alignas(16) float As[16][64];
    __shared__ alignas(16) float Bs[16][64];
    const int tid = threadIdx.x;
    const int tx = tid & 15, ty = tid >> 4;
    const int bm = blockIdx.y * 64, bn = blockIdx.x * 64;
    const int am  = tid >> 2, akq = tid & 3;
    const int bkk = tid >> 4, bn4 = tid & 15;

    const int gc = bn + bn4 * 4;
    const float* Bp; int bst;
    if (gc < 576)      { const int sg = gc / 192;
                         const float* Ws = (sg == 0) ? Wq : (sg == 1) ? Wk : Wv;
                         Bp = Ws + (gc - sg * 192); bst = 192; }
    else if (gc < 864) { const int sg = (gc - 576) / 144;
                         Bp = ((sg == 0) ? Wqp : Wkp) + (gc - 576 - sg * 144); bst = 144; }
    else               { Bp = Wvp + (gc - 864); bst = 288; }

    float acc[4][4];
#pragma unroll
    for (int i = 0; i < 4; i++)
#pragma unroll
        for (int j = 0; j < 4; j++) acc[i][j] = 0.f;

    for (int k0 = 0; k0 < CS; k0 += 16) {
        float4 av = *(const float4*)(s + (size_t)(bm + am) * CS + k0 + akq * 4);
        As[akq*4+0][am] = av.x; As[akq*4+1][am] = av.y;
        As[akq*4+2][am] = av.z; As[akq*4+3][am] = av.w;
        float4 wv4 = *(const float4*)(Bp + (size_t)(k0 + bkk) * bst);
        *(float4*)&Bs[bkk][bn4*4] = wv4;
        __syncthreads();
#pragma unroll
        for (int kk = 0; kk < 16; kk++) {
            float4 a = *(const float4*)&As[kk][ty*4];
            float4 b = *(const float4*)&Bs[kk][tx*4];
            acc[0][0]=fmaf(a.x,b.x,acc[0][0]); acc[0][1]=fmaf(a.x,b.y,acc[0][1]);
            acc[0][2]=fmaf(a.x,b.z,acc[0][2]); acc[0][3]=fmaf(a.x,b.w,acc[0][3]);
            acc[1][0]=fmaf(a.y,b.x,acc[1][0]); acc[1][1]=fmaf(a.y,b.y,acc[1][1]);
            acc[1][2]=fmaf(a.y,b.z,acc[1][2]); acc[1][3]=fmaf(a.y,b.w,acc[1][3]);
            acc[2][0]=fmaf(a.z,b.x,acc[2][0]); acc[2][1]=fmaf(a.z,b.y,acc[2][1]);
            acc[2][2]=fmaf(a.z,b.z,acc[2][2]); acc[2][3]=fmaf(a.z,b.w,acc[2][3]);
            acc[3][0]=fmaf(a.w,b.x,acc[3][0]); acc[3][1]=fmaf(a.w,b.y,acc[3][1]);
            acc[3][2]=fmaf(a.w,b.z,acc[3][2]); acc[3][3]=fmaf(a.w,b.w,acc[3][3]);
        }
        __syncthreads();
    }
    const int gc0 = bn + tx * 4;
    const float* bptr;
    if (gc0 < 576)      { const int sg = gc0 / 192;
                          bptr = ((sg == 0) ? bq : (sg == 1) ? bk : bvs) + (gc0 - sg * 192); }
    else if (gc0 < 864) { const int sg = (gc0 - 576) / 144;
                          bptr = ((sg == 0) ? bqp : bkp) + (gc0 - 576 - sg * 144); }
    else                { bptr = bvp + (gc0 - 864); }
#pragma unroll
    for (int i = 0; i < 4; i++) {
        const int row = bm + ty * 4 + i;
#pragma unroll
        for (int j = 0; j < 4; j++)
            g_proj[(size_t)row * PROJW + gc0 + j] = acc[i][j] + bptr[j];
    }
}

// ---------------- local -> global points ----------------
__global__ void k_points(const float* __restrict__ rot, const float* __restrict__ trans)
{
    const int n = blockIdx.x;
    __shared__ float R[9], T[3];
    if (threadIdx.x < 9) R[threadIdx.x] = rot[n*9 + threadIdx.x];
    if (threadIdx.x < 3) T[threadIdx.x] = trans[n*3 + threadIdx.x];
    __syncthreads();
    const int t = threadIdx.x;  // 0..191
    const float* src; float* dst;
    const float* row = g_proj + (size_t)n * PROJW;
    if (t < 48)       { src = row + 576 + t*3;      dst = g_qg + n*144 + t*3; }
    else if (t < 96)  { src = row + 720 + (t-48)*3; dst = g_kg + n*144 + (t-48)*3; }
    else              { src = row + 864 + (t-96)*3; dst = g_vg + n*288 + (t-96)*3; }
    const float p0 = src[0], p1 = src[1], p2 = src[2];
    dst[0] = fmaf(R[0],p0, fmaf(R[1],p1, fmaf(R[2],p2, T[0])));
    dst[1] = fmaf(R[3],p0, fmaf(R[4],p1, fmaf(R[5],p2, T[1])));
    dst[2] = fmaf(R[6],p0, fmaf(R[7],p1, fmaf(R[8],p2, T[2])));
}

// ---------------- fused logits (cp.async pipelined) ----------------
#define LO_WBT   0        // 1536
#define LO_EMB   1536     // 768
#define LO_PH    2304     // 36
#define LO_BB    2340     // 12
#define LO_HW    2352     // 12
#define LO_QS    2364     // 384
#define LO_QGS   2748     // 288
#define LO_TS    3036     // 6 (+pad)
#define LO_KS    3044     // 32*196 = 6272
#define LO_KGS   9316     // 32*148 = 4736
#define LO_KTS   14052    // 96
#define LO_ZS0   14148    // 32*132 = 4224
#define LO_ZS1   18372    // 4224
#define LO_END   22596    // floats (90384 B)

__device__ __forceinline__ void logits_tile(const float* __restrict__ sm,
    const float* __restrict__ zbuf, int n, int ng, int m0, int ml, int h0, int h1)
{
    // pair bias: z . WbT (8 independent chains; Wb reads are warp-broadcast)
    const float4* zr = (const float4*)(zbuf + ml*132);
    const float4* w0 = (const float4*)(sm + LO_WBT + h0*128);
    const float4* w1 = (const float4*)(sm + LO_WBT + h1*128);
    float p0x=0,p0y=0,p0z=0,p0w=0, p1x=0,p1y=0,p1z=0,p1w=0;
#pragma unroll 8
    for (int q2 = 0; q2 < 32; q2++) {
        const float4 zv = zr[q2], a = w0[q2], b = w1[q2];
        p0x=fmaf(zv.x,a.x,p0x); p0y=fmaf(zv.y,a.y,p0y);
        p0z=fmaf(zv.z,a.z,p0z); p0w=fmaf(zv.w,a.w,p0w);
        p1x=fmaf(zv.x,b.x,p1x); p1y=fmaf(zv.y,b.y,p1y);
        p1z=fmaf(zv.z,b.z,p1z); p1w=fmaf(zv.w,b.w,p1w);
    }
    float acc0 = sm[LO_BB + h0] + ((p0x + p0y) + (p0z + p0w));
    float acc1 = sm[LO_BB + h1] + ((p1x + p1y) + (p1z + p1w));

    // scalar logits
    const float4* q40 = (const float4*)(sm + LO_QS + ng*192 + h0*16);
    const float4* q41 = (const float4*)(sm + LO_QS + ng*192 + h1*16);
    const float4* k4  = (const float4*)(sm + LO_KS + ml*196);
    float s0 = 0.f, s1 = 0.f;
#pragma unroll
    for (int c4 = 0; c4 < 4; c4++) {
        const float4 qa = q40[c4], qb = q41[c4];
        const float4 ka = k4[h0*4 + c4], kb = k4[h1*4 + c4];
        s0 = fmaf(qa.x,ka.x, fmaf(qa.y,ka.y, fmaf(qa.z,ka.z, fmaf(qa.w,ka.w, s0))));
        s1 = fmaf(qb.x,kb.x, fmaf(qb.y,kb.y, fmaf(qb.z,kb.z, fmaf(qb.w,kb.w, s1))));
    }
    acc0 = fmaf(s0, 0.25f, acc0);
    acc1 = fmaf(s1, 0.25f, acc1);

    // point logits (float4, conflict-free: stride 148)
    const float4* qgv0 = (const float4*)(sm + LO_QGS + ng*144 + h0*12);
    const float4* qgv1 = qgv0 + 3;
    const float4* kgv  = (const float4*)(sm + LO_KGS + ml*148);
    float pd0 = 0.f, pd1 = 0.f;
#pragma unroll
    for (int j = 0; j < 3; j++) {
        const float4 qa = qgv0[j], ka = kgv[h0*3 + j];
        const float4 qb = qgv1[j], kb = kgv[h1*3 + j];
        float d;
        d = qa.x-ka.x; pd0 = fmaf(d,d,pd0);
        d = qa.y-ka.y; pd0 = fmaf(d,d,pd0);
        d = qa.z-ka.z; pd0 = fmaf(d,d,pd0);
        d = qa.w-ka.w; pd0 = fmaf(d,d,pd0);
        d = qb.x-kb.x; pd1 = fmaf(d,d,pd1);
        d = qb.y-kb.y; pd1 = fmaf(d,d,pd1);
        d = qb.z-kb.z; pd1 = fmaf(d,d,pd1);
        d = qb.w-kb.w; pd1 = fmaf(d,d,pd1);
    }
    acc0 = fmaf(-0.5f * sm[LO_HW + h0], pd0, acc0);
    acc1 = fmaf(-0.5f * sm[LO_HW + h1], pd1, acc1);

    // distance bias + multiscale
    const float dx = sm[LO_TS + ng*3 + 0] - sm[LO_KTS + ml*3 + 0];
    const float dy = sm[LO_TS + ng*3 + 1] - sm[LO_KTS + ml*3 + 1];
    const float dz = sm[LO_TS + ng*3 + 2] - sm[LO_KTS + ml*3 + 2];
    const float dist = __fsqrt_rn(fmaf(dx,dx, fmaf(dy,dy, dz*dz)));
    int bin = (int)ceilf(dist * 2.0f) - 1;
    bin = max(0, min(63, bin));
    const float ms0 = (dist <= 5.0f) ? sm[LO_PH + h0]
                     : (dist <= 15.0f) ? sm[LO_PH + 12 + h0] : 0.f;
    const float ms1 = (dist <= 5.0f) ? sm[LO_PH + h1]
                     : (dist <= 15.0f) ? sm[LO_PH + 12 + h1] : 0.f;
    acc0 += sm[LO_EMB + bin*12 + h0] + sm[LO_PH + 24 + h0] + ms0;
    acc1 += sm[LO_EMB + bin*12 + h1] + sm[LO_PH + 24 + h1] + ms1;

    const int m = m0 + ml;
    g_attn[(size_t)h0*NRES*NRES + (size_t)n*NRES + m] = acc0;
    g_attn[(size_t)h1*NRES*NRES + (size_t)n*NRES + m] = acc1;
}

__global__ void k_logits(const float* __restrict__ z, const float* __restrict__ trans,
                         const float* __restrict__ Wb, const float* __restrict__ bb,
                         const float* __restrict__ emb, const float* __restrict__ sl,
                         const float* __restrict__ hw)
{
    extern __shared__ float sm[];
    const int tid = threadIdx.x;       // 192 threads
    const int n0 = blockIdx.y * 2;
    const int mh = blockIdx.x;

    for (int i = tid; i < 1536; i += 192) {
        const int h = i >> 7, c = i & 127;
        sm[LO_WBT + i] = Wb[c*NH + h];
    }
    for (int i = tid; i < 768; i += 192) sm[LO_EMB + i] = emb[i];
    if (tid < 12) {
        sm[LO_BB + tid] = bb[tid];
        sm[LO_HW + tid] = hw[tid];
        const float e0 = expf(sl[tid]), e1 = expf(sl[12+tid]), e2 = expf(sl[24+tid]);
        const float inv = 1.0f / (e0 + e1 + e2);
        sm[LO_PH + tid] = e0*inv; sm[LO_PH + 12 + tid] = e1*inv; sm[LO_PH + 24 + tid] = e2*inv;
    }
    for (int i = tid; i < 384; i += 192) sm[LO_QS  + i] = g_proj[(size_t)(n0 + i/192)*PROJW + (i%192)];
    for (int i = tid; i < 288; i += 192) sm[LO_QGS + i] = g_qg[n0*144 + i];
    if (tid < 6) sm[LO_TS + tid] = trans[n0*3 + tid];

    float* zs0 = sm + LO_ZS0;
    float* zs1 = sm + LO_ZS1;

    const int ml = tid & 31;
    const int hp = tid >> 5;
    const int h0 = hp * 2, h1 = h0 + 1;

    // prefetch helpers (each thread issues its share)
    auto pf_z = [&](float* zb, int n, int m0) {
        const float* zsrc = z + ((size_t)n * NRES + m0) * CZ;
        for (int i = tid; i < 1024; i += 192)
            cpa16(zb + (i >> 5) * 132 + (i & 31) * 4, zsrc + i * 4);
    };
    auto pf_k = [&](int m0) {
        for (int i = tid; i < 1536; i += 192) {
            const int row = i / 48, q = i - row * 48;
            cpa16(sm + LO_KS + row*196 + q*4, g_proj + (size_t)(m0+row)*PROJW + 192 + q*4);
        }
        for (int i = tid; i < 1152; i += 192) {
            const int row = i / 36, q = i - row * 36;
            cpa16(sm + LO_KGS + row*148 + q*4, g_kg + (m0+row)*144 + q*4);
        }
        if (tid < 24) cpa16(sm + LO_KTS + tid*4, trans + m0*3 + tid*4);
    };

    {
        const int m0 = mh * 256;
        pf_z(zs0, n0, m0); CP_COMMIT();
        pf_k(m0);          CP_COMMIT();
    }

    for (int mt = 0; mt < 8; mt++) {
        const int m0 = mh * 256 + mt * 32;
        pf_z(zs1, n0 + 1, m0); CP_COMMIT();
        CP_WAIT1();
        __syncthreads();
        logits_tile(sm, zs0, n0, 0, m0, ml, h0, h1);
        __syncthreads();                      // zs0 reads done before overwrite
        if (mt < 7) { pf_z(zs0, n0, m0 + 32); CP_COMMIT(); CP_WAIT1(); }
        else        { CP_WAIT0(); }
        __syncthreads();
        logits_tile(sm, zs1, n0 + 1, 1, m0, ml, h0, h1);
        __syncthreads();                      // K reads done before overwrite
        if (mt < 7) { pf_k(m0 + 32); CP_COMMIT(); }
    }
}

// ---------------- softmax over m (attn layout [h][n][m]) ----------------
__global__ void k_softmax()
{
    const int n = blockIdx.x;
    const int h = threadIdx.x >> 5, lane = threadIdx.x & 31;   // 384 thr
    float* p = g_attn + (size_t)h*NRES*NRES + (size_t)n*NRES;
    float v[16];
    float mx = -1e30f;
#pragma unroll
    for (int i = 0; i < 16; i++) { v[i] = p[lane + 32*i]; mx = fmaxf(mx, v[i]); }
#pragma unroll
    for (int o = 16; o; o >>= 1) mx = fmaxf(mx, __shfl_xor_sync(0xffffffffu, mx, o));
    float sum = 0.f;
#pragma unroll
    for (int i = 0; i < 16; i++) { v[i] = expf(v[i] - mx); sum += v[i]; }
#pragma unroll
    for (int o = 16; o; o >>= 1) sum += __shfl_xor_sync(0xffffffffu, sum, o);
    const float inv = 1.0f / sum;
#pragma unroll
    for (int i = 0; i < 16; i++) p[lane + 32*i] = v[i] * inv;
}

// ---------------- pair_feat (cp.async double-buffered z) ----------------
#define PF_END 17920
__global__ void k_pairfeat(const float* __restrict__ z)
{
    extern __shared__ float sm[];
    const int n = blockIdx.x, tid = threadIdx.x;  // 512 thr
    float* zb[2]  = { sm, sm + 8192 };
    float* atb[2] = { sm + 16384, sm + 17152 };

    const float4* zsrc = (const float4*)(z + (size_t)n * NRES * CZ);

    {
        const int buf = 0;
        for (int i = tid; i < 2048; i += 512) cpa16(zb[buf] + i*4, zsrc + i);
        if (tid < 192) {
            const int h = tid / 16, q = tid % 16;
            cpa16(atb[buf] + h*64 + q*4,
                  g_attn + (size_t)h*NRES*NRES + (size_t)n*NRES + q*4);
        }
        CP_COMMIT();
    }

    const int h = (tid < 384) ? (tid >> 5) : 0;
    const int cq = tid & 31;
    float a0=0.f, a1=0.f, a2=0.f, a3=0.f;

    for (int mc = 0; mc < 8; mc++) {
        if (mc + 1 < 8) {
            const int buf = (mc + 1) & 1;
            const int m0 = (mc + 1) * 64;
            for (int i = tid; i < 2048; i += 512) cpa16(zb[buf] + i*4, zsrc + 2048*(mc+1) + i);
            if (tid < 192) {
                const int hh = tid / 16, q = tid % 16;
                cpa16(atb[buf] + hh*64 + q*4,
                      g_attn + (size_t)hh*NRES*NRES + (size_t)n*NRES + m0 + q*4);
            }
            CP_COMMIT();
            CP_WAIT1();
        } else {
            CP_WAIT0();
        }
        __syncthreads();
        if (tid < 384) {
            const float* zc = zb[mc & 1];
            const float* ac = atb[mc & 1];
#pragma unroll 4
            for (int mm = 0; mm < 64; mm++) {
                const float w = ac[h*64 + mm];
                const float4 zv = *(const float4*)(zc + mm*128 + cq*4);
                a0 = fmaf(w, zv.x, a0); a1 = fmaf(w, zv.y, a1);
                a2 = fmaf(w, zv.z, a2); a3 = fmaf(w, zv.w, a3);
            }
        }
        __syncthreads();
    }
    if (tid < 384) {
        float* dst = g_feats + (size_t)n * OUTD + h * HF + 48 + cq * 4;
        dst[0]=a0; dst[1]=a1; dst[2]=a2; dst[3]=a3;
    }
}

// ---------------- out_scalar + out_pts(local) + norms; 4 n per block ----------------
#define OV_AT 0
#define OV_V  1536
#define OV_VG 7680
#define OV_PG 16896
#define OV_END 18048
__global__ void k_outv(const float* __restrict__ rot, const float* __restrict__ trans)
{
    extern __shared__ float sm[];
    const int n0 = blockIdx.x * 4, tid = threadIdx.x;  // 480 thr, grid 128
    float acc0=0.f, acc1=0.f, acc2=0.f, acc3=0.f;

    for (int mc = 0; mc < 16; mc++) {
        const int m0 = mc * 32;
        __syncthreads();
        for (int i = tid; i < 1536; i += 480) {
            const int ni = i / 384, r = i - ni*384;
            const int hh = r >> 5, mm = r & 31;
            sm[OV_AT + i] = g_attn[(size_t)hh*NRES*NRES + (size_t)(n0+ni)*NRES + m0 + mm];
        }
        for (int i = tid; i < 6144; i += 480) {
            const int mm = i / 192, x = i - mm*192;
            sm[OV_V + i] = g_proj[(size_t)(m0+mm)*PROJW + 384 + x];
        }
        for (int i = tid; i < 9216; i += 480) sm[OV_VG + i] = g_vg[m0*288 + i];
        __syncthreads();

        if (tid < 192) {
            const int hh = tid >> 4, c = tid & 15;
            const float* vs = sm + OV_V + hh*16 + c;
            const float* as = sm + OV_AT + hh*32;
#pragma unroll
            for (int mm = 0; mm < 32; mm++) {
                const float vv = vs[mm*192];
                acc0 = fmaf(as[mm],       vv, acc0);
                acc1 = fmaf(as[384+mm],   vv, acc1);
                acc2 = fmaf(as[768+mm],   vv, acc2);
                acc3 = fmaf(as[1152+mm],  vv, acc3);
            }
        } else {
            const int idx = tid - 192, hh = idx / 24, u = idx - hh*24;
            const float* vs = sm + OV_VG + hh*24 + u;
            const float* as = sm + OV_AT + hh*32;
#pragma unroll
            for (int mm = 0; mm < 32; mm++) {
                const float vv = vs[mm*288];
                acc0 = fmaf(as[mm],       vv, acc0);
                acc1 = fmaf(as[384+mm],   vv, acc1);
                acc2 = fmaf(as[768+mm],   vv, acc2);
                acc3 = fmaf(as[1152+mm],  vv, acc3);
            }
        }
    }
    __syncthreads();
    if (tid < 192) {
        const int hh = tid >> 4, c = tid & 15;
        g_feats[(size_t)(n0+0)*OUTD + hh*HF + c] = acc0;
        g_feats[(size_t)(n0+1)*OUTD + hh*HF + c] = acc1;
        g_feats[(size_t)(n0+2)*OUTD + hh*HF + c] = acc2;
        g_feats[(size_t)(n0+3)*OUTD + hh*HF + c] = acc3;
    } else {
        const int idx = tid - 192;
        sm[OV_PG + 0*288 + idx] = acc0;
        sm[OV_PG + 1*288 + idx] = acc1;
        sm[OV_PG + 2*288 + idx] = acc2;
        sm[OV_PG + 3*288 + idx] = acc3;
    }
    __syncthreads();
    if (tid < 384) {
        const int ni = tid / 96, r = tid - ni*96;
        const int hh = r / 8, p = r - hh*8;
        const int n = n0 + ni;
        float R[9];
#pragma unroll
        for (int i = 0; i < 9; i++) R[i] = rot[n*9 + i];
        const float gx = sm[OV_PG + ni*288 + hh*24 + p*3 + 0] - trans[n*3 + 0];
        const float gy = sm[OV_PG + ni*288 + hh*24 + p*3 + 1] - trans[n*3 + 1];
        const float gz = sm[OV_PG + ni*288 + hh*24 + p*3 + 2] - trans[n*3 + 2];
        const float lx = fmaf(R[0],gx, fmaf(R[3],gy, R[6]*gz));
        const float ly = fmaf(R[1],gx, fmaf(R[4],gy, R[7]*gz));
        const float lz = fmaf(R[2],gx, fmaf(R[5],gy, R[8]*gz));
        float* f = g_feats + (size_t)n*OUTD + hh*HF;
        f[16 + p*3 + 0] = lx; f[16 + p*3 + 1] = ly; f[16 + p*3 + 2] = lz;
        f[40 + p] = __fsqrt_rn(fmaf(lx,lx, fmaf(ly,ly, lz*lz)));
    }
}

// ---------------- final GEMM (split-K) ----------------
__global__ void k_sgemm(const float* __restrict__ A, const float* __restrict__ B,
                        float* __restrict__ C, int Nc, int K, int kLen)
{
    __shared__ alignas(16) float As[16][64];
    __shared__ alignas(16) float Bs[16][64];
    const int tid = threadIdx.x;
    const int tx = tid & 15, ty = tid >> 4;
    const int bm = blockIdx.y * 64, bn = blockIdx.x * 64;
    const int k0base = blockIdx.z * kLen;
    C += (size_t)blockIdx.z * (size_t)(gridDim.y * 64) * Nc;

    const int am  = tid >> 2, akq = tid & 3;
    const int bkk = tid >> 4, bn4 = tid & 15;

    float acc[4][4];
#pragma unroll
    for (int i = 0; i < 4; i++)
#pragma unroll
        for (int j = 0; j < 4; j++) acc[i][j] = 0.f;

    for (int kt = 0; kt < kLen; kt += 16) {
        const int k0 = k0base + kt;
        float4 av = *(const float4*)(A + (size_t)(bm + am) * K + k0 + akq * 4);
        As[akq*4+0][am] = av.x; As[akq*4+1][am] = av.y;
        As[akq*4+2][am] = av.z; As[akq*4+3][am] = av.w;
        float4 bv = make_float4(0.f,0.f,0.f,0.f);
        const int col = bn + bn4 * 4;
        if (col < Nc) bv = *(const float4*)(B + (size_t)(k0 + bkk) * Nc + col);
        *(float4*)&Bs[bkk][bn4*4] = bv;
        __syncthreads();
#pragma unroll
        for (int kk = 0; kk < 16; kk++) {
            float4 a = *(const float4*)&As[kk][ty*4];
            float4 b = *(const float4*)&Bs[kk][tx*4];
            acc[0][0]=fmaf(a.x,b.x,acc[0][0]); acc[0][1]=fmaf(a.x,b.y,acc[0][1]);
            acc[0][2]=fmaf(a.x,b.z,acc[0][2]); acc[0][3]=fmaf(a.x,b.w,acc[0][3]);
            acc[1][0]=fmaf(a.y,b.x,acc[1][0]); acc[1][1]=fmaf(a.y,b.y,acc[1][1]);
            acc[1][2]=fmaf(a.y,b.z,acc[1][2]); acc[1][3]=fmaf(a.y,b.w,acc[1][3]);
            acc[2][0]=fmaf(a.z,b.x,acc[2][0]); acc[2][1]=fmaf(a.z,b.y,acc[2][1]);
            acc[2][2]=fmaf(a.z,b.z,acc[2][2]); acc[2][3]=fmaf(a.z,b.w,acc[2][3]);
            acc[3][0]=fmaf(a.w,b.x,acc[3][0]); acc[3][1]=fmaf(a.w,b.y,acc[3][1]);
            acc[3][2]=fmaf(a.w,b.z,acc[3][2]); acc[3][3]=fmaf(a.w,b.w,acc[3][3]);
        }
        __syncthreads();
    }
#pragma unroll
    for (int i = 0; i < 4; i++) {
        const int row = bm + ty * 4 + i;
#pragma unroll
        for (int j = 0; j < 4; j++) {
            const int col = bn + tx * 4 + j;
            if (col < Nc) C[(size_t)row * Nc + col] = acc[i][j];
        }
    }
}

// ---------------- split-K reduce + bias ----------------
__global__ void k_reduce(const float* __restrict__ bout, float* __restrict__ out)
{
    const int i = blockIdx.x * 256 + threadIdx.x;
    const int NE = NRES * CS;
    const float v = g_part[i] + g_part[NE + i] + g_part[2*NE + i] + g_part[3*NE + i];
    out[i] = v + bout[i % CS];
}

// ---------------- launch ----------------
static float* symaddr(const void* sym) {
    void* p = nullptr;
    cudaGetSymbolAddress(&p, sym);
    return (float*)p;
}

extern "C" void kernel_launch(void* const* d_in, const int* in_sizes, int n_in,
                              void* d_out, int out_size) {
    const float* s     = (const float*)d_in[0];
    const float* z     = (const float*)d_in[1];
    const float* trans = (const float*)d_in[2];
    const float* rot   = (const float*)d_in[3];
    const float* Wq    = (const float*)d_in[4];
    const float* bq    = (const float*)d_in[5];
    const float* Wk    = (const float*)d_in[6];
    const float* bk    = (const float*)d_in[7];
    const float* Wv    = (const float*)d_in[8];
    const float* bv    = (const float*)d_in[9];
    const float* Wqp   = (const float*)d_in[10];
    const float* bqp   = (const float*)d_in[11];
    const float* Wkp   = (const float*)d_in[12];
    const float* bkp   = (const float*)d_in[13];
    const float* Wvp   = (const float*)d_in[14];
    const float* bvp   = (const float*)d_in[15];
    const float* Wb    = (const float*)d_in[16];
    const float* bb    = (const float*)d_in[17];
    const float* emb   = (const float*)d_in[18];
    const float* sl    = (const float*)d_in[19];
    const float* hw    = (const float*)d_in[20];
    const float* Wout  = (const float*)d_in[21];
    const float* bout  = (const float*)d_in[22];
    float* out = (float*)d_out;

    float* pf = symaddr(g_feats);
    float* pp = symaddr(g_part);

    cudaFuncSetAttribute(k_logits,   cudaFuncAttributeMaxDynamicSharedMemorySize, LO_END * (int)sizeof(float));
    cudaFuncSetAttribute(k_pairfeat, cudaFuncAttributeMaxDynamicSharedMemorySize, PF_END * (int)sizeof(float));
    cudaFuncSetAttribute(k_outv,     cudaFuncAttributeMaxDynamicSharedMemorySize, OV_END * (int)sizeof(float));

    k_proj<<<dim3(18,8,1), 256>>>(s, Wq,bq, Wk,bk, Wv,bv, Wqp,bqp, Wkp,bkp, Wvp,bvp);
    k_points<<<NRES, 192>>>(rot, trans);
    k_logits<<<dim3(2,256,1), 192, LO_END * sizeof(float)>>>(z, trans, Wb, bb, emb, sl, hw);
    k_softmax<<<NRES, 384>>>();
    k_pairfeat<<<NRES, 512, PF_END * sizeof(float)>>>(z);
    k_outv<<<128, 480, OV_END * sizeof(float)>>>(rot, trans);
    k_sgemm<<<dim3(6,8,4), 256>>>(pf, Wout, pp, CS, OUTD, OUTD/4);
    k_reduce<<<(NRES*CS)/256, 256>>>(bout, out);
}

// round 8
// speedup vs baseline: 2.2457x; 1.1734x over previous
#include <cuda_runtime.h>
#include <math.h>

#define NRES 512
#define CS   384
#define CZ   128
#define NH   12
#define OUTD 2112
#define HF   176
#define PROJW 1152   // 192 q | 192 k | 192 v | 144 qp | 144 kp | 288 vp
#define N2   (NRES*NRES)

// ---------------- scratch ----------------
__device__ alignas(16) float g_proj[NRES*PROJW];
__device__ alignas(16) float g_qg[NRES*144];
__device__ alignas(16) float g_kg[NRES*144];
__device__ alignas(16) float g_vg[NRES*288];
__device__ alignas(16) float g_attn[(size_t)NH*NRES*NRES];   // [h][n][m]
__device__ alignas(16) float g_feats[(size_t)NRES*OUTD];
__device__ alignas(16) float g_part[(size_t)4*NRES*CS];

// ---------------- cp.async helpers ----------------
__device__ __forceinline__ void cpa16(void* dst_smem, const void* src_gmem) {
    unsigned int d = (unsigned int)__cvta_generic_to_shared(dst_smem);
    asm volatile("cp.async.ca.shared.global [%0], [%1], 16;\n" :: "r"(d), "l"(src_gmem));
}
#define CP_COMMIT() asm volatile("cp.async.commit_group;\n" ::: "memory")
#define CP_WAIT0()  asm volatile("cp.async.wait_group 0;\n" ::: "memory")
#define CP_WAIT1()  asm volatile("cp.async.wait_group 1;\n" ::: "memory")

// ---------------- fused projection GEMM ----------------
__global__ void k_proj(const float* __restrict__ s,
    const float* __restrict__ Wq,  const float* __restrict__ bq,
    const float* __restrict__ Wk,  const float* __restrict__ bk,
    const float* __restrict__ Wv,  const float* __restrict__ bvs,
    const float* __restrict__ Wqp, const float* __restrict__ bqp,
    const float* __restrict__ Wkp, const float* __restrict__ bkp,
    const float* __restrict__ Wvp, const float* __restrict__ bvp)
{
    __shared__ alignas(16) float As[16][64];
    __shared__ alignas(16) float Bs[16][64];
    const int tid = threadIdx.x;
    const int tx = tid & 15, ty = tid >> 4;
    const int bm = blockIdx.y * 64, bn = blockIdx.x * 64;
    const int am  = tid >> 2, akq = tid & 3;
    const int bkk = tid >> 4, bn4 = tid & 15;

    const int gc = bn + bn4 * 4;
    const float* Bp; int bst;
    if (gc < 576)      { const int sg = gc / 192;
                         const float* Ws = (sg == 0) ? Wq : (sg == 1) ? Wk : Wv;
                         Bp = Ws + (gc - sg * 192); bst = 192; }
    else if (gc < 864) { const int sg = (gc - 576) / 144;
                         Bp = ((sg == 0) ? Wqp : Wkp) + (gc - 576 - sg * 144); bst = 144; }
    else               { Bp = Wvp + (gc - 864); bst = 288; }

    float acc[4][4];
#pragma unroll
    for (int i = 0; i < 4; i++)
#pragma unroll
        for (int j = 0; j < 4; j++) acc[i][j] = 0.f;

    for (int k0 = 0; k0 < CS; k0 += 16) {
        float4 av = *(const float4*)(s + (size_t)(bm + am) * CS + k0 + akq * 4);
        As[akq*4+0][am] = av.x; As[akq*4+1][am] = av.y;
        As[akq*4+2][am] = av.z; As[akq*4+3][am] = av.w;
        float4 wv4 = *(const float4*)(Bp + (size_t)(k0 + bkk) * bst);
        *(float4*)&Bs[bkk][bn4*4] = wv4;
        __syncthreads();
#pragma unroll
        for (int kk = 0; kk < 16; kk++) {
            float4 a = *(const float4*)&As[kk][ty*4];
            float4 b = *(const float4*)&Bs[kk][tx*4];
            acc[0][0]=fmaf(a.x,b.x,acc[0][0]); acc[0][1]=fmaf(a.x,b.y,acc[0][1]);
            acc[0][2]=fmaf(a.x,b.z,acc[0][2]); acc[0][3]=fmaf(a.x,b.w,acc[0][3]);
            acc[1][0]=fmaf(a.y,b.x,acc[1][0]); acc[1][1]=fmaf(a.y,b.y,acc[1][1]);
            acc[1][2]=fmaf(a.y,b.z,acc[1][2]); acc[1][3]=fmaf(a.y,b.w,acc[1][3]);
            acc[2][0]=fmaf(a.z,b.x,acc[2][0]); acc[2][1]=fmaf(a.z,b.y,acc[2][1]);
            acc[2][2]=fmaf(a.z,b.z,acc[2][2]); acc[2][3]=fmaf(a.z,b.w,acc[2][3]);
            acc[3][0]=fmaf(a.w,b.x,acc[3][0]); acc[3][1]=fmaf(a.w,b.y,acc[3][1]);
            acc[3][2]=fmaf(a.w,b.z,acc[3][2]); acc[3][3]=fmaf(a.w,b.w,acc[3][3]);
        }
        __syncthreads();
    }
    const int gc0 = bn + tx * 4;
    const float* bptr;
    if (gc0 < 576)      { const int sg = gc0 / 192;
                          bptr = ((sg == 0) ? bq : (sg == 1) ? bk : bvs) + (gc0 - sg * 192); }
    else if (gc0 < 864) { const int sg = (gc0 - 576) / 144;
                          bptr = ((sg == 0) ? bqp : bkp) + (gc0 - 576 - sg * 144); }
    else                { bptr = bvp + (gc0 - 864); }
#pragma unroll
    for (int i = 0; i < 4; i++) {
        const int row = bm + ty * 4 + i;
#pragma unroll
        for (int j = 0; j < 4; j++)
            g_proj[(size_t)row * PROJW + gc0 + j] = acc[i][j] + bptr[j];
    }
}

// ---------------- local -> global points ----------------
__global__ void k_points(const float* __restrict__ rot, const float* __restrict__ trans)
{
    const int n = blockIdx.x;
    __shared__ float R[9], T[3];
    if (threadIdx.x < 9) R[threadIdx.x] = rot[n*9 + threadIdx.x];
    if (threadIdx.x < 3) T[threadIdx.x] = trans[n*3 + threadIdx.x];
    __syncthreads();
    const int t = threadIdx.x;  // 0..191
    const float* src; float* dst;
    const float* row = g_proj + (size_t)n * PROJW;
    if (t < 48)       { src = row + 576 + t*3;      dst = g_qg + n*144 + t*3; }
    else if (t < 96)  { src = row + 720 + (t-48)*3; dst = g_kg + n*144 + (t-48)*3; }
    else              { src = row + 864 + (t-96)*3; dst = g_vg + n*288 + (t-96)*3; }
    const float p0 = src[0], p1 = src[1], p2 = src[2];
    dst[0] = fmaf(R[0],p0, fmaf(R[1],p1, fmaf(R[2],p2, T[0])));
    dst[1] = fmaf(R[3],p0, fmaf(R[4],p1, fmaf(R[5],p2, T[1])));
    dst[2] = fmaf(R[6],p0, fmaf(R[7],p1, fmaf(R[8],p2, T[2])));
}

// ---------------- pair bias stream: g_attn[h][n][m] = z@Wb + bb + dist_bias + multiscale
// 1 block per n, 256 threads, 128-m chunks double-buffered via cp.async.
#define PB_WBT 0        // 1536
#define PB_EMB 1536     // 768
#define PB_PH  2304     // 36
#define PB_BB  2340     // 12
#define PB_TN  2352     // 4
#define PB_TM0 2356     // 384
#define PB_TM1 2740     // 384 (end 3124)
#define PB_Z0  3136     // 128*132 = 16896
#define PB_Z1  20032    // 16896
#define PB_END 36928    // floats = 147712 B
__global__ void k_pairbias(const float* __restrict__ z, const float* __restrict__ trans,
                           const float* __restrict__ Wb, const float* __restrict__ bb,
                           const float* __restrict__ emb, const float* __restrict__ sl)
{
    extern __shared__ float sm[];
    const int n = blockIdx.x, tid = threadIdx.x;  // 256 thr

    for (int i = tid; i < 1536; i += 256) {
        const int h = i >> 7, c = i & 127;
        sm[PB_WBT + i] = Wb[c*NH + h];
    }
    for (int i = tid; i < 768; i += 256) sm[PB_EMB + i] = emb[i];
    if (tid < 12) {
        sm[PB_BB + tid] = bb[tid];
        const float e0 = expf(sl[tid]), e1 = expf(sl[12+tid]), e2 = expf(sl[24+tid]);
        const float inv = 1.0f / (e0 + e1 + e2);
        sm[PB_PH + tid] = e0*inv; sm[PB_PH + 12 + tid] = e1*inv; sm[PB_PH + 24 + tid] = e2*inv;
    }
    if (tid < 3) sm[PB_TN + tid] = trans[n*3 + tid];

    auto pf = [&](int buf, int mc) {
        float* zb = sm + (buf ? PB_Z1 : PB_Z0);
        const float4* zsrc = (const float4*)(z + ((size_t)n * NRES + mc*128) * CZ);
        for (int i = tid; i < 4096; i += 256)
            cpa16(zb + (i >> 5)*132 + (i & 31)*4, zsrc + i);
        if (tid < 96)
            cpa16(sm + (buf ? PB_TM1 : PB_TM0) + tid*4, trans + mc*384 + tid*4);
    };

    pf(0, 0); CP_COMMIT();

    const int ml = tid & 127;
    const int hg = tid >> 7;       // 0/1
    const int hb = hg * 6;

    for (int mc = 0; mc < 4; mc++) {
        if (mc < 3) { pf((mc+1)&1, mc+1); CP_COMMIT(); CP_WAIT1(); }
        else        { CP_WAIT0(); }
        __syncthreads();
        const float* zb = sm + ((mc & 1) ? PB_Z1 : PB_Z0);
        const float* tm = sm + ((mc & 1) ? PB_TM1 : PB_TM0);
        const float4* zr = (const float4*)(zb + ml*132);

        float a[6][4];
#pragma unroll
        for (int j = 0; j < 6; j++) { a[j][0]=0.f; a[j][1]=0.f; a[j][2]=0.f; a[j][3]=0.f; }
#pragma unroll 8
        for (int c4 = 0; c4 < 32; c4++) {
            const float4 zv = zr[c4];
#pragma unroll
            for (int j = 0; j < 6; j++) {
                const float4 w = ((const float4*)(sm + PB_WBT + (hb+j)*128))[c4];
                a[j][0] = fmaf(zv.x, w.x, a[j][0]);
                a[j][1] = fmaf(zv.y, w.y, a[j][1]);
                a[j][2] = fmaf(zv.z, w.z, a[j][2]);
                a[j][3] = fmaf(zv.w, w.w, a[j][3]);
            }
        }
        const float dx = sm[PB_TN+0] - tm[ml*3+0];
        const float dy = sm[PB_TN+1] - tm[ml*3+1];
        const float dz = sm[PB_TN+2] - tm[ml*3+2];
        const float dist = __fsqrt_rn(fmaf(dx,dx, fmaf(dy,dy, dz*dz)));
        int bin = (int)ceilf(dist * 2.0f) - 1;
        bin = max(0, min(63, bin));
        const int msrow = (dist <= 5.0f) ? 0 : (dist <= 15.0f) ? 12 : -1;
        const int m = mc*128 + ml;
#pragma unroll
        for (int j = 0; j < 6; j++) {
            const int h = hb + j;
            float v = sm[PB_BB + h] + ((a[j][0]+a[j][1]) + (a[j][2]+a[j][3]));
            v += sm[PB_EMB + bin*12 + h] + sm[PB_PH + 24 + h];
            if (msrow >= 0) v += sm[PB_PH + msrow + h];
            g_attn[(size_t)h*N2 + (size_t)n*NRES + m] = v;
        }
        __syncthreads();
    }
}

// ---------------- geometry logits: += scalar qk + point logits ----------------
// grid (2 mh, 128 ny): 4 n x 256 m per block, 192 thr (warp = head pair, 32 m lanes)
#define L_HW   0       // 12 (pad 16)
#define L_QS   16      // 4*192 = 768
#define L_QGS  784     // 4*144 = 576
#define L_KS0  1360    // 32*196 = 6272
#define L_KG0  7632    // 32*148 = 4736
#define L_KS1  12368   // 6272
#define L_KG1  18640   // 4736
#define L_END  23376   // floats = 93504 B
__global__ void k_logits(const float* __restrict__ hw)
{
    extern __shared__ float sm[];
    const int tid = threadIdx.x;       // 192
    const int n0 = blockIdx.y * 4;
    const int mh = blockIdx.x;

    if (tid < 12) sm[L_HW + tid] = hw[tid];
    for (int i = tid; i < 768; i += 192) sm[L_QS  + i] = g_proj[(size_t)(n0 + i/192)*PROJW + (i%192)];
    for (int i = tid; i < 576; i += 192) sm[L_QGS + i] = g_qg[n0*144 + i];

    auto pf_k = [&](int buf, int m0) {
        float* KS = sm + (buf ? L_KS1 : L_KS0);
        float* KG = sm + (buf ? L_KG1 : L_KG0);
        for (int i = tid; i < 1536; i += 192) {
            const int row = i / 48, q = i - row*48;
            cpa16(KS + row*196 + q*4, g_proj + (size_t)(m0+row)*PROJW + 192 + q*4);
        }
        for (int i = tid; i < 1152; i += 192) {
            const int row = i / 36, q = i - row*36;
            cpa16(KG + row*148 + q*4, g_kg + (m0+row)*144 + q*4);
        }
    };

    pf_k(0, mh*256); CP_COMMIT();

    const int ml = tid & 31;
    const int hp = tid >> 5;
    const int h0 = hp*2, h1 = h0 + 1;
    const float hw0 = -0.5f * hw[h0], hw1 = -0.5f * hw[h1];

    for (int mt = 0; mt < 8; mt++) {
        const int m0 = mh*256 + mt*32;
        if (mt < 7) { pf_k((mt+1)&1, m0+32); CP_COMMIT(); CP_WAIT1(); }
        else        { CP_WAIT0(); }
        __syncthreads();
        const float* KS = sm + ((mt & 1) ? L_KS1 : L_KS0);
        const float* KG = sm + ((mt & 1) ? L_KG1 : L_KG0);
        const float4* k4  = (const float4*)(KS + ml*196);
        const float4* kgv = (const float4*)(KG + ml*148);

#pragma unroll
        for (int ng = 0; ng < 4; ng++) {
            const int n = n0 + ng;
            // scalar logits
            const float4* q40 = (const float4*)(sm + L_QS + ng*192 + h0*16);
            const float4* q41 = (const float4*)(sm + L_QS + ng*192 + h1*16);
            float s0 = 0.f, s1 = 0.f;
#pragma unroll
            for (int c4 = 0; c4 < 4; c4++) {
                const float4 qa = q40[c4], qb = q41[c4];
                const float4 ka = k4[h0*4 + c4], kb = k4[h1*4 + c4];
                s0 = fmaf(qa.x,ka.x, fmaf(qa.y,ka.y, fmaf(qa.z,ka.z, fmaf(qa.w,ka.w, s0))));
                s1 = fmaf(qb.x,kb.x, fmaf(qb.y,kb.y, fmaf(qb.z,kb.z, fmaf(qb.w,kb.w, s1))));
            }
            // point logits
            const float4* qgv0 = (const float4*)(sm + L_QGS + ng*144 + h0*12);
            const float4* qgv1 = qgv0 + 3;
            float pd0 = 0.f, pd1 = 0.f;
#pragma unroll
            for (int j = 0; j < 3; j++) {
                const float4 qa = qgv0[j], ka = kgv[h0*3 + j];
                const float4 qb = qgv1[j], kb = kgv[h1*3 + j];
                float d;
                d = qa.x-ka.x; pd0 = fmaf(d,d,pd0);
                d = qa.y-ka.y; pd0 = fmaf(d,d,pd0);
                d = qa.z-ka.z; pd0 = fmaf(d,d,pd0);
                d = qa.w-ka.w; pd0 = fmaf(d,d,pd0);
                d = qb.x-kb.x; pd1 = fmaf(d,d,pd1);
                d = qb.y-kb.y; pd1 = fmaf(d,d,pd1);
                d = qb.z-kb.z; pd1 = fmaf(d,d,pd1);
                d = qb.w-kb.w; pd1 = fmaf(d,d,pd1);
            }
            const float acc0 = fmaf(s0, 0.25f, hw0 * pd0);
            const float acc1 = fmaf(s1, 0.25f, hw1 * pd1);
            const int m = m0 + ml;
            g_attn[(size_t)h0*N2 + (size_t)n*NRES + m] += acc0;
            g_attn[(size_t)h1*N2 + (size_t)n*NRES + m] += acc1;
        }
        __syncthreads();
    }
}

// ---------------- softmax over m (attn layout [h][n][m]) ----------------
__global__ void k_softmax()
{
    const int n = blockIdx.x;
    const int h = threadIdx.x >> 5, lane = threadIdx.x & 31;   // 384 thr
    float* p = g_attn + (size_t)h*N2 + (size_t)n*NRES;
    float v[16];
    float mx = -1e30f;
#pragma unroll
    for (int i = 0; i < 16; i++) { v[i] = p[lane + 32*i]; mx = fmaxf(mx, v[i]); }
#pragma unroll
    for (int o = 16; o; o >>= 1) mx = fmaxf(mx, __shfl_xor_sync(0xffffffffu, mx, o));
    float sum = 0.f;
#pragma unroll
    for (int i = 0; i < 16; i++) { v[i] = expf(v[i] - mx); sum += v[i]; }
#pragma unroll
    for (int o = 16; o; o >>= 1) sum += __shfl_xor_sync(0xffffffffu, sum, o);
    const float inv = 1.0f / sum;
#pragma unroll
    for (int i = 0; i < 16; i++) p[lane + 32*i] = v[i] * inv;
}

// ---------------- pair_feat (cp.async double-buffered z, float4 attn) ----------------
#define PF_END 17920
__global__ void k_pairfeat(const float* __restrict__ z)
{
    extern __shared__ float sm[];
    const int n = blockIdx.x, tid = threadIdx.x;  // 384 thr
    float* zb[2]  = { sm, sm + 8192 };
    float* atb[2] = { sm + 16384, sm + 17152 };

    const float4* zsrc = (const float4*)(z + (size_t)n * NRES * CZ);

    {
        for (int i = tid; i < 2048; i += 384) cpa16(zb[0] + i*4, zsrc + i);
        if (tid < 192) {
            const int h = tid / 16, q = tid % 16;
            cpa16(atb[0] + h*64 + q*4,
                  g_attn + (size_t)h*N2 + (size_t)n*NRES + q*4);
        }
        CP_COMMIT();
    }

    const int h = tid >> 5;
    const int cq = tid & 31;
    float a0=0.f, a1=0.f, a2=0.f, a3=0.f;

    for (int mc = 0; mc < 8; mc++) {
        if (mc + 1 < 8) {
            const int buf = (mc + 1) & 1;
            const int m0 = (mc + 1) * 64;
            for (int i = tid; i < 2048; i += 384) cpa16(zb[buf] + i*4, zsrc + 2048*(mc+1) + i);
            if (tid < 192) {
                const int hh = tid / 16, q = tid % 16;
                cpa16(atb[buf] + hh*64 + q*4,
                      g_attn + (size_t)hh*N2 + (size_t)n*NRES + m0 + q*4);
            }
            CP_COMMIT();
            CP_WAIT1();
        } else {
            CP_WAIT0();
        }
        __syncthreads();
        const float* zc = zb[mc & 1];
        const float* ac = atb[mc & 1] + h*64;
#pragma unroll 2
        for (int mm4 = 0; mm4 < 16; mm4++) {
            const float4 w = *(const float4*)(ac + mm4*4);
            const float4 z0 = *(const float4*)(zc + (mm4*4+0)*128 + cq*4);
            const float4 z1 = *(const float4*)(zc + (mm4*4+1)*128 + cq*4);
            const float4 z2 = *(const float4*)(zc + (mm4*4+2)*128 + cq*4);
            const float4 z3 = *(const float4*)(zc + (mm4*4+3)*128 + cq*4);
            a0 = fmaf(w.x, z0.x, a0); a1 = fmaf(w.x, z0.y, a1);
            a2 = fmaf(w.x, z0.z, a2); a3 = fmaf(w.x, z0.w, a3);
            a0 = fmaf(w.y, z1.x, a0); a1 = fmaf(w.y, z1.y, a1);
            a2 = fmaf(w.y, z1.z, a2); a3 = fmaf(w.y, z1.w, a3);
            a0 = fmaf(w.z, z2.x, a0); a1 = fmaf(w.z, z2.y, a1);
            a2 = fmaf(w.z, z2.z, a2); a3 = fmaf(w.z, z2.w, a3);
            a0 = fmaf(w.w, z3.x, a0); a1 = fmaf(w.w, z3.y, a1);
            a2 = fmaf(w.w, z3.z, a2); a3 = fmaf(w.w, z3.w, a3);
        }
        __syncthreads();
    }
    float* dst = g_feats + (size_t)n * OUTD + h * HF + 48 + cq * 4;
    dst[0]=a0; dst[1]=a1; dst[2]=a2; dst[3]=a3;
}

// ---------------- out_scalar + out_pts(local) + norms; 4 n per block ----------------
#define OV_AT 0        // 12*128 [h][m][ni]
#define OV_V  1536     // 6144
#define OV_VG 7680     // 9216
#define OV_PG 16896    // 4*288
#define OV_END 18048
__global__ void k_outv(const float* __restrict__ rot, const float* __restrict__ trans)
{
    extern __shared__ float sm[];
    const int n0 = blockIdx.x * 4, tid = threadIdx.x;  // 480 thr, grid 128
    float acc0=0.f, acc1=0.f, acc2=0.f, acc3=0.f;

    for (int mc = 0; mc < 16; mc++) {
        const int m0 = mc * 32;
        __syncthreads();
        // attn transposed: at_s[hh*128 + mm*4 + ni]
        for (int i = tid; i < 1536; i += 480) {
            const int hh = i >> 7, r = i & 127;
            const int ni = r >> 5, mm = r & 31;
            sm[OV_AT + hh*128 + mm*4 + ni] =
                g_attn[(size_t)hh*N2 + (size_t)(n0+ni)*NRES + m0 + mm];
        }
        for (int i = tid; i < 1536; i += 480) {
            const int mm = i / 48, q = i - mm*48;
            cpa16(sm + OV_V + mm*192 + q*4, g_proj + (size_t)(m0+mm)*PROJW + 384 + q*4);
        }
        for (int i = tid; i < 2304; i += 480)
            cpa16(sm + OV_VG + i*4, g_vg + m0*288 + i*4);
        CP_COMMIT(); CP_WAIT0();
        __syncthreads();

        if (tid < 192) {
            const int hh = tid >> 4, c = tid & 15;
            const float* vs = sm + OV_V + hh*16 + c;
            const float4* at4 = (const float4*)(sm + OV_AT + hh*128);
#pragma unroll
            for (int mm = 0; mm < 32; mm++) {
                const float4 w = at4[mm];
                const float vv = vs[mm*192];
                acc0 = fmaf(w.x, vv, acc0);
                acc1 = fmaf(w.y, vv, acc1);
                acc2 = fmaf(w.z, vv, acc2);
                acc3 = fmaf(w.w, vv, acc3);
            }
        } else {
            const int idx = tid - 192, hh = idx / 24, u = idx - hh*24;
            const float* vs = sm + OV_VG + hh*24 + u;
            const float4* at4 = (const float4*)(sm + OV_AT + hh*128);
#pragma unroll
            for (int mm = 0; mm < 32; mm++) {
                const float4 w = at4[mm];
                const float vv = vs[mm*288];
                acc0 = fmaf(w.x, vv, acc0);
                acc1 = fmaf(w.y, vv, acc1);
                acc2 = fmaf(w.z, vv, acc2);
                acc3 = fmaf(w.w, vv, acc3);
            }
        }
    }
    __syncthreads();
    if (tid < 192) {
        const int hh = tid >> 4, c = tid & 15;
        g_feats[(size_t)(n0+0)*OUTD + hh*HF + c] = acc0;
        g_feats[(size_t)(n0+1)*OUTD + hh*HF + c] = acc1;
        g_feats[(size_t)(n0+2)*OUTD + hh*HF + c] = acc2;
        g_feats[(size_t)(n0+3)*OUTD + hh*HF + c] = acc3;
    } else {
        const int idx = tid - 192;
        sm[OV_PG + 0*288 + idx] = acc0;
        sm[OV_PG + 1*288 + idx] = acc1;
        sm[OV_PG + 2*288 + idx] = acc2;
        sm[OV_PG + 3*288 + idx] = acc3;
    }
    __syncthreads();
    if (tid < 384) {
        const int ni = tid / 96, r = tid - ni*96;
        const int hh = r / 8, p = r - hh*8;
        const int n = n0 + ni;
        float R[9];
#pragma unroll
        for (int i = 0; i < 9; i++) R[i] = rot[n*9 + i];
        const float gx = sm[OV_PG + ni*288 + hh*24 + p*3 + 0] - trans[n*3 + 0];
        const float gy = sm[OV_PG + ni*288 + hh*24 + p*3 + 1] - trans[n*3 + 1];
        const float gz = sm[OV_PG + ni*288 + hh*24 + p*3 + 2] - trans[n*3 + 2];
        const float lx = fmaf(R[0],gx, fmaf(R[3],gy, R[6]*gz));
        const float ly = fmaf(R[1],gx, fmaf(R[4],gy, R[7]*gz));
        const float lz = fmaf(R[2],gx, fmaf(R[5],gy, R[8]*gz));
        float* f = g_feats + (size_t)n*OUTD + hh*HF;
        f[16 + p*3 + 0] = lx; f[16 + p*3 + 1] = ly; f[16 + p*3 + 2] = lz;
        f[40 + p] = __fsqrt_rn(fmaf(lx,lx, fmaf(ly,ly, lz*lz)));
    }
}

// ---------------- final GEMM (split-K) ----------------
__global__ void k_sgemm(const float* __restrict__ A, const float* __restrict__ B,
                        float* __restrict__ C, int Nc, int K, int kLen)
{
    __shared__ alignas(16) float As[16][64];
    __shared__ alignas(16) float Bs[16][64];
    const int tid = threadIdx.x;
    const int tx = tid & 15, ty = tid >> 4;
    const int bm = blockIdx.y * 64, bn = blockIdx.x * 64;
    const int k0base = blockIdx.z * kLen;
    C += (size_t)blockIdx.z * (size_t)(gridDim.y * 64) * Nc;

    const int am  = tid >> 2, akq = tid & 3;
    const int bkk = tid >> 4, bn4 = tid & 15;

    float acc[4][4];
#pragma unroll
    for (int i = 0; i < 4; i++)
#pragma unroll
        for (int j = 0; j < 4; j++) acc[i][j] = 0.f;

    for (int kt = 0; kt < kLen; kt += 16) {
        const int k0 = k0base + kt;
        float4 av = *(const float4*)(A + (size_t)(bm + am) * K + k0 + akq * 4);
        As[akq*4+0][am] = av.x; As[akq*4+1][am] = av.y;
        As[akq*4+2][am] = av.z; As[akq*4+3][am] = av.w;
        float4 bv = make_float4(0.f,0.f,0.f,0.f);
        const int col = bn + bn4 * 4;
        if (col < Nc) bv = *(const float4*)(B + (size_t)(k0 + bkk) * Nc + col);
        *(float4*)&Bs[bkk][bn4*4] = bv;
        __syncthreads();
#pragma unroll
        for (int kk = 0; kk < 16; kk++) {
            float4 a = *(const float4*)&As[kk][ty*4];
            float4 b = *(const float4*)&Bs[kk][tx*4];
            acc[0][0]=fmaf(a.x,b.x,acc[0][0]); acc[0][1]=fmaf(a.x,b.y,acc[0][1]);
            acc[0][2]=fmaf(a.x,b.z,acc[0][2]); acc[0][3]=fmaf(a.x,b.w,acc[0][3]);
            acc[1][0]=fmaf(a.y,b.x,acc[1][0]); acc[1][1]=fmaf(a.y,b.y,acc[1][1]);
            acc[1][2]=fmaf(a.y,b.z,acc[1][2]); acc[1][3]=fmaf(a.y,b.w,acc[1][3]);
            acc[2][0]=fmaf(a.z,b.x,acc[2][0]); acc[2][1]=fmaf(a.z,b.y,acc[2][1]);
            acc[2][2]=fmaf(a.z,b.z,acc[2][2]); acc[2][3]=fmaf(a.z,b.w,acc[2][3]);
            acc[3][0]=fmaf(a.w,b.x,acc[3][0]); acc[3][1]=fmaf(a.w,b.y,acc[3][1]);
            acc[3][2]=fmaf(a.w,b.z,acc[3][2]); acc[3][3]=fmaf(a.w,b.w,acc[3][3]);
        }
        __syncthreads();
    }
#pragma unroll
    for (int i = 0; i < 4; i++) {
        const int row = bm + ty * 4 + i;
#pragma unroll
        for (int j = 0; j < 4; j++) {
            const int col = bn + tx * 4 + j;
            if (col < Nc) C[(size_t)row * Nc + col] = acc[i][j];
        }
    }
}

// ---------------- split-K reduce + bias ----------------
__global__ void k_reduce(const float* __restrict__ bout, float* __restrict__ out)
{
    const int i = blockIdx.x * 256 + threadIdx.x;
    const int NE = NRES * CS;
    const float v = g_part[i] + g_part[NE + i] + g_part[2*NE + i] + g_part[3*NE + i];
    out[i] = v + bout[i % CS];
}

// ---------------- launch ----------------
static float* symaddr(const void* sym) {
    void* p = nullptr;
    cudaGetSymbolAddress(&p, sym);
    return (float*)p;
}

extern "C" void kernel_launch(void* const* d_in, const int* in_sizes, int n_in,
                              void* d_out, int out_size) {
    const float* s     = (const float*)d_in[0];
    const float* z     = (const float*)d_in[1];
    const float* trans = (const float*)d_in[2];
    const float* rot   = (const float*)d_in[3];
    const float* Wq    = (const float*)d_in[4];
    const float* bq    = (const float*)d_in[5];
    const float* Wk    = (const float*)d_in[6];
    const float* bk    = (const float*)d_in[7];
    const float* Wv    = (const float*)d_in[8];
    const float* bv    = (const float*)d_in[9];
    const float* Wqp   = (const float*)d_in[10];
    const float* bqp   = (const float*)d_in[11];
    const float* Wkp   = (const float*)d_in[12];
    const float* bkp   = (const float*)d_in[13];
    const float* Wvp   = (const float*)d_in[14];
    const float* bvp   = (const float*)d_in[15];
    const float* Wb    = (const float*)d_in[16];
    const float* bb    = (const float*)d_in[17];
    const float* emb   = (const float*)d_in[18];
    const float* sl    = (const float*)d_in[19];
    const float* hw    = (const float*)d_in[20];
    const float* Wout  = (const float*)d_in[21];
    const float* bout  = (const float*)d_in[22];
    float* out = (float*)d_out;

    float* pf = symaddr(g_feats);
    float* pp = symaddr(g_part);

    cudaFuncSetAttribute(k_pairbias, cudaFuncAttributeMaxDynamicSharedMemorySize, PB_END * (int)sizeof(float));
    cudaFuncSetAttribute(k_logits,   cudaFuncAttributeMaxDynamicSharedMemorySize, L_END  * (int)sizeof(float));
    cudaFuncSetAttribute(k_pairfeat, cudaFuncAttributeMaxDynamicSharedMemorySize, PF_END * (int)sizeof(float));
    cudaFuncSetAttribute(k_outv,     cudaFuncAttributeMaxDynamicSharedMemorySize, OV_END * (int)sizeof(float));

    k_proj<<<dim3(18,8,1), 256>>>(s, Wq,bq, Wk,bk, Wv,bv, Wqp,bqp, Wkp,bkp, Wvp,bvp);
    k_points<<<NRES, 192>>>(rot, trans);
    k_pairbias<<<NRES, 256, PB_END * sizeof(float)>>>(z, trans, Wb, bb, emb, sl);
    k_logits<<<dim3(2,128,1), 192, L_END * sizeof(float)>>>(hw);
    k_softmax<<<NRES, 384>>>();
    k_pairfeat<<<NRES, 384, PF_END * sizeof(float)>>>(z);
    k_outv<<<128, 480, OV_END * sizeof(float)>>>(rot, trans);
    k_sgemm<<<dim3(6,8,4), 256>>>(pf, Wout, pp, CS, OUTD, OUTD/4);
    k_reduce<<<(NRES*CS)/256, 256>>>(bout, out);
}

// round 10
// speedup vs baseline: 2.4294x; 1.0818x over previous
#include <cuda_runtime.h>
#include <math.h>

#define NRES 512
#define CS   384
#define CZ   128
#define NH   12
#define OUTD 2112
#define HF   176
#define PROJW 1152   // 192 q | 192 k | 192 v | 144 qp | 144 kp | 288 vp
#define N2   (NRES*NRES)

// ---------------- scratch ----------------
__device__ alignas(16) float g_proj[NRES*PROJW];
__device__ alignas(16) float g_vg[NRES*288];
__device__ alignas(16) float g_gA[336*NRES];   // [h*28+c][n]: 0.25*q | hw*qg
__device__ alignas(16) float g_gB[336*NRES];   // [h*28+c][m]: k | kg
__device__ alignas(16) float g_gC[NH*NRES];    // [h][m]: -0.5*hw*K2
__device__ alignas(16) float g_attn[(size_t)NH*NRES*NRES];   // [h][n][m]
__device__ alignas(16) float g_feats[(size_t)NRES*OUTD];
__device__ alignas(16) float g_part[(size_t)4*NRES*CS];

// ---------------- cp.async helpers ----------------
__device__ __forceinline__ void cpa16(void* dst_smem, const void* src_gmem) {
    unsigned int d = (unsigned int)__cvta_generic_to_shared(dst_smem);
    asm volatile("cp.async.ca.shared.global [%0], [%1], 16;\n" :: "r"(d), "l"(src_gmem));
}
#define CP_COMMIT() asm volatile("cp.async.commit_group;\n" ::: "memory")
#define CP_WAIT0()  asm volatile("cp.async.wait_group 0;\n" ::: "memory")
#define CP_WAIT1()  asm volatile("cp.async.wait_group 1;\n" ::: "memory")

// ---------------- fused projection GEMM ----------------
__global__ void k_proj(const float* __restrict__ s,
    const float* __restrict__ Wq,  const float* __restrict__ bq,
    const float* __restrict__ Wk,  const float* __restrict__ bk,
    const float* __restrict__ Wv,  const float* __restrict__ bvs,
    const float* __restrict__ Wqp, const float* __restrict__ bqp,
    const float* __restrict__ Wkp, const float* __restrict__ bkp,
    const float* __restrict__ Wvp, const float* __restrict__ bvp)
{
    __shared__ alignas(16) float As[16][64];
    __shared__ alignas(16) float Bs[16][64];
    const int tid = threadIdx.x;
    const int tx = tid & 15, ty = tid >> 4;
    const int bm = blockIdx.y * 64, bn = blockIdx.x * 64;
    const int am  = tid >> 2, akq = tid & 3;
    const int bkk = tid >> 4, bn4 = tid & 15;

    const int gc = bn + bn4 * 4;
    const float* Bp; int bst;
    if (gc < 576)      { const int sg = gc / 192;
                         const float* Ws = (sg == 0) ? Wq : (sg == 1) ? Wk : Wv;
                         Bp = Ws + (gc - sg * 192); bst = 192; }
    else if (gc < 864) { const int sg = (gc - 576) / 144;
                         Bp = ((sg == 0) ? Wqp : Wkp) + (gc - 576 - sg * 144); bst = 144; }
    else               { Bp = Wvp + (gc - 864); bst = 288; }

    float acc[4][4];
#pragma unroll
    for (int i = 0; i < 4; i++)
#pragma unroll
        for (int j = 0; j < 4; j++) acc[i][j] = 0.f;

    for (int k0 = 0; k0 < CS; k0 += 16) {
        float4 av = *(const float4*)(s + (size_t)(bm + am) * CS + k0 + akq * 4);
        As[akq*4+0][am] = av.x; As[akq*4+1][am] = av.y;
        As[akq*4+2][am] = av.z; As[akq*4+3][am] = av.w;
        float4 wv4 = *(const float4*)(Bp + (size_t)(k0 + bkk) * bst);
        *(float4*)&Bs[bkk][bn4*4] = wv4;
        __syncthreads();
#pragma unroll
        for (int kk = 0; kk < 16; kk++) {
            float4 a = *(const float4*)&As[kk][ty*4];
            float4 b = *(const float4*)&Bs[kk][tx*4];
            acc[0][0]=fmaf(a.x,b.x,acc[0][0]); acc[0][1]=fmaf(a.x,b.y,acc[0][1]);
            acc[0][2]=fmaf(a.x,b.z,acc[0][2]); acc[0][3]=fmaf(a.x,b.w,acc[0][3]);
            acc[1][0]=fmaf(a.y,b.x,acc[1][0]); acc[1][1]=fmaf(a.y,b.y,acc[1][1]);
            acc[1][2]=fmaf(a.y,b.z,acc[1][2]); acc[1][3]=fmaf(a.y,b.w,acc[1][3]);
            acc[2][0]=fmaf(a.z,b.x,acc[2][0]); acc[2][1]=fmaf(a.z,b.y,acc[2][1]);
            acc[2][2]=fmaf(a.z,b.z,acc[2][2]); acc[2][3]=fmaf(a.z,b.w,acc[2][3]);
            acc[3][0]=fmaf(a.w,b.x,acc[3][0]); acc[3][1]=fmaf(a.w,b.y,acc[3][1]);
            acc[3][2]=fmaf(a.w,b.z,acc[3][2]); acc[3][3]=fmaf(a.w,b.w,acc[3][3]);
        }
        __syncthreads();
    }
    const int gc0 = bn + tx * 4;
    const float* bptr;
    if (gc0 < 576)      { const int sg = gc0 / 192;
                          bptr = ((sg == 0) ? bq : (sg == 1) ? bk : bvs) + (gc0 - sg * 192); }
    else if (gc0 < 864) { const int sg = (gc0 - 576) / 144;
                          bptr = ((sg == 0) ? bqp : bkp) + (gc0 - 576 - sg * 144); }
    else                { bptr = bvp + (gc0 - 864); }
#pragma unroll
    for (int i = 0; i < 4; i++) {
        const int row = bm + ty * 4 + i;
#pragma unroll
        for (int j = 0; j < 4; j++)
            g_proj[(size_t)row * PROJW + gc0 + j] = acc[i][j] + bptr[j];
    }
}

// ---------------- prep: frames + GEMM operands A/B/C ----------------
__global__ void k_prep(const float* __restrict__ rot, const float* __restrict__ trans,
                       const float* __restrict__ hw)
{
    const int n = blockIdx.x;
    __shared__ float R[9], T[3];
    __shared__ float kgs[144];
    if (threadIdx.x < 9) R[threadIdx.x] = rot[n*9 + threadIdx.x];
    if (threadIdx.x < 3) T[threadIdx.x] = trans[n*3 + threadIdx.x];
    __syncthreads();
    const int t = threadIdx.x;  // 0..191
    const float* row = g_proj + (size_t)n * PROJW;
    if (t < 48) {
        const float* src = row + 576 + t*3;
        const float p0 = src[0], p1 = src[1], p2 = src[2];
        const float gx = fmaf(R[0],p0, fmaf(R[1],p1, fmaf(R[2],p2, T[0])));
        const float gy = fmaf(R[3],p0, fmaf(R[4],p1, fmaf(R[5],p2, T[1])));
        const float gz = fmaf(R[6],p0, fmaf(R[7],p1, fmaf(R[8],p2, T[2])));
        const int h = t >> 2, p = t & 3;
        const float w = hw[h];
        g_gA[(h*28+16+p*3+0)*NRES + n] = w*gx;
        g_gA[(h*28+16+p*3+1)*NRES + n] = w*gy;
        g_gA[(h*28+16+p*3+2)*NRES + n] = w*gz;
    } else if (t < 96) {
        const int u = t - 48;
        const float* src = row + 720 + u*3;
        const float p0 = src[0], p1 = src[1], p2 = src[2];
        const float gx = fmaf(R[0],p0, fmaf(R[1],p1, fmaf(R[2],p2, T[0])));
        const float gy = fmaf(R[3],p0, fmaf(R[4],p1, fmaf(R[5],p2, T[1])));
        const float gz = fmaf(R[6],p0, fmaf(R[7],p1, fmaf(R[8],p2, T[2])));
        const int h = u >> 2, p = u & 3;
        g_gB[(h*28+16+p*3+0)*NRES + n] = gx;
        g_gB[(h*28+16+p*3+1)*NRES + n] = gy;
        g_gB[(h*28+16+p*3+2)*NRES + n] = gz;
        kgs[u*3+0] = gx; kgs[u*3+1] = gy; kgs[u*3+2] = gz;
    } else {
        const int u = t - 96;
        const float* src = row + 864 + u*3;
        float* dst = g_vg + n*288 + u*3;
        const float p0 = src[0], p1 = src[1], p2 = src[2];
        dst[0] = fmaf(R[0],p0, fmaf(R[1],p1, fmaf(R[2],p2, T[0])));
        dst[1] = fmaf(R[3],p0, fmaf(R[4],p1, fmaf(R[5],p2, T[1])));
        dst[2] = fmaf(R[6],p0, fmaf(R[7],p1, fmaf(R[8],p2, T[2])));
    }
    // scalar q/k into A/B
    {
        const int h = t >> 4, c = t & 15;
        g_gA[(h*28+c)*NRES + n] = 0.25f * row[h*16 + c];
        g_gB[(h*28+c)*NRES + n] = row[192 + h*16 + c];
    }
    __syncthreads();
    if (t < 12) {
        float s2 = 0.f;
#pragma unroll
        for (int j = 0; j < 12; j++) s2 = fmaf(kgs[t*12+j], kgs[t*12+j], s2);
        g_gC[t*NRES + n] = -0.5f * hw[t] * s2;
    }
}

// ---------------- pair bias stream (single-buffer, 2 blocks/SM) ----------------
#define PB_WBT 0        // 1536
#define PB_EMB 1536     // 768
#define PB_PH  2304     // 36
#define PB_BB  2340     // 12
#define PB_TN  2352     // 4
#define PB_TM  2356     // 384
#define PB_Z   2740     // 128*132 = 16896
#define PB_END 19636    // 78544 B
__global__ void k_pairbias(const float* __restrict__ z, const float* __restrict__ trans,
                           const float* __restrict__ Wb, const float* __restrict__ bb,
                           const float* __restrict__ emb, const float* __restrict__ sl)
{
    extern __shared__ float sm[];
    const int n = blockIdx.x, tid = threadIdx.x;  // 256 thr

    auto pf = [&](int mc) {
        const float4* zsrc = (const float4*)(z + ((size_t)n * NRES + mc*128) * CZ);
        float* zb = sm + PB_Z;
        for (int i = tid; i < 4096; i += 256)
            cpa16(zb + (i >> 5)*132 + (i & 31)*4, zsrc + i);
        if (tid < 96)
            cpa16(sm + PB_TM + tid*4, trans + mc*384 + tid*4);
    };
    pf(0); CP_COMMIT();

    for (int i = tid; i < 1536; i += 256) {
        const int h = i >> 7, c = i & 127;
        sm[PB_WBT + i] = Wb[c*NH + h];
    }
    for (int i = tid; i < 768; i += 256) sm[PB_EMB + i] = emb[i];
    if (tid < 12) {
        sm[PB_BB + tid] = bb[tid];
        const float e0 = expf(sl[tid]), e1 = expf(sl[12+tid]), e2 = expf(sl[24+tid]);
        const float inv = 1.0f / (e0 + e1 + e2);
        sm[PB_PH + tid] = e0*inv; sm[PB_PH + 12 + tid] = e1*inv; sm[PB_PH + 24 + tid] = e2*inv;
    }
    if (tid < 3) sm[PB_TN + tid] = trans[n*3 + tid];

    const int ml = tid & 127;
    const int hb = (tid >> 7) * 6;

    for (int mc = 0; mc < 4; mc++) {
        CP_WAIT0();
        __syncthreads();
        const float4* zr = (const float4*)(sm + PB_Z + ml*132);
        const float* tm = sm + PB_TM;

        float a[6][4];
#pragma unroll
        for (int j = 0; j < 6; j++) { a[j][0]=0.f; a[j][1]=0.f; a[j][2]=0.f; a[j][3]=0.f; }
#pragma unroll 8
        for (int c4 = 0; c4 < 32; c4++) {
            const float4 zv = zr[c4];
#pragma unroll
            for (int j = 0; j < 6; j++) {
                const float4 w = ((const float4*)(sm + PB_WBT + (hb+j)*128))[c4];
                a[j][0] = fmaf(zv.x, w.x, a[j][0]);
                a[j][1] = fmaf(zv.y, w.y, a[j][1]);
                a[j][2] = fmaf(zv.z, w.z, a[j][2]);
                a[j][3] = fmaf(zv.w, w.w, a[j][3]);
            }
        }
        const float dx = sm[PB_TN+0] - tm[ml*3+0];
        const float dy = sm[PB_TN+1] - tm[ml*3+1];
        const float dz = sm[PB_TN+2] - tm[ml*3+2];
        const float dist = __fsqrt_rn(fmaf(dx,dx, fmaf(dy,dy, dz*dz)));
        int bin = (int)ceilf(dist * 2.0f) - 1;
        bin = max(0, min(63, bin));
        const int msrow = (dist <= 5.0f) ? 0 : (dist <= 15.0f) ? 12 : -1;
        const int m = mc*128 + ml;
#pragma unroll
        for (int j = 0; j < 6; j++) {
            const int h = hb + j;
            float v = sm[PB_BB + h] + ((a[j][0]+a[j][1]) + (a[j][2]+a[j][3]));
            v += sm[PB_EMB + bin*12 + h] + sm[PB_PH + 24 + h];
            if (msrow >= 0) v += sm[PB_PH + msrow + h];
            g_attn[(size_t)h*N2 + (size_t)n*NRES + m] = v;
        }
        __syncthreads();
        if (mc < 3) { pf(mc+1); CP_COMMIT(); }
    }
}

// ---------------- geometry logits as batched GEMM K=28 ----------------
__global__ void k_geo()
{
    __shared__ alignas(16) float As[28][64];
    __shared__ alignas(16) float Bs[28][64];
    __shared__ alignas(16) float Cs[64];
    const int h = blockIdx.z;
    const int n0 = blockIdx.y * 64, m0 = blockIdx.x * 64;
    const int tid = threadIdx.x;
    const int tx = tid & 15, ty = tid >> 4;

    for (int i = tid; i < 1792; i += 256) {
        const int c = i >> 6, r = i & 63;
        As[c][r] = g_gA[(size_t)(h*28+c)*NRES + n0 + r];
        Bs[c][r] = g_gB[(size_t)(h*28+c)*NRES + m0 + r];
    }
    if (tid < 64) Cs[tid] = g_gC[h*NRES + m0 + tid];
    __syncthreads();

    float acc[4][4];
#pragma unroll
    for (int i = 0; i < 4; i++)
#pragma unroll
        for (int j = 0; j < 4; j++) acc[i][j] = 0.f;

#pragma unroll
    for (int c = 0; c < 28; c++) {
        const float4 a = *(const float4*)&As[c][ty*4];
        const float4 b = *(const float4*)&Bs[c][tx*4];
        acc[0][0]=fmaf(a.x,b.x,acc[0][0]); acc[0][1]=fmaf(a.x,b.y,acc[0][1]);
        acc[0][2]=fmaf(a.x,b.z,acc[0][2]); acc[0][3]=fmaf(a.x,b.w,acc[0][3]);
        acc[1][0]=fmaf(a.y,b.x,acc[1][0]); acc[1][1]=fmaf(a.y,b.y,acc[1][1]);
        acc[1][2]=fmaf(a.y,b.z,acc[1][2]); acc[1][3]=fmaf(a.y,b.w,acc[1][3]);
        acc[2][0]=fmaf(a.z,b.x,acc[2][0]); acc[2][1]=fmaf(a.z,b.y,acc[2][1]);
        acc[2][2]=fmaf(a.z,b.z,acc[2][2]); acc[2][3]=fmaf(a.z,b.w,acc[2][3]);
        acc[3][0]=fmaf(a.w,b.x,acc[3][0]); acc[3][1]=fmaf(a.w,b.y,acc[3][1]);
        acc[3][2]=fmaf(a.w,b.z,acc[3][2]); acc[3][3]=fmaf(a.w,b.w,acc[3][3]);
    }
    const float4 cv = *(const float4*)&Cs[tx*4];
#pragma unroll
    for (int i = 0; i < 4; i++) {
        float4* gp = (float4*)(g_attn + (size_t)h*N2 + (size_t)(n0 + ty*4 + i)*NRES + m0 + tx*4);
        float4 o = *gp;
        o.x += acc[i][0] + cv.x;
        o.y += acc[i][1] + cv.y;
        o.z += acc[i][2] + cv.z;
        o.w += acc[i][3] + cv.w;
        *gp = o;
    }
}

// ---------------- softmax over m ----------------
__global__ void k_softmax()
{
    const int n = blockIdx.x;
    const int h = threadIdx.x >> 5, lane = threadIdx.x & 31;   // 384 thr
    float* p = g_attn + (size_t)h*N2 + (size_t)n*NRES;
    float v[16];
    float mx = -1e30f;
#pragma unroll
    for (int i = 0; i < 16; i++) { v[i] = p[lane + 32*i]; mx = fmaxf(mx, v[i]); }
#pragma unroll
    for (int o = 16; o; o >>= 1) mx = fmaxf(mx, __shfl_xor_sync(0xffffffffu, mx, o));
    float sum = 0.f;
#pragma unroll
    for (int i = 0; i < 16; i++) { v[i] = expf(v[i] - mx); sum += v[i]; }
#pragma unroll
    for (int o = 16; o; o >>= 1) sum += __shfl_xor_sync(0xffffffffu, sum, o);
    const float inv = 1.0f / sum;
#pragma unroll
    for (int i = 0; i < 16; i++) p[lane + 32*i] = v[i] * inv;
}

// ---------------- pair_feat (cp.async double-buffered z) ----------------
#define PF_END 17920
__global__ void k_pairfeat(const float* __restrict__ z)
{
    extern __shared__ float sm[];
    const int n = blockIdx.x, tid = threadIdx.x;  // 384 thr
    float* zb[2]  = { sm, sm + 8192 };
    float* atb[2] = { sm + 16384, sm + 17152 };

    const float4* zsrc = (const float4*)(z + (size_t)n * NRES * CZ);

    {
        for (int i = tid; i < 2048; i += 384) cpa16(zb[0] + i*4, zsrc + i);
        if (tid < 192) {
            const int h = tid / 16, q = tid % 16;
            cpa16(atb[0] + h*64 + q*4,
                  g_attn + (size_t)h*N2 + (size_t)n*NRES + q*4);
        }
        CP_COMMIT();
    }

    const int h = tid >> 5;
    const int cq = tid & 31;
    float a0=0.f, a1=0.f, a2=0.f, a3=0.f;

    for (int mc = 0; mc < 8; mc++) {
        if (mc + 1 < 8) {
            const int buf = (mc + 1) & 1;
            const int m0 = (mc + 1) * 64;
            for (int i = tid; i < 2048; i += 384) cpa16(zb[buf] + i*4, zsrc + 2048*(mc+1) + i);
            if (tid < 192) {
                const int hh = tid / 16, q = tid % 16;
                cpa16(atb[buf] + hh*64 + q*4,
                      g_attn + (size_t)hh*N2 + (size_t)n*NRES + m0 + q*4);
            }
            CP_COMMIT();
            CP_WAIT1();
        } else {
            CP_WAIT0();
        }
        __syncthreads();
        const float* zc = zb[mc & 1];
        const float* ac = atb[mc & 1] + h*64;
#pragma unroll 2
        for (int mm4 = 0; mm4 < 16; mm4++) {
            const float4 w = *(const float4*)(ac + mm4*4);
            const float4 z0 = *(const float4*)(zc + (mm4*4+0)*128 + cq*4);
            const float4 z1 = *(const float4*)(zc + (mm4*4+1)*128 + cq*4);
            const float4 z2 = *(const float4*)(zc + (mm4*4+2)*128 + cq*4);
            const float4 z3 = *(const float4*)(zc + (mm4*4+3)*128 + cq*4);
            a0 = fmaf(w.x, z0.x, a0); a1 = fmaf(w.x, z0.y, a1);
            a2 = fmaf(w.x, z0.z, a2); a3 = fmaf(w.x, z0.w, a3);
            a0 = fmaf(w.y, z1.x, a0); a1 = fmaf(w.y, z1.y, a1);
            a2 = fmaf(w.y, z1.z, a2); a3 = fmaf(w.y, z1.w, a3);
            a0 = fmaf(w.z, z2.x, a0); a1 = fmaf(w.z, z2.y, a1);
            a2 = fmaf(w.z, z2.z, a2); a3 = fmaf(w.z, z2.w, a3);
            a0 = fmaf(w.w, z3.x, a0); a1 = fmaf(w.w, z3.y, a1);
            a2 = fmaf(w.w, z3.z, a2); a3 = fmaf(w.w, z3.w, a3);
        }
        __syncthreads();
    }
    float* dst = g_feats + (size_t)n * OUTD + h * HF + 48 + cq * 4;
    dst[0]=a0; dst[1]=a1; dst[2]=a2; dst[3]=a3;
}

// ---------------- out_scalar + out_pts(local) + norms; 4 n per block ----------------
#define OV_AT 0        // 12*128 [h][m][ni]
#define OV_V  1536     // 6144
#define OV_VG 7680     // 9216
#define OV_PG 16896    // 4*288
#define OV_END 18048
__global__ void k_outv(const float* __restrict__ rot, const float* __restrict__ trans)
{
    extern __shared__ float sm[];
    const int n0 = blockIdx.x * 4, tid = threadIdx.x;  // 480 thr, grid 128
    float acc0=0.f, acc1=0.f, acc2=0.f, acc3=0.f;

    for (int mc = 0; mc < 16; mc++) {
        const int m0 = mc * 32;
        __syncthreads();
        for (int i = tid; i < 1536; i += 480) {
            const int hh = i >> 7, r = i & 127;
            const int ni = r >> 5, mm = r & 31;
            sm[OV_AT + hh*128 + mm*4 + ni] =
                g_attn[(size_t)hh*N2 + (size_t)(n0+ni)*NRES + m0 + mm];
        }
        for (int i = tid; i < 1536; i += 480) {
            const int mm = i / 48, q = i - mm*48;
            cpa16(sm + OV_V + mm*192 + q*4, g_proj + (size_t)(m0+mm)*PROJW + 384 + q*4);
        }
        for (int i = tid; i < 2304; i += 480)
            cpa16(sm + OV_VG + i*4, g_vg + m0*288 + i*4);
        CP_COMMIT(); CP_WAIT0();
        __syncthreads();

        if (tid < 192) {
            const int hh = tid >> 4, c = tid & 15;
            const float* vs = sm + OV_V + hh*16 + c;
            const float4* at4 = (const float4*)(sm + OV_AT + hh*128);
#pragma unroll
            for (int mm = 0; mm < 32; mm++) {
                const float4 w = at4[mm];
                const float vv = vs[mm*192];
                acc0 = fmaf(w.x, vv, acc0);
                acc1 = fmaf(w.y, vv, acc1);
                acc2 = fmaf(w.z, vv, acc2);
                acc3 = fmaf(w.w, vv, acc3);
            }
        } else {
            const int idx = tid - 192, hh = idx / 24, u = idx - hh*24;
            const float* vs = sm + OV_VG + hh*24 + u;
            const float4* at4 = (const float4*)(sm + OV_AT + hh*128);
#pragma unroll
            for (int mm = 0; mm < 32; mm++) {
                const float4 w = at4[mm];
                const float vv = vs[mm*288];
                acc0 = fmaf(w.x, vv, acc0);
                acc1 = fmaf(w.y, vv, acc1);
                acc2 = fmaf(w.z, vv, acc2);
                acc3 = fmaf(w.w, vv, acc3);
            }
        }
    }
    __syncthreads();
    if (tid < 192) {
        const int hh = tid >> 4, c = tid & 15;
        g_feats[(size_t)(n0+0)*OUTD + hh*HF + c] = acc0;
        g_feats[(size_t)(n0+1)*OUTD + hh*HF + c] = acc1;
        g_feats[(size_t)(n0+2)*OUTD + hh*HF + c] = acc2;
        g_feats[(size_t)(n0+3)*OUTD + hh*HF + c] = acc3;
    } else {
        const int idx = tid - 192;
        sm[OV_PG + 0*288 + idx] = acc0;
        sm[OV_PG + 1*288 + idx] = acc1;
        sm[OV_PG + 2*288 + idx] = acc2;
        sm[OV_PG + 3*288 + idx] = acc3;
    }
    __syncthreads();
    if (tid < 384) {
        const int ni = tid / 96, r = tid - ni*96;
        const int hh = r / 8, p = r - hh*8;
        const int n = n0 + ni;
        float R[9];
#pragma unroll
        for (int i = 0; i < 9; i++) R[i] = rot[n*9 + i];
        const float gx = sm[OV_PG + ni*288 + hh*24 + p*3 + 0] - trans[n*3 + 0];
        const float gy = sm[OV_PG + ni*288 + hh*24 + p*3 + 1] - trans[n*3 + 1];
        const float gz = sm[OV_PG + ni*288 + hh*24 + p*3 + 2] - trans[n*3 + 2];
        const float lx = fmaf(R[0],gx, fmaf(R[3],gy, R[6]*gz));
        const float ly = fmaf(R[1],gx, fmaf(R[4],gy, R[7]*gz));
        const float lz = fmaf(R[2],gx, fmaf(R[5],gy, R[8]*gz));
        float* f = g_feats + (size_t)n*OUTD + hh*HF;
        f[16 + p*3 + 0] = lx; f[16 + p*3 + 1] = ly; f[16 + p*3 + 2] = lz;
        f[40 + p] = __fsqrt_rn(fmaf(lx,lx, fmaf(ly,ly, lz*lz)));
    }
}

// ---------------- final GEMM (split-K) ----------------
__global__ void k_sgemm(const float* __restrict__ A, const float* __restrict__ B,
                        float* __restrict__ C, int Nc, int K, int kLen)
{
    __shared__ alignas(16) float As[16][64];
    __shared__ alignas(16) float Bs[16][64];
    const int tid = threadIdx.x;
    const int tx = tid & 15, ty = tid >> 4;
    const int bm = blockIdx.y * 64, bn = blockIdx.x * 64;
    const int k0base = blockIdx.z * kLen;
    C += (size_t)blockIdx.z * (size_t)(gridDim.y * 64) * Nc;

    const int am  = tid >> 2, akq = tid & 3;
    const int bkk = tid >> 4, bn4 = tid & 15;

    float acc[4][4];
#pragma unroll
    for (int i = 0; i < 4; i++)
#pragma unroll
        for (int j = 0; j < 4; j++) acc[i][j] = 0.f;

    for (int kt = 0; kt < kLen; kt += 16) {
        const int k0 = k0base + kt;
        float4 av = *(const float4*)(A + (size_t)(bm + am) * K + k0 + akq * 4);
        As[akq*4+0][am] = av.x; As[akq*4+1][am] = av.y;
        As[akq*4+2][am] = av.z; As[akq*4+3][am] = av.w;
        float4 bv = make_float4(0.f,0.f,0.f,0.f);
        const int col = bn + bn4 * 4;
        if (col < Nc) bv = *(const float4*)(B + (size_t)(k0 + bkk) * Nc + col);
        *(float4*)&Bs[bkk][bn4*4] = bv;
        __syncthreads();
#pragma unroll
        for (int kk = 0; kk < 16; kk++) {
            float4 a = *(const float4*)&As[kk][ty*4];
            float4 b = *(const float4*)&Bs[kk][tx*4];
            acc[0][0]=fmaf(a.x,b.x,acc[0][0]); acc[0][1]=fmaf(a.x,b.y,acc[0][1]);
            acc[0][2]=fmaf(a.x,b.z,acc[0][2]); acc[0][3]=fmaf(a.x,b.w,acc[0][3]);
            acc[1][0]=fmaf(a.y,b.x,acc[1][0]); acc[1][1]=fmaf(a.y,b.y,acc[1][1]);
            acc[1][2]=fmaf(a.y,b.z,acc[1][2]); acc[1][3]=fmaf(a.y,b.w,acc[1][3]);
            acc[2][0]=fmaf(a.z,b.x,acc[2][0]); acc[2][1]=fmaf(a.z,b.y,acc[2][1]);
            acc[2][2]=fmaf(a.z,b.z,acc[2][2]); acc[2][3]=fmaf(a.z,b.w,acc[2][3]);
            acc[3][0]=fmaf(a.w,b.x,acc[3][0]); acc[3][1]=fmaf(a.w,b.y,acc[3][1]);
            acc[3][2]=fmaf(a.w,b.z,acc[3][2]); acc[3][3]=fmaf(a.w,b.w,acc[3][3]);
        }
        __syncthreads();
    }
#pragma unroll
    for (int i = 0; i < 4; i++) {
        const int row = bm + ty * 4 + i;
#pragma unroll
        for (int j = 0; j < 4; j++) {
            const int col = bn + tx * 4 + j;
            if (col < Nc) C[(size_t)row * Nc + col] = acc[i][j];
        }
    }
}

// ---------------- split-K reduce + bias ----------------
__global__ void k_reduce(const float* __restrict__ bout, float* __restrict__ out)
{
    const int i = blockIdx.x * 256 + threadIdx.x;
    const int NE = NRES * CS;
    const float v = g_part[i] + g_part[NE + i] + g_part[2*NE + i] + g_part[3*NE + i];
    out[i] = v + bout[i % CS];
}

// ---------------- launch ----------------
static float* symaddr(const void* sym) {
    void* p = nullptr;
    cudaGetSymbolAddress(&p, sym);
    return (float*)p;
}

extern "C" void kernel_launch(void* const* d_in, const int* in_sizes, int n_in,
                              void* d_out, int out_size) {
    const float* s     = (const float*)d_in[0];
    const float* z     = (const float*)d_in[1];
    const float* trans = (const float*)d_in[2];
    const float* rot   = (const float*)d_in[3];
    const float* Wq    = (const float*)d_in[4];
    const float* bq    = (const float*)d_in[5];
    const float* Wk    = (const float*)d_in[6];
    const float* bk    = (const float*)d_in[7];
    const float* Wv    = (const float*)d_in[8];
    const float* bv    = (const float*)d_in[9];
    const float* Wqp   = (const float*)d_in[10];
    const float* bqp   = (const float*)d_in[11];
    const float* Wkp   = (const float*)d_in[12];
    const float* bkp   = (const float*)d_in[13];
    const float* Wvp   = (const float*)d_in[14];
    const float* bvp   = (const float*)d_in[15];
    const float* Wb    = (const float*)d_in[16];
    const float* bb    = (const float*)d_in[17];
    const float* emb   = (const float*)d_in[18];
    const float* sl    = (const float*)d_in[19];
    const float* hw    = (const float*)d_in[20];
    const float* Wout  = (const float*)d_in[21];
    const float* bout  = (const float*)d_in[22];
    float* out = (float*)d_out;

    float* pf = symaddr(g_feats);
    float* pp = symaddr(g_part);

    cudaFuncSetAttribute(k_pairbias, cudaFuncAttributeMaxDynamicSharedMemorySize, PB_END * (int)sizeof(float));
    cudaFuncSetAttribute(k_pairfeat, cudaFuncAttributeMaxDynamicSharedMemorySize, PF_END * (int)sizeof(float));
    cudaFuncSetAttribute(k_outv,     cudaFuncAttributeMaxDynamicSharedMemorySize, OV_END * (int)sizeof(float));

    k_proj<<<dim3(18,8,1), 256>>>(s, Wq,bq, Wk,bk, Wv,bv, Wqp,bqp, Wkp,bkp, Wvp,bvp);
    k_prep<<<NRES, 192>>>(rot, trans, hw);
    k_pairbias<<<NRES, 256, PB_END * sizeof(float)>>>(z, trans, Wb, bb, emb, sl);
    k_geo<<<dim3(8,8,12), 256>>>();
    k_softmax<<<NRES, 384>>>();
    k_pairfeat<<<NRES, 384, PF_END * sizeof(float)>>>(z);
    k_outv<<<128, 480, OV_END * sizeof(float)>>>(rot, trans);
    k_sgemm<<<dim3(6,8,4), 256>>>(pf, Wout, pp, CS, OUTD, OUTD/4);
    k_reduce<<<(NRES*CS)/256, 256>>>(bout, out);
}

// round 12
// speedup vs baseline: 2.7747x; 1.1421x over previous
#include <cuda_runtime.h>
#include <math.h>

#define NRES 512
#define CS   384
#define CZ   128
#define NH   12
#define OUTD 2112
#define HF   176
#define PROJW 1152   // 192 q | 192 k | 192 v | 144 qp | 144 kp | 288 vp
#define N2   (NRES*NRES)

// ---------------- scratch ----------------
__device__ alignas(16) float g_proj[NRES*PROJW];
__device__ alignas(16) float g_vg[NRES*288];
__device__ alignas(16) float g_gA[336*NRES];   // [h*28+c][n]: 0.25*q | hw*qg
__device__ alignas(16) float g_gB[336*NRES];   // [h*28+c][m]: k | kg
__device__ alignas(16) float g_gC[NH*NRES];    // [h][m]: -0.5*hw*K2
__device__ alignas(16) float g_attn[(size_t)NH*NRES*NRES];   // [h][n][m]
__device__ alignas(16) float g_feats[(size_t)NRES*OUTD];
__device__ alignas(16) float g_part[(size_t)4*NRES*CS];

// ---------------- cp.async helpers ----------------
__device__ __forceinline__ void cpa16(void* dst_smem, const void* src_gmem) {
    unsigned int d = (unsigned int)__cvta_generic_to_shared(dst_smem);
    asm volatile("cp.async.ca.shared.global [%0], [%1], 16;\n" :: "r"(d), "l"(src_gmem));
}
#define CP_COMMIT() asm volatile("cp.async.commit_group;\n" ::: "memory")
#define CP_WAIT0()  asm volatile("cp.async.wait_group 0;\n" ::: "memory")
#define CP_WAIT1()  asm volatile("cp.async.wait_group 1;\n" ::: "memory")

// ---------------- fused projection GEMM ----------------
__global__ void k_proj(const float* __restrict__ s,
    const float* __restrict__ Wq,  const float* __restrict__ bq,
    const float* __restrict__ Wk,  const float* __restrict__ bk,
    const float* __restrict__ Wv,  const float* __restrict__ bvs,
    const float* __restrict__ Wqp, const float* __restrict__ bqp,
    const float* __restrict__ Wkp, const float* __restrict__ bkp,
    const float* __restrict__ Wvp, const float* __restrict__ bvp)
{
    __shared__ alignas(16) float As[16][64];
    __shared__ alignas(16) float Bs[16][64];
    const int tid = threadIdx.x;
    const int tx = tid & 15, ty = tid >> 4;
    const int bm = blockIdx.y * 64, bn = blockIdx.x * 64;
    const int am  = tid >> 2, akq = tid & 3;
    const int bkk = tid >> 4, bn4 = tid & 15;

    const int gc = bn + bn4 * 4;
    const float* Bp; int bst;
    if (gc < 576)      { const int sg = gc / 192;
                         const float* Ws = (sg == 0) ? Wq : (sg == 1) ? Wk : Wv;
                         Bp = Ws + (gc - sg * 192); bst = 192; }
    else if (gc < 864) { const int sg = (gc - 576) / 144;
                         Bp = ((sg == 0) ? Wqp : Wkp) + (gc - 576 - sg * 144); bst = 144; }
    else               { Bp = Wvp + (gc - 864); bst = 288; }

    float acc[4][4];
#pragma unroll
    for (int i = 0; i < 4; i++)
#pragma unroll
        for (int j = 0; j < 4; j++) acc[i][j] = 0.f;

    for (int k0 = 0; k0 < CS; k0 += 16) {
        float4 av = *(const float4*)(s + (size_t)(bm + am) * CS + k0 + akq * 4);
        As[akq*4+0][am] = av.x; As[akq*4+1][am] = av.y;
        As[akq*4+2][am] = av.z; As[akq*4+3][am] = av.w;
        float4 wv4 = *(const float4*)(Bp + (size_t)(k0 + bkk) * bst);
        *(float4*)&Bs[bkk][bn4*4] = wv4;
        __syncthreads();
#pragma unroll
        for (int kk = 0; kk < 16; kk++) {
            float4 a = *(const float4*)&As[kk][ty*4];
            float4 b = *(const float4*)&Bs[kk][tx*4];
            acc[0][0]=fmaf(a.x,b.x,acc[0][0]); acc[0][1]=fmaf(a.x,b.y,acc[0][1]);
            acc[0][2]=fmaf(a.x,b.z,acc[0][2]); acc[0][3]=fmaf(a.x,b.w,acc[0][3]);
            acc[1][0]=fmaf(a.y,b.x,acc[1][0]); acc[1][1]=fmaf(a.y,b.y,acc[1][1]);
            acc[1][2]=fmaf(a.y,b.z,acc[1][2]); acc[1][3]=fmaf(a.y,b.w,acc[1][3]);
            acc[2][0]=fmaf(a.z,b.x,acc[2][0]); acc[2][1]=fmaf(a.z,b.y,acc[2][1]);
            acc[2][2]=fmaf(a.z,b.z,acc[2][2]); acc[2][3]=fmaf(a.z,b.w,acc[2][3]);
            acc[3][0]=fmaf(a.w,b.x,acc[3][0]); acc[3][1]=fmaf(a.w,b.y,acc[3][1]);
            acc[3][2]=fmaf(a.w,b.z,acc[3][2]); acc[3][3]=fmaf(a.w,b.w,acc[3][3]);
        }
        __syncthreads();
    }
    const int gc0 = bn + tx * 4;
    const float* bptr;
    if (gc0 < 576)      { const int sg = gc0 / 192;
                          bptr = ((sg == 0) ? bq : (sg == 1) ? bk : bvs) + (gc0 - sg * 192); }
    else if (gc0 < 864) { const int sg = (gc0 - 576) / 144;
                          bptr = ((sg == 0) ? bqp : bkp) + (gc0 - 576 - sg * 144); }
    else                { bptr = bvp + (gc0 - 864); }
#pragma unroll
    for (int i = 0; i < 4; i++) {
        const int row = bm + ty * 4 + i;
#pragma unroll
        for (int j = 0; j < 4; j++)
            g_proj[(size_t)row * PROJW + gc0 + j] = acc[i][j] + bptr[j];
    }
}

// ---------------- prep: frames + GEMM operands A/B/C ----------------
__global__ void k_prep(const float* __restrict__ rot, const float* __restrict__ trans,
                       const float* __restrict__ hw)
{
    const int n = blockIdx.x;
    __shared__ float R[9], T[3];
    __shared__ float kgs[144];
    if (threadIdx.x < 9) R[threadIdx.x] = rot[n*9 + threadIdx.x];
    if (threadIdx.x < 3) T[threadIdx.x] = trans[n*3 + threadIdx.x];
    __syncthreads();
    const int t = threadIdx.x;  // 0..191
    const float* row = g_proj + (size_t)n * PROJW;
    if (t < 48) {
        const float* src = row + 576 + t*3;
        const float p0 = src[0], p1 = src[1], p2 = src[2];
        const float gx = fmaf(R[0],p0, fmaf(R[1],p1, fmaf(R[2],p2, T[0])));
        const float gy = fmaf(R[3],p0, fmaf(R[4],p1, fmaf(R[5],p2, T[1])));
        const float gz = fmaf(R[6],p0, fmaf(R[7],p1, fmaf(R[8],p2, T[2])));
        const int h = t >> 2, p = t & 3;
        const float w = hw[h];
        g_gA[(h*28+16+p*3+0)*NRES + n] = w*gx;
        g_gA[(h*28+16+p*3+1)*NRES + n] = w*gy;
        g_gA[(h*28+16+p*3+2)*NRES + n] = w*gz;
    } else if (t < 96) {
        const int u = t - 48;
        const float* src = row + 720 + u*3;
        const float p0 = src[0], p1 = src[1], p2 = src[2];
        const float gx = fmaf(R[0],p0, fmaf(R[1],p1, fmaf(R[2],p2, T[0])));
        const float gy = fmaf(R[3],p0, fmaf(R[4],p1, fmaf(R[5],p2, T[1])));
        const float gz = fmaf(R[6],p0, fmaf(R[7],p1, fmaf(R[8],p2, T[2])));
        const int h = u >> 2, p = u & 3;
        g_gB[(h*28+16+p*3+0)*NRES + n] = gx;
        g_gB[(h*28+16+p*3+1)*NRES + n] = gy;
        g_gB[(h*28+16+p*3+2)*NRES + n] = gz;
        kgs[u*3+0] = gx; kgs[u*3+1] = gy; kgs[u*3+2] = gz;
    } else {
        const int u = t - 96;
        const float* src = row + 864 + u*3;
        float* dst = g_vg + n*288 + u*3;
        const float p0 = src[0], p1 = src[1], p2 = src[2];
        dst[0] = fmaf(R[0],p0, fmaf(R[1],p1, fmaf(R[2],p2, T[0])));
        dst[1] = fmaf(R[3],p0, fmaf(R[4],p1, fmaf(R[5],p2, T[1])));
        dst[2] = fmaf(R[6],p0, fmaf(R[7],p1, fmaf(R[8],p2, T[2])));
    }
    {
        const int h = t >> 4, c = t & 15;
        g_gA[(h*28+c)*NRES + n] = 0.25f * row[h*16 + c];
        g_gB[(h*28+c)*NRES + n] = row[192 + h*16 + c];
    }
    __syncthreads();
    if (t < 12) {
        float s2 = 0.f;
#pragma unroll
        for (int j = 0; j < 12; j++) s2 = fmaf(kgs[t*12+j], kgs[t*12+j], s2);
        g_gC[t*NRES + n] = -0.5f * hw[t] * s2;
    }
}

// ---------------- pair bias stream ----------------
#define PB_WBT 0        // 1536
#define PB_EMB 1536     // 768
#define PB_PH  2304     // 36
#define PB_BB  2340     // 12
#define PB_TN  2352     // 4
#define PB_TM  2356     // 384
#define PB_Z   2740     // 128*132 = 16896
#define PB_END 19636    // 78544 B
__global__ void k_pairbias(const float* __restrict__ z, const float* __restrict__ trans,
                           const float* __restrict__ Wb, const float* __restrict__ bb,
                           const float* __restrict__ emb, const float* __restrict__ sl)
{
    extern __shared__ float sm[];
    const int n = blockIdx.x, tid = threadIdx.x;  // 256 thr

    auto pf = [&](int mc) {
        const float4* zsrc = (const float4*)(z + ((size_t)n * NRES + mc*128) * CZ);
        float* zb = sm + PB_Z;
        for (int i = tid; i < 4096; i += 256)
            cpa16(zb + (i >> 5)*132 + (i & 31)*4, zsrc + i);
        if (tid < 96)
            cpa16(sm + PB_TM + tid*4, trans + mc*384 + tid*4);
    };
    pf(0); CP_COMMIT();

    for (int i = tid; i < 1536; i += 256) {
        const int h = i >> 7, c = i & 127;
        sm[PB_WBT + i] = Wb[c*NH + h];
    }
    for (int i = tid; i < 768; i += 256) sm[PB_EMB + i] = emb[i];
    if (tid < 12) {
        sm[PB_BB + tid] = bb[tid];
        const float e0 = expf(sl[tid]), e1 = expf(sl[12+tid]), e2 = expf(sl[24+tid]);
        const float inv = 1.0f / (e0 + e1 + e2);
        sm[PB_PH + tid] = e0*inv; sm[PB_PH + 12 + tid] = e1*inv; sm[PB_PH + 24 + tid] = e2*inv;
    }
    if (tid < 3) sm[PB_TN + tid] = trans[n*3 + tid];

    const int ml = tid & 127;
    const int hb = (tid >> 7) * 6;

    for (int mc = 0; mc < 4; mc++) {
        CP_WAIT0();
        __syncthreads();
        const float4* zr = (const float4*)(sm + PB_Z + ml*132);
        const float* tm = sm + PB_TM;

        float a[6][4];
#pragma unroll
        for (int j = 0; j < 6; j++) { a[j][0]=0.f; a[j][1]=0.f; a[j][2]=0.f; a[j][3]=0.f; }
#pragma unroll 8
        for (int c4 = 0; c4 < 32; c4++) {
            const float4 zv = zr[c4];
#pragma unroll
            for (int j = 0; j < 6; j++) {
                const float4 w = ((const float4*)(sm + PB_WBT + (hb+j)*128))[c4];
                a[j][0] = fmaf(zv.x, w.x, a[j][0]);
                a[j][1] = fmaf(zv.y, w.y, a[j][1]);
                a[j][2] = fmaf(zv.z, w.z, a[j][2]);
                a[j][3] = fmaf(zv.w, w.w, a[j][3]);
            }
        }
        const float dx = sm[PB_TN+0] - tm[ml*3+0];
        const float dy = sm[PB_TN+1] - tm[ml*3+1];
        const float dz = sm[PB_TN+2] - tm[ml*3+2];
        const float dist = __fsqrt_rn(fmaf(dx,dx, fmaf(dy,dy, dz*dz)));
        int bin = (int)ceilf(dist * 2.0f) - 1;
        bin = max(0, min(63, bin));
        const int msrow = (dist <= 5.0f) ? 0 : (dist <= 15.0f) ? 12 : -1;
        const int m = mc*128 + ml;
#pragma unroll
        for (int j = 0; j < 6; j++) {
            const int h = hb + j;
            float v = sm[PB_BB + h] + ((a[j][0]+a[j][1]) + (a[j][2]+a[j][3]));
            v += sm[PB_EMB + bin*12 + h] + sm[PB_PH + 24 + h];
            if (msrow >= 0) v += sm[PB_PH + msrow + h];
            g_attn[(size_t)h*N2 + (size_t)n*NRES + m] = v;
        }
        __syncthreads();
        if (mc < 3) { pf(mc+1); CP_COMMIT(); }
    }
}

// ---------------- geometry logits as batched GEMM K=28 ----------------
__global__ void k_geo()
{
    __shared__ alignas(16) float As[28][64];
    __shared__ alignas(16) float Bs[28][64];
    __shared__ alignas(16) float Cs[64];
    const int h = blockIdx.z;
    const int n0 = blockIdx.y * 64, m0 = blockIdx.x * 64;
    const int tid = threadIdx.x;
    const int tx = tid & 15, ty = tid >> 4;

    for (int i = tid; i < 1792; i += 256) {
        const int c = i >> 6, r = i & 63;
        As[c][r] = g_gA[(size_t)(h*28+c)*NRES + n0 + r];
        Bs[c][r] = g_gB[(size_t)(h*28+c)*NRES + m0 + r];
    }
    if (tid < 64) Cs[tid] = g_gC[h*NRES + m0 + tid];
    __syncthreads();

    float acc[4][4];
#pragma unroll
    for (int i = 0; i < 4; i++)
#pragma unroll
        for (int j = 0; j < 4; j++) acc[i][j] = 0.f;

#pragma unroll
    for (int c = 0; c < 28; c++) {
        const float4 a = *(const float4*)&As[c][ty*4];
        const float4 b = *(const float4*)&Bs[c][tx*4];
        acc[0][0]=fmaf(a.x,b.x,acc[0][0]); acc[0][1]=fmaf(a.x,b.y,acc[0][1]);
        acc[0][2]=fmaf(a.x,b.z,acc[0][2]); acc[0][3]=fmaf(a.x,b.w,acc[0][3]);
        acc[1][0]=fmaf(a.y,b.x,acc[1][0]); acc[1][1]=fmaf(a.y,b.y,acc[1][1]);
        acc[1][2]=fmaf(a.y,b.z,acc[1][2]); acc[1][3]=fmaf(a.y,b.w,acc[1][3]);
        acc[2][0]=fmaf(a.z,b.x,acc[2][0]); acc[2][1]=fmaf(a.z,b.y,acc[2][1]);
        acc[2][2]=fmaf(a.z,b.z,acc[2][2]); acc[2][3]=fmaf(a.z,b.w,acc[2][3]);
        acc[3][0]=fmaf(a.w,b.x,acc[3][0]); acc[3][1]=fmaf(a.w,b.y,acc[3][1]);
        acc[3][2]=fmaf(a.w,b.z,acc[3][2]); acc[3][3]=fmaf(a.w,b.w,acc[3][3]);
    }
    const float4 cv = *(const float4*)&Cs[tx*4];
#pragma unroll
    for (int i = 0; i < 4; i++) {
        float4* gp = (float4*)(g_attn + (size_t)h*N2 + (size_t)(n0 + ty*4 + i)*NRES + m0 + tx*4);
        float4 o = *gp;
        o.x += acc[i][0] + cv.x;
        o.y += acc[i][1] + cv.y;
        o.z += acc[i][2] + cv.z;
        o.w += acc[i][3] + cv.w;
        *gp = o;
    }
}

// ---------------- softmax over m ----------------
__global__ void k_softmax()
{
    const int n = blockIdx.x;
    const int h = threadIdx.x >> 5, lane = threadIdx.x & 31;   // 384 thr
    float* p = g_attn + (size_t)h*N2 + (size_t)n*NRES;
    float v[16];
    float mx = -1e30f;
#pragma unroll
    for (int i = 0; i < 16; i++) { v[i] = p[lane + 32*i]; mx = fmaxf(mx, v[i]); }
#pragma unroll
    for (int o = 16; o; o >>= 1) mx = fmaxf(mx, __shfl_xor_sync(0xffffffffu, mx, o));
    float sum = 0.f;
#pragma unroll
    for (int i = 0; i < 16; i++) { v[i] = __expf(v[i] - mx); sum += v[i]; }
#pragma unroll
    for (int o = 16; o; o >>= 1) sum += __shfl_xor_sync(0xffffffffu, sum, o);
    const float inv = 1.0f / sum;
#pragma unroll
    for (int i = 0; i < 16; i++) p[lane + 32*i] = v[i] * inv;
}

// ---------------- pair_feat (cp.async double-buffered z) ----------------
#define PF_END 17920
__global__ void k_pairfeat(const float* __restrict__ z)
{
    extern __shared__ float sm[];
    const int n = blockIdx.x, tid = threadIdx.x;  // 384 thr
    float* zb[2]  = { sm, sm + 8192 };
    float* atb[2] = { sm + 16384, sm + 17152 };

    const float4* zsrc = (const float4*)(z + (size_t)n * NRES * CZ);

    {
        for (int i = tid; i < 2048; i += 384) cpa16(zb[0] + i*4, zsrc + i);
        if (tid < 192) {
            const int h = tid / 16, q = tid % 16;
            cpa16(atb[0] + h*64 + q*4,
                  g_attn + (size_t)h*N2 + (size_t)n*NRES + q*4);
        }
        CP_COMMIT();
    }

    const int h = tid >> 5;
    const int cq = tid & 31;
    float a0=0.f, a1=0.f, a2=0.f, a3=0.f;

    for (int mc = 0; mc < 8; mc++) {
        if (mc + 1 < 8) {
            const int buf = (mc + 1) & 1;
            const int m0 = (mc + 1) * 64;
            for (int i = tid; i < 2048; i += 384) cpa16(zb[buf] + i*4, zsrc + 2048*(mc+1) + i);
            if (tid < 192) {
                const int hh = tid / 16, q = tid % 16;
                cpa16(atb[buf] + hh*64 + q*4,
                      g_attn + (size_t)hh*N2 + (size_t)n*NRES + m0 + q*4);
            }
            CP_COMMIT();
            CP_WAIT1();
        } else {
            CP_WAIT0();
        }
        __syncthreads();
        const float* zc = zb[mc & 1];
        const float* ac = atb[mc & 1] + h*64;
#pragma unroll 2
        for (int mm4 = 0; mm4 < 16; mm4++) {
            const float4 w = *(const float4*)(ac + mm4*4);
            const float4 z0 = *(const float4*)(zc + (mm4*4+0)*128 + cq*4);
            const float4 z1 = *(const float4*)(zc + (mm4*4+1)*128 + cq*4);
            const float4 z2 = *(const float4*)(zc + (mm4*4+2)*128 + cq*4);
            const float4 z3 = *(const float4*)(zc + (mm4*4+3)*128 + cq*4);
            a0 = fmaf(w.x, z0.x, a0); a1 = fmaf(w.x, z0.y, a1);
            a2 = fmaf(w.x, z0.z, a2); a3 = fmaf(w.x, z0.w, a3);
            a0 = fmaf(w.y, z1.x, a0); a1 = fmaf(w.y, z1.y, a1);
            a2 = fmaf(w.y, z1.z, a2); a3 = fmaf(w.y, z1.w, a3);
            a0 = fmaf(w.z, z2.x, a0); a1 = fmaf(w.z, z2.y, a1);
            a2 = fmaf(w.z, z2.z, a2); a3 = fmaf(w.z, z2.w, a3);
            a0 = fmaf(w.w, z3.x, a0); a1 = fmaf(w.w, z3.y, a1);
            a2 = fmaf(w.w, z3.z, a2); a3 = fmaf(w.w, z3.w, a3);
        }
        __syncthreads();
    }
    float* dst = g_feats + (size_t)n * OUTD + h * HF + 48 + cq * 4;
    dst[0]=a0; dst[1]=a1; dst[2]=a2; dst[3]=a3;
}

// ---------------- out_scalar + out_pts(local) + norms; 4 n per block ----------------
#define OV_AT 0        // 12*128 [h][m][ni]
#define OV_V  1536     // 6144
#define OV_VG 7680     // 9216
#define OV_PG 16896    // 4*288
#define OV_END 18048
__global__ void k_outv(const float* __restrict__ rot, const float* __restrict__ trans)
{
    extern __shared__ float sm[];
    const int n0 = blockIdx.x * 4, tid = threadIdx.x;  // 480 thr, grid 128
    float acc0=0.f, acc1=0.f, acc2=0.f, acc3=0.f;

    for (int mc = 0; mc < 16; mc++) {
        const int m0 = mc * 32;
        __syncthreads();
        for (int i = tid; i < 1536; i += 480) {
            const int hh = i >> 7, r = i & 127;
            const int ni = r >> 5, mm = r & 31;
            sm[OV_AT + hh*128 + mm*4 + ni] =
                g_attn[(size_t)hh*N2 + (size_t)(n0+ni)*NRES + m0 + mm];
        }
        for (int i = tid; i < 1536; i += 480) {
            const int mm = i / 48, q = i - mm*48;
            cpa16(sm + OV_V + mm*192 + q*4, g_proj + (size_t)(m0+mm)*PROJW + 384 + q*4);
        }
        for (int i = tid; i < 2304; i += 480)
            cpa16(sm + OV_VG + i*4, g_vg + m0*288 + i*4);
        CP_COMMIT(); CP_WAIT0();
        __syncthreads();

        if (tid < 192) {
            const int hh = tid >> 4, c = tid & 15;
            const float* vs = sm + OV_V + hh*16 + c;
            const float4* at4 = (const float4*)(sm + OV_AT + hh*128);
#pragma unroll
            for (int mm = 0; mm < 32; mm++) {
                const float4 w = at4[mm];
                const float vv = vs[mm*192];
                acc0 = fmaf(w.x, vv, acc0);
                acc1 = fmaf(w.y, vv, acc1);
                acc2 = fmaf(w.z, vv, acc2);
                acc3 = fmaf(w.w, vv, acc3);
            }
        } else {
            const int idx = tid - 192, hh = idx / 24, u = idx - hh*24;
            const float* vs = sm + OV_VG + hh*24 + u;
            const float4* at4 = (const float4*)(sm + OV_AT + hh*128);
#pragma unroll
            for (int mm = 0; mm < 32; mm++) {
                const float4 w = at4[mm];
                const float vv = vs[mm*288];
                acc0 = fmaf(w.x, vv, acc0);
                acc1 = fmaf(w.y, vv, acc1);
                acc2 = fmaf(w.z, vv, acc2);
                acc3 = fmaf(w.w, vv, acc3);
            }
        }
    }
    __syncthreads();
    if (tid < 192) {
        const int hh = tid >> 4, c = tid & 15;
        g_feats[(size_t)(n0+0)*OUTD + hh*HF + c] = acc0;
        g_feats[(size_t)(n0+1)*OUTD + hh*HF + c] = acc1;
        g_feats[(size_t)(n0+2)*OUTD + hh*HF + c] = acc2;
        g_feats[(size_t)(n0+3)*OUTD + hh*HF + c] = acc3;
    } else {
        const int idx = tid - 192;
        sm[OV_PG + 0*288 + idx] = acc0;
        sm[OV_PG + 1*288 + idx] = acc1;
        sm[OV_PG + 2*288 + idx] = acc2;
        sm[OV_PG + 3*288 + idx] = acc3;
    }
    __syncthreads();
    if (tid < 384) {
        const int ni = tid / 96, r = tid - ni*96;
        const int hh = r / 8, p = r - hh*8;
        const int n = n0 + ni;
        float R[9];
#pragma unroll
        for (int i = 0; i < 9; i++) R[i] = rot[n*9 + i];
        const float gx = sm[OV_PG + ni*288 + hh*24 + p*3 + 0] - trans[n*3 + 0];
        const float gy = sm[OV_PG + ni*288 + hh*24 + p*3 + 1] - trans[n*3 + 1];
        const float gz = sm[OV_PG + ni*288 + hh*24 + p*3 + 2] - trans[n*3 + 2];
        const float lx = fmaf(R[0],gx, fmaf(R[3],gy, R[6]*gz));
        const float ly = fmaf(R[1],gx, fmaf(R[4],gy, R[7]*gz));
        const float lz = fmaf(R[2],gx, fmaf(R[5],gy, R[8]*gz));
        float* f = g_feats + (size_t)n*OUTD + hh*HF;
        f[16 + p*3 + 0] = lx; f[16 + p*3 + 1] = ly; f[16 + p*3 + 2] = lz;
        f[40 + p] = __fsqrt_rn(fmaf(lx,lx, fmaf(ly,ly, lz*lz)));
    }
}

// ---------------- final GEMM (split-K) ----------------
__global__ void k_sgemm(const float* __restrict__ A, const float* __restrict__ B,
                        float* __restrict__ C, int Nc, int K, int kLen)
{
    __shared__ alignas(16) float As[16][64];
    __shared__ alignas(16) float Bs[16][64];
    const int tid = threadIdx.x;
    const int tx = tid & 15, ty = tid >> 4;
    const int bm = blockIdx.y * 64, bn = blockIdx.x * 64;
    const int k0base = blockIdx.z * kLen;
    C += (size_t)blockIdx.z * (size_t)(gridDim.y * 64) * Nc;

    const int am  = tid >> 2, akq = tid & 3;
    const int bkk = tid >> 4, bn4 = tid & 15;

    float acc[4][4];
#pragma unroll
    for (int i = 0; i < 4; i++)
#pragma unroll
        for (int j = 0; j < 4; j++) acc[i][j] = 0.f;

    for (int kt = 0; kt < kLen; kt += 16) {
        const int k0 = k0base + kt;
        float4 av = *(const float4*)(A + (size_t)(bm + am) * K + k0 + akq * 4);
        As[akq*4+0][am] = av.x; As[akq*4+1][am] = av.y;
        As[akq*4+2][am] = av.z; As[akq*4+3][am] = av.w;
        float4 bv = make_float4(0.f,0.f,0.f,0.f);
        const int col = bn + bn4 * 4;
        if (col < Nc) bv = *(const float4*)(B + (size_t)(k0 + bkk) * Nc + col);
        *(float4*)&Bs[bkk][bn4*4] = bv;
        __syncthreads();
#pragma unroll
        for (int kk = 0; kk < 16; kk++) {
            float4 a = *(const float4*)&As[kk][ty*4];
            float4 b = *(const float4*)&Bs[kk][tx*4];
            acc[0][0]=fmaf(a.x,b.x,acc[0][0]); acc[0][1]=fmaf(a.x,b.y,acc[0][1]);
            acc[0][2]=fmaf(a.x,b.z,acc[0][2]); acc[0][3]=fmaf(a.x,b.w,acc[0][3]);
            acc[1][0]=fmaf(a.y,b.x,acc[1][0]); acc[1][1]=fmaf(a.y,b.y,acc[1][1]);
            acc[1][2]=fmaf(a.y,b.z,acc[1][2]); acc[1][3]=fmaf(a.y,b.w,acc[1][3]);
            acc[2][0]=fmaf(a.z,b.x,acc[2][0]); acc[2][1]=fmaf(a.z,b.y,acc[2][1]);
            acc[2][2]=fmaf(a.z,b.z,acc[2][2]); acc[2][3]=fmaf(a.z,b.w,acc[2][3]);
            acc[3][0]=fmaf(a.w,b.x,acc[3][0]); acc[3][1]=fmaf(a.w,b.y,acc[3][1]);
            acc[3][2]=fmaf(a.w,b.z,acc[3][2]); acc[3][3]=fmaf(a.w,b.w,acc[3][3]);
        }
        __syncthreads();
    }
#pragma unroll
    for (int i = 0; i < 4; i++) {
        const int row = bm + ty * 4 + i;
#pragma unroll
        for (int j = 0; j < 4; j++) {
            const int col = bn + tx * 4 + j;
            if (col < Nc) C[(size_t)row * Nc + col] = acc[i][j];
        }
    }
}

// ---------------- split-K reduce + bias ----------------
__global__ void k_reduce(const float* __restrict__ bout, float* __restrict__ out)
{
    const int i = blockIdx.x * 256 + threadIdx.x;
    const int NE = NRES * CS;
    const float v = g_part[i] + g_part[NE + i] + g_part[2*NE + i] + g_part[3*NE + i];
    out[i] = v + bout[i % CS];
}

// ---------------- launch ----------------
static float* symaddr(const void* sym) {
    void* p = nullptr;
    cudaGetSymbolAddress(&p, sym);
    return (float*)p;
}

extern "C" void kernel_launch(void* const* d_in, const int* in_sizes, int n_in,
                              void* d_out, int out_size) {
    const float* s     = (const float*)d_in[0];
    const float* z     = (const float*)d_in[1];
    const float* trans = (const float*)d_in[2];
    const float* rot   = (const float*)d_in[3];
    const float* Wq    = (const float*)d_in[4];
    const float* bq    = (const float*)d_in[5];
    const float* Wk    = (const float*)d_in[6];
    const float* bk    = (const float*)d_in[7];
    const float* Wv    = (const float*)d_in[8];
    const float* bv    = (const float*)d_in[9];
    const float* Wqp   = (const float*)d_in[10];
    const float* bqp   = (const float*)d_in[11];
    const float* Wkp   = (const float*)d_in[12];
    const float* bkp   = (const float*)d_in[13];
    const float* Wvp   = (const float*)d_in[14];
    const float* bvp   = (const float*)d_in[15];
    const float* Wb    = (const float*)d_in[16];
    const float* bb    = (const float*)d_in[17];
    const float* emb   = (const float*)d_in[18];
    const float* sl    = (const float*)d_in[19];
    const float* hw    = (const float*)d_in[20];
    const float* Wout  = (const float*)d_in[21];
    const float* bout  = (const float*)d_in[22];
    float* out = (float*)d_out;

    float* pf = symaddr(g_feats);
    float* pp = symaddr(g_part);

    // one-time host resources (streams/events only; no device memory)
    static cudaStream_t s2 = nullptr;
    static cudaEvent_t evFork = nullptr, evZ = nullptr, evS = nullptr, evP = nullptr;
    if (!s2) {
        cudaStreamCreateWithFlags(&s2, cudaStreamNonBlocking);
        cudaEventCreateWithFlags(&evFork, cudaEventDisableTiming);
        cudaEventCreateWithFlags(&evZ,    cudaEventDisableTiming);
        cudaEventCreateWithFlags(&evS,    cudaEventDisableTiming);
        cudaEventCreateWithFlags(&evP,    cudaEventDisableTiming);
        cudaFuncSetAttribute(k_pairbias, cudaFuncAttributeMaxDynamicSharedMemorySize, PB_END * (int)sizeof(float));
        cudaFuncSetAttribute(k_pairfeat, cudaFuncAttributeMaxDynamicSharedMemorySize, PF_END * (int)sizeof(float));
        cudaFuncSetAttribute(k_outv,     cudaFuncAttributeMaxDynamicSharedMemorySize, OV_END * (int)sizeof(float));
    }

    // fork: z-path (pairbias) on s2 concurrent with s-path (proj->prep) on default
    cudaEventRecord(evFork, 0);
    cudaStreamWaitEvent(s2, evFork, 0);
    k_pairbias<<<NRES, 256, PB_END * sizeof(float), s2>>>(z, trans, Wb, bb, emb, sl);
    cudaEventRecord(evZ, s2);

    k_proj<<<dim3(18,8,1), 256>>>(s, Wq,bq, Wk,bk, Wv,bv, Wqp,bqp, Wkp,bkp, Wvp,bvp);
    k_prep<<<NRES, 192>>>(rot, trans, hw);

    // join: geo RMWs attn (needs pairbias) and reads prep outputs
    cudaStreamWaitEvent(0, evZ, 0);
    k_geo<<<dim3(8,8,12), 256>>>();
    k_softmax<<<NRES, 384>>>();
    cudaEventRecord(evS, 0);

    // fork: pairfeat (z-stream) on s2 concurrent with outv (V-stream) on default
    cudaStreamWaitEvent(s2, evS, 0);
    k_pairfeat<<<NRES, 384, PF_END * sizeof(float), s2>>>(z);
    cudaEventRecord(evP, s2);

    k_outv<<<128, 480, OV_END * sizeof(float)>>>(rot, trans);

    // join before final GEMM (needs complete g_feats)
    cudaStreamWaitEvent(0, evP, 0);
    k_sgemm<<<dim3(6,8,4), 256>>>(pf, Wout, pp, CS, OUTD, OUTD/4);
    k_reduce<<<(NRES*CS)/256, 256>>>(bout, out);
}

// round 13
// speedup vs baseline: 3.0185x; 1.0879x over previous
#include <cuda_runtime.h>
#include <math.h>

#define NRES 512
#define CS   384
#define CZ   128
#define NH   12
#define OUTD 2112
#define HF   176
#define PROJW 1152   // 192 q | 192 k | 192 v | 144 qp | 144 kp | 288 vp
#define N2   (NRES*NRES)

// ---------------- scratch ----------------
__device__ alignas(16) float g_proj[NRES*PROJW];
__device__ alignas(16) float g_vg[NRES*288];
__device__ alignas(16) float g_gA[336*NRES];
__device__ alignas(16) float g_gB[336*NRES];
__device__ alignas(16) float g_gC[NH*NRES];
__device__ alignas(16) float g_attn[(size_t)NH*NRES*NRES];   // [h][n][m]
__device__ alignas(16) float g_feats[(size_t)NRES*OUTD];
__device__ alignas(16) float g_part[(size_t)8*NRES*CS];

// ---------------- cp.async helpers ----------------
__device__ __forceinline__ void cpa16(void* dst_smem, const void* src_gmem) {
    unsigned int d = (unsigned int)__cvta_generic_to_shared(dst_smem);
    asm volatile("cp.async.ca.shared.global [%0], [%1], 16;\n" :: "r"(d), "l"(src_gmem));
}
#define CP_COMMIT() asm volatile("cp.async.commit_group;\n" ::: "memory")
#define CP_WAIT0()  asm volatile("cp.async.wait_group 0;\n" ::: "memory")
#define CP_WAIT1()  asm volatile("cp.async.wait_group 1;\n" ::: "memory")

// ---------------- fused projection GEMM ----------------
__global__ void k_proj(const float* __restrict__ s,
    const float* __restrict__ Wq,  const float* __restrict__ bq,
    const float* __restrict__ Wk,  const float* __restrict__ bk,
    const float* __restrict__ Wv,  const float* __restrict__ bvs,
    const float* __restrict__ Wqp, const float* __restrict__ bqp,
    const float* __restrict__ Wkp, const float* __restrict__ bkp,
    const float* __restrict__ Wvp, const float* __restrict__ bvp)
{
    __shared__ alignas(16) float As[16][64];
    __shared__ alignas(16) float Bs[16][64];
    const int tid = threadIdx.x;
    const int tx = tid & 15, ty = tid >> 4;
    const int bm = blockIdx.y * 64, bn = blockIdx.x * 64;
    const int am  = tid >> 2, akq = tid & 3;
    const int bkk = tid >> 4, bn4 = tid & 15;

    const int gc = bn + bn4 * 4;
    const float* Bp; int bst;
    if (gc < 576)      { const int sg = gc / 192;
                         const float* Ws = (sg == 0) ? Wq : (sg == 1) ? Wk : Wv;
                         Bp = Ws + (gc - sg * 192); bst = 192; }
    else if (gc < 864) { const int sg = (gc - 576) / 144;
                         Bp = ((sg == 0) ? Wqp : Wkp) + (gc - 576 - sg * 144); bst = 144; }
    else               { Bp = Wvp + (gc - 864); bst = 288; }

    float acc[4][4];
#pragma unroll
    for (int i = 0; i < 4; i++)
#pragma unroll
        for (int j = 0; j < 4; j++) acc[i][j] = 0.f;

    for (int k0 = 0; k0 < CS; k0 += 16) {
        float4 av = *(const float4*)(s + (size_t)(bm + am) * CS + k0 + akq * 4);
        As[akq*4+0][am] = av.x; As[akq*4+1][am] = av.y;
        As[akq*4+2][am] = av.z; As[akq*4+3][am] = av.w;
        float4 wv4 = *(const float4*)(Bp + (size_t)(k0 + bkk) * bst);
        *(float4*)&Bs[bkk][bn4*4] = wv4;
        __syncthreads();
#pragma unroll
        for (int kk = 0; kk < 16; kk++) {
            float4 a = *(const float4*)&As[kk][ty*4];
            float4 b = *(const float4*)&Bs[kk][tx*4];
            acc[0][0]=fmaf(a.x,b.x,acc[0][0]); acc[0][1]=fmaf(a.x,b.y,acc[0][1]);
            acc[0][2]=fmaf(a.x,b.z,acc[0][2]); acc[0][3]=fmaf(a.x,b.w,acc[0][3]);
            acc[1][0]=fmaf(a.y,b.x,acc[1][0]); acc[1][1]=fmaf(a.y,b.y,acc[1][1]);
            acc[1][2]=fmaf(a.y,b.z,acc[1][2]); acc[1][3]=fmaf(a.y,b.w,acc[1][3]);
            acc[2][0]=fmaf(a.z,b.x,acc[2][0]); acc[2][1]=fmaf(a.z,b.y,acc[2][1]);
            acc[2][2]=fmaf(a.z,b.z,acc[2][2]); acc[2][3]=fmaf(a.z,b.w,acc[2][3]);
            acc[3][0]=fmaf(a.w,b.x,acc[3][0]); acc[3][1]=fmaf(a.w,b.y,acc[3][1]);
            acc[3][2]=fmaf(a.w,b.z,acc[3][2]); acc[3][3]=fmaf(a.w,b.w,acc[3][3]);
        }
        __syncthreads();
    }
    const int gc0 = bn + tx * 4;
    const float* bptr;
    if (gc0 < 576)      { const int sg = gc0 / 192;
                          bptr = ((sg == 0) ? bq : (sg == 1) ? bk : bvs) + (gc0 - sg * 192); }
    else if (gc0 < 864) { const int sg = (gc0 - 576) / 144;
                          bptr = ((sg == 0) ? bqp : bkp) + (gc0 - 576 - sg * 144); }
    else                { bptr = bvp + (gc0 - 864); }
#pragma unroll
    for (int i = 0; i < 4; i++) {
        const int row = bm + ty * 4 + i;
#pragma unroll
        for (int j = 0; j < 4; j++)
            g_proj[(size_t)row * PROJW + gc0 + j] = acc[i][j] + bptr[j];
    }
}

// ---------------- prep: frames + GEMM operands A/B/C ----------------
__global__ void k_prep(const float* __restrict__ rot, const float* __restrict__ trans,
                       const float* __restrict__ hw)
{
    const int n = blockIdx.x;
    __shared__ float R[9], T[3];
    __shared__ float kgs[144];
    if (threadIdx.x < 9) R[threadIdx.x] = rot[n*9 + threadIdx.x];
    if (threadIdx.x < 3) T[threadIdx.x] = trans[n*3 + threadIdx.x];
    __syncthreads();
    const int t = threadIdx.x;  // 0..191
    const float* row = g_proj + (size_t)n * PROJW;
    if (t < 48) {
        const float* src = row + 576 + t*3;
        const float p0 = src[0], p1 = src[1], p2 = src[2];
        const float gx = fmaf(R[0],p0, fmaf(R[1],p1, fmaf(R[2],p2, T[0])));
        const float gy = fmaf(R[3],p0, fmaf(R[4],p1, fmaf(R[5],p2, T[1])));
        const float gz = fmaf(R[6],p0, fmaf(R[7],p1, fmaf(R[8],p2, T[2])));
        const int h = t >> 2, p = t & 3;
        const float w = hw[h];
        g_gA[(h*28+16+p*3+0)*NRES + n] = w*gx;
        g_gA[(h*28+16+p*3+1)*NRES + n] = w*gy;
        g_gA[(h*28+16+p*3+2)*NRES + n] = w*gz;
    } else if (t < 96) {
        const int u = t - 48;
        const float* src = row + 720 + u*3;
        const float p0 = src[0], p1 = src[1], p2 = src[2];
        const float gx = fmaf(R[0],p0, fmaf(R[1],p1, fmaf(R[2],p2, T[0])));
        const float gy = fmaf(R[3],p0, fmaf(R[4],p1, fmaf(R[5],p2, T[1])));
        const float gz = fmaf(R[6],p0, fmaf(R[7],p1, fmaf(R[8],p2, T[2])));
        const int h = u >> 2, p = u & 3;
        g_gB[(h*28+16+p*3+0)*NRES + n] = gx;
        g_gB[(h*28+16+p*3+1)*NRES + n] = gy;
        g_gB[(h*28+16+p*3+2)*NRES + n] = gz;
        kgs[u*3+0] = gx; kgs[u*3+1] = gy; kgs[u*3+2] = gz;
    } else {
        const int u = t - 96;
        const float* src = row + 864 + u*3;
        float* dst = g_vg + n*288 + u*3;
        const float p0 = src[0], p1 = src[1], p2 = src[2];
        dst[0] = fmaf(R[0],p0, fmaf(R[1],p1, fmaf(R[2],p2, T[0])));
        dst[1] = fmaf(R[3],p0, fmaf(R[4],p1, fmaf(R[5],p2, T[1])));
        dst[2] = fmaf(R[6],p0, fmaf(R[7],p1, fmaf(R[8],p2, T[2])));
    }
    {
        const int h = t >> 4, c = t & 15;
        g_gA[(h*28+c)*NRES + n] = 0.25f * row[h*16 + c];
        g_gB[(h*28+c)*NRES + n] = row[192 + h*16 + c];
    }
    __syncthreads();
    if (t < 12) {
        float s2 = 0.f;
#pragma unroll
        for (int j = 0; j < 12; j++) s2 = fmaf(kgs[t*12+j], kgs[t*12+j], s2);
        g_gC[t*NRES + n] = -0.5f * hw[t] * s2;
    }
}

// ---------------- pair bias stream (64-m chunks, true double buffer) ----------------
#define PB_WBT 0        // 1536
#define PB_EMB 1536     // 768
#define PB_PH  2304     // 36
#define PB_BB  2340     // 12
#define PB_TN  2352     // 4
#define PB_TM0 2356     // 192
#define PB_TM1 2548     // 192
#define PB_Z0  2740     // 64*132 = 8448
#define PB_Z1  11188    // 8448
#define PB_END 19636    // 78544 B
__global__ void k_pairbias(const float* __restrict__ z, const float* __restrict__ trans,
                           const float* __restrict__ Wb, const float* __restrict__ bb,
                           const float* __restrict__ emb, const float* __restrict__ sl)
{
    extern __shared__ float sm[];
    const int n = blockIdx.x, tid = threadIdx.x;  // 256 thr

    auto pf = [&](int buf, int mc) {
        const float4* zsrc = (const float4*)(z + ((size_t)n * NRES + mc*64) * CZ);
        float* zb = sm + (buf ? PB_Z1 : PB_Z0);
        for (int i = tid; i < 2048; i += 256)
            cpa16(zb + (i >> 5)*132 + (i & 31)*4, zsrc + i);
        if (tid < 48)
            cpa16(sm + (buf ? PB_TM1 : PB_TM0) + tid*4, trans + mc*192 + tid*4);
    };
    pf(0, 0); CP_COMMIT();
    pf(1, 1); CP_COMMIT();

    for (int i = tid; i < 1536; i += 256) {
        const int h = i >> 7, c = i & 127;
        sm[PB_WBT + i] = Wb[c*NH + h];
    }
    for (int i = tid; i < 768; i += 256) sm[PB_EMB + i] = emb[i];
    if (tid < 12) {
        sm[PB_BB + tid] = bb[tid];
        const float e0 = expf(sl[tid]), e1 = expf(sl[12+tid]), e2 = expf(sl[24+tid]);
        const float inv = 1.0f / (e0 + e1 + e2);
        sm[PB_PH + tid] = e0*inv; sm[PB_PH + 12 + tid] = e1*inv; sm[PB_PH + 24 + tid] = e2*inv;
    }
    if (tid < 3) sm[PB_TN + tid] = trans[n*3 + tid];

    const int ml = tid & 63;
    const int hb = (tid >> 6) * 3;      // 4 head-groups of 3

    for (int mc = 0; mc < 8; mc++) {
        if (mc < 7) CP_WAIT1(); else CP_WAIT0();
        __syncthreads();
        const int buf = mc & 1;
        const float4* zr = (const float4*)(sm + (buf ? PB_Z1 : PB_Z0) + ml*132);
        const float* tm = sm + (buf ? PB_TM1 : PB_TM0);

        float a[3][4];
#pragma unroll
        for (int j = 0; j < 3; j++) { a[j][0]=0.f; a[j][1]=0.f; a[j][2]=0.f; a[j][3]=0.f; }
#pragma unroll 8
        for (int c4 = 0; c4 < 32; c4++) {
            const float4 zv = zr[c4];
#pragma unroll
            for (int j = 0; j < 3; j++) {
                const float4 w = ((const float4*)(sm + PB_WBT + (hb+j)*128))[c4];
                a[j][0] = fmaf(zv.x, w.x, a[j][0]);
                a[j][1] = fmaf(zv.y, w.y, a[j][1]);
                a[j][2] = fmaf(zv.z, w.z, a[j][2]);
                a[j][3] = fmaf(zv.w, w.w, a[j][3]);
            }
        }
        const float dx = sm[PB_TN+0] - tm[ml*3+0];
        const float dy = sm[PB_TN+1] - tm[ml*3+1];
        const float dz = sm[PB_TN+2] - tm[ml*3+2];
        const float dist = __fsqrt_rn(fmaf(dx,dx, fmaf(dy,dy, dz*dz)));
        int bin = (int)ceilf(dist * 2.0f) - 1;
        bin = max(0, min(63, bin));
        const int msrow = (dist <= 5.0f) ? 0 : (dist <= 15.0f) ? 12 : -1;
        const int m = mc*64 + ml;
#pragma unroll
        for (int j = 0; j < 3; j++) {
            const int h = hb + j;
            float v = sm[PB_BB + h] + ((a[j][0]+a[j][1]) + (a[j][2]+a[j][3]));
            v += sm[PB_EMB + bin*12 + h] + sm[PB_PH + 24 + h];
            if (msrow >= 0) v += sm[PB_PH + msrow + h];
            g_attn[(size_t)h*N2 + (size_t)n*NRES + m] = v;
        }
        __syncthreads();
        if (mc + 2 < 8) { pf(buf, mc + 2); CP_COMMIT(); }
    }
}

// ---------------- geometry logits as batched GEMM K=28 ----------------
__global__ void k_geo()
{
    __shared__ alignas(16) float As[28][64];
    __shared__ alignas(16) float Bs[28][64];
    __shared__ alignas(16) float Cs[64];
    const int h = blockIdx.z;
    const int n0 = blockIdx.y * 64, m0 = blockIdx.x * 64;
    const int tid = threadIdx.x;
    const int tx = tid & 15, ty = tid >> 4;

    for (int i = tid; i < 1792; i += 256) {
        const int c = i >> 6, r = i & 63;
        As[c][r] = g_gA[(size_t)(h*28+c)*NRES + n0 + r];
        Bs[c][r] = g_gB[(size_t)(h*28+c)*NRES + m0 + r];
    }
    if (tid < 64) Cs[tid] = g_gC[h*NRES + m0 + tid];
    __syncthreads();

    float acc[4][4];
#pragma unroll
    for (int i = 0; i < 4; i++)
#pragma unroll
        for (int j = 0; j < 4; j++) acc[i][j] = 0.f;

#pragma unroll
    for (int c = 0; c < 28; c++) {
        const float4 a = *(const float4*)&As[c][ty*4];
        const float4 b = *(const float4*)&Bs[c][tx*4];
        acc[0][0]=fmaf(a.x,b.x,acc[0][0]); acc[0][1]=fmaf(a.x,b.y,acc[0][1]);
        acc[0][2]=fmaf(a.x,b.z,acc[0][2]); acc[0][3]=fmaf(a.x,b.w,acc[0][3]);
        acc[1][0]=fmaf(a.y,b.x,acc[1][0]); acc[1][1]=fmaf(a.y,b.y,acc[1][1]);
        acc[1][2]=fmaf(a.y,b.z,acc[1][2]); acc[1][3]=fmaf(a.y,b.w,acc[1][3]);
        acc[2][0]=fmaf(a.z,b.x,acc[2][0]); acc[2][1]=fmaf(a.z,b.y,acc[2][1]);
        acc[2][2]=fmaf(a.z,b.z,acc[2][2]); acc[2][3]=fmaf(a.z,b.w,acc[2][3]);
        acc[3][0]=fmaf(a.w,b.x,acc[3][0]); acc[3][1]=fmaf(a.w,b.y,acc[3][1]);
        acc[3][2]=fmaf(a.w,b.z,acc[3][2]); acc[3][3]=fmaf(a.w,b.w,acc[3][3]);
    }
    const float4 cv = *(const float4*)&Cs[tx*4];
#pragma unroll
    for (int i = 0; i < 4; i++) {
        float4* gp = (float4*)(g_attn + (size_t)h*N2 + (size_t)(n0 + ty*4 + i)*NRES + m0 + tx*4);
        float4 o = *gp;
        o.x += acc[i][0] + cv.x;
        o.y += acc[i][1] + cv.y;
        o.z += acc[i][2] + cv.z;
        o.w += acc[i][3] + cv.w;
        *gp = o;
    }
}

// ---------------- softmax over m ----------------
__global__ void k_softmax()
{
    const int n = blockIdx.x;
    const int h = threadIdx.x >> 5, lane = threadIdx.x & 31;   // 384 thr
    float* p = g_attn + (size_t)h*N2 + (size_t)n*NRES;
    float v[16];
    float mx = -1e30f;
#pragma unroll
    for (int i = 0; i < 16; i++) { v[i] = p[lane + 32*i]; mx = fmaxf(mx, v[i]); }
#pragma unroll
    for (int o = 16; o; o >>= 1) mx = fmaxf(mx, __shfl_xor_sync(0xffffffffu, mx, o));
    float sum = 0.f;
#pragma unroll
    for (int i = 0; i < 16; i++) { v[i] = __expf(v[i] - mx); sum += v[i]; }
#pragma unroll
    for (int o = 16; o; o >>= 1) sum += __shfl_xor_sync(0xffffffffu, sum, o);
    const float inv = 1.0f / sum;
#pragma unroll
    for (int i = 0; i < 16; i++) p[lane + 32*i] = v[i] * inv;
}

// ---------------- pair_feat (cp.async double-buffered z) ----------------
#define PF_END 17920
__global__ void k_pairfeat(const float* __restrict__ z)
{
    extern __shared__ float sm[];
    const int n = blockIdx.x, tid = threadIdx.x;  // 384 thr
    float* zb[2]  = { sm, sm + 8192 };
    float* atb[2] = { sm + 16384, sm + 17152 };

    const float4* zsrc = (const float4*)(z + (size_t)n * NRES * CZ);

    {
        for (int i = tid; i < 2048; i += 384) cpa16(zb[0] + i*4, zsrc + i);
        if (tid < 192) {
            const int h = tid / 16, q = tid % 16;
            cpa16(atb[0] + h*64 + q*4,
                  g_attn + (size_t)h*N2 + (size_t)n*NRES + q*4);
        }
        CP_COMMIT();
    }

    const int h = tid >> 5;
    const int cq = tid & 31;
    float a0=0.f, a1=0.f, a2=0.f, a3=0.f;

    for (int mc = 0; mc < 8; mc++) {
        if (mc + 1 < 8) {
            const int buf = (mc + 1) & 1;
            const int m0 = (mc + 1) * 64;
            for (int i = tid; i < 2048; i += 384) cpa16(zb[buf] + i*4, zsrc + 2048*(mc+1) + i);
            if (tid < 192) {
                const int hh = tid / 16, q = tid % 16;
                cpa16(atb[buf] + hh*64 + q*4,
                      g_attn + (size_t)hh*N2 + (size_t)n*NRES + m0 + q*4);
            }
            CP_COMMIT();
            CP_WAIT1();
        } else {
            CP_WAIT0();
        }
        __syncthreads();
        const float* zc = zb[mc & 1];
        const float* ac = atb[mc & 1] + h*64;
#pragma unroll 2
        for (int mm4 = 0; mm4 < 16; mm4++) {
            const float4 w = *(const float4*)(ac + mm4*4);
            const float4 z0 = *(const float4*)(zc + (mm4*4+0)*128 + cq*4);
            const float4 z1 = *(const float4*)(zc + (mm4*4+1)*128 + cq*4);
            const float4 z2 = *(const float4*)(zc + (mm4*4+2)*128 + cq*4);
            const float4 z3 = *(const float4*)(zc + (mm4*4+3)*128 + cq*4);
            a0 = fmaf(w.x, z0.x, a0); a1 = fmaf(w.x, z0.y, a1);
            a2 = fmaf(w.x, z0.z, a2); a3 = fmaf(w.x, z0.w, a3);
            a0 = fmaf(w.y, z1.x, a0); a1 = fmaf(w.y, z1.y, a1);
            a2 = fmaf(w.y, z1.z, a2); a3 = fmaf(w.y, z1.w, a3);
            a0 = fmaf(w.z, z2.x, a0); a1 = fmaf(w.z, z2.y, a1);
            a2 = fmaf(w.z, z2.z, a2); a3 = fmaf(w.z, z2.w, a3);
            a0 = fmaf(w.w, z3.x, a0); a1 = fmaf(w.w, z3.y, a1);
            a2 = fmaf(w.w, z3.z, a2); a3 = fmaf(w.w, z3.w, a3);
        }
        __syncthreads();
    }
    float* dst = g_feats + (size_t)n * OUTD + h * HF + 48 + cq * 4;
    dst[0]=a0; dst[1]=a1; dst[2]=a2; dst[3]=a3;
}

// ---------------- out_scalar + out_pts(local) + norms; 4 n per block ----------------
#define OV_AT 0        // 12*128 [h][m][ni]
#define OV_V  1536     // 6144
#define OV_VG 7680     // 9216
#define OV_PG 16896    // 4*288
#define OV_END 18048
__global__ void k_outv(const float* __restrict__ rot, const float* __restrict__ trans)
{
    extern __shared__ float sm[];
    const int n0 = blockIdx.x * 4, tid = threadIdx.x;  // 480 thr, grid 128
    float acc0=0.f, acc1=0.f, acc2=0.f, acc3=0.f;

    for (int mc = 0; mc < 16; mc++) {
        const int m0 = mc * 32;
        __syncthreads();
        for (int i = tid; i < 1536; i += 480) {
            const int hh = i >> 7, r = i & 127;
            const int ni = r >> 5, mm = r & 31;
            sm[OV_AT + hh*128 + mm*4 + ni] =
                g_attn[(size_t)hh*N2 + (size_t)(n0+ni)*NRES + m0 + mm];
        }
        for (int i = tid; i < 1536; i += 480) {
            const int mm = i / 48, q = i - mm*48;
            cpa16(sm + OV_V + mm*192 + q*4, g_proj + (size_t)(m0+mm)*PROJW + 384 + q*4);
        }
        for (int i = tid; i < 2304; i += 480)
            cpa16(sm + OV_VG + i*4, g_vg + m0*288 + i*4);
        CP_COMMIT(); CP_WAIT0();
        __syncthreads();

        if (tid < 192) {
            const int hh = tid >> 4, c = tid & 15;
            const float* vs = sm + OV_V + hh*16 + c;
            const float4* at4 = (const float4*)(sm + OV_AT + hh*128);
#pragma unroll
            for (int mm = 0; mm < 32; mm++) {
                const float4 w = at4[mm];
                const float vv = vs[mm*192];
                acc0 = fmaf(w.x, vv, acc0);
                acc1 = fmaf(w.y, vv, acc1);
                acc2 = fmaf(w.z, vv, acc2);
                acc3 = fmaf(w.w, vv, acc3);
            }
        } else {
            const int idx = tid - 192, hh = idx / 24, u = idx - hh*24;
            const float* vs = sm + OV_VG + hh*24 + u;
            const float4* at4 = (const float4*)(sm + OV_AT + hh*128);
#pragma unroll
            for (int mm = 0; mm < 32; mm++) {
                const float4 w = at4[mm];
                const float vv = vs[mm*288];
                acc0 = fmaf(w.x, vv, acc0);
                acc1 = fmaf(w.y, vv, acc1);
                acc2 = fmaf(w.z, vv, acc2);
                acc3 = fmaf(w.w, vv, acc3);
            }
        }
    }
    __syncthreads();
    if (tid < 192) {
        const int hh = tid >> 4, c = tid & 15;
        g_feats[(size_t)(n0+0)*OUTD + hh*HF + c] = acc0;
        g_feats[(size_t)(n0+1)*OUTD + hh*HF + c] = acc1;
        g_feats[(size_t)(n0+2)*OUTD + hh*HF + c] = acc2;
        g_feats[(size_t)(n0+3)*OUTD + hh*HF + c] = acc3;
    } else {
        const int idx = tid - 192;
        sm[OV_PG + 0*288 + idx] = acc0;
        sm[OV_PG + 1*288 + idx] = acc1;
        sm[OV_PG + 2*288 + idx] = acc2;
        sm[OV_PG + 3*288 + idx] = acc3;
    }
    __syncthreads();
    if (tid < 384) {
        const int ni = tid / 96, r = tid - ni*96;
        const int hh = r / 8, p = r - hh*8;
        const int n = n0 + ni;
        float R[9];
#pragma unroll
        for (int i = 0; i < 9; i++) R[i] = rot[n*9 + i];
        const float gx = sm[OV_PG + ni*288 + hh*24 + p*3 + 0] - trans[n*3 + 0];
        const float gy = sm[OV_PG + ni*288 + hh*24 + p*3 + 1] - trans[n*3 + 1];
        const float gz = sm[OV_PG + ni*288 + hh*24 + p*3 + 2] - trans[n*3 + 2];
        const float lx = fmaf(R[0],gx, fmaf(R[3],gy, R[6]*gz));
        const float ly = fmaf(R[1],gx, fmaf(R[4],gy, R[7]*gz));
        const float lz = fmaf(R[2],gx, fmaf(R[5],gy, R[8]*gz));
        float* f = g_feats + (size_t)n*OUTD + hh*HF;
        f[16 + p*3 + 0] = lx; f[16 + p*3 + 1] = ly; f[16 + p*3 + 2] = lz;
        f[40 + p] = __fsqrt_rn(fmaf(lx,lx, fmaf(ly,ly, lz*lz)));
    }
}

// ---------------- selective-K GEMM over per-head column ranges ----------------
// K indices: for h in [3*bz, 3*bz+3): cols h*HF+kbase .. h*HF+kbase+klen
__global__ void k_sgemm_sel(const float* __restrict__ A, const float* __restrict__ B,
                            float* __restrict__ C, int pbase, int kbase, int klen)
{
    __shared__ alignas(16) float As[16][64];
    __shared__ alignas(16) float Bs[16][64];
    const int tid = threadIdx.x;
    const int tx = tid & 15, ty = tid >> 4;
    const int bm = blockIdx.y * 64, bn = blockIdx.x * 64;
    const int hb = blockIdx.z * 3;
    C += (size_t)(pbase + blockIdx.z) * NRES * CS;

    const int am  = tid >> 2, akq = tid & 3;
    const int bkk = tid >> 4, bn4 = tid & 15;

    float acc[4][4];
#pragma unroll
    for (int i = 0; i < 4; i++)
#pragma unroll
        for (int j = 0; j < 4; j++) acc[i][j] = 0.f;

    for (int hh = hb; hh < hb + 3; hh++) {
        const int kc0 = hh * HF + kbase;
        for (int kt = 0; kt < klen; kt += 16) {
            const int kc = kc0 + kt;
            float4 av = *(const float4*)(A + (size_t)(bm + am) * OUTD + kc + akq * 4);
            As[akq*4+0][am] = av.x; As[akq*4+1][am] = av.y;
            As[akq*4+2][am] = av.z; As[akq*4+3][am] = av.w;
            float4 bv = *(const float4*)(B + (size_t)(kc + bkk) * CS + bn + bn4 * 4);
            *(float4*)&Bs[bkk][bn4*4] = bv;
            __syncthreads();
#pragma unroll
            for (int kk = 0; kk < 16; kk++) {
                float4 a = *(const float4*)&As[kk][ty*4];
                float4 b = *(const float4*)&Bs[kk][tx*4];
                acc[0][0]=fmaf(a.x,b.x,acc[0][0]); acc[0][1]=fmaf(a.x,b.y,acc[0][1]);
                acc[0][2]=fmaf(a.x,b.z,acc[0][2]); acc[0][3]=fmaf(a.x,b.w,acc[0][3]);
                acc[1][0]=fmaf(a.y,b.x,acc[1][0]); acc[1][1]=fmaf(a.y,b.y,acc[1][1]);
                acc[1][2]=fmaf(a.y,b.z,acc[1][2]); acc[1][3]=fmaf(a.y,b.w,acc[1][3]);
                acc[2][0]=fmaf(a.z,b.x,acc[2][0]); acc[2][1]=fmaf(a.z,b.y,acc[2][1]);
                acc[2][2]=fmaf(a.z,b.z,acc[2][2]); acc[2][3]=fmaf(a.z,b.w,acc[2][3]);
                acc[3][0]=fmaf(a.w,b.x,acc[3][0]); acc[3][1]=fmaf(a.w,b.y,acc[3][1]);
                acc[3][2]=fmaf(a.w,b.z,acc[3][2]); acc[3][3]=fmaf(a.w,b.w,acc[3][3]);
            }
            __syncthreads();
        }
    }
#pragma unroll
    for (int i = 0; i < 4; i++) {
        const int row = bm + ty * 4 + i;
#pragma unroll
        for (int j = 0; j < 4; j++)
            C[(size_t)row * CS + bn + tx * 4 + j] = acc[i][j];
    }
}

// ---------------- reduce 8 partials + bias ----------------
__global__ void k_reduce(const float* __restrict__ bout, float* __restrict__ out)
{
    const int i = blockIdx.x * 256 + threadIdx.x;
    const int NE = NRES * CS;
    float v = 0.f;
#pragma unroll
    for (int p = 0; p < 8; p++) v += g_part[(size_t)p*NE + i];
    out[i] = v + bout[i % CS];
}

// ---------------- launch ----------------
static float* symaddr(const void* sym) {
    void* p = nullptr;
    cudaGetSymbolAddress(&p, sym);
    return (float*)p;
}

extern "C" void kernel_launch(void* const* d_in, const int* in_sizes, int n_in,
                              void* d_out, int out_size) {
    const float* s     = (const float*)d_in[0];
    const float* z     = (const float*)d_in[1];
    const float* trans = (const float*)d_in[2];
    const float* rot   = (const float*)d_in[3];
    const float* Wq    = (const float*)d_in[4];
    const float* bq    = (const float*)d_in[5];
    const float* Wk    = (const float*)d_in[6];
    const float* bk    = (const float*)d_in[7];
    const float* Wv    = (const float*)d_in[8];
    const float* bv    = (const float*)d_in[9];
    const float* Wqp   = (const float*)d_in[10];
    const float* bqp   = (const float*)d_in[11];
    const float* Wkp   = (const float*)d_in[12];
    const float* bkp   = (const float*)d_in[13];
    const float* Wvp   = (const float*)d_in[14];
    const float* bvp   = (const float*)d_in[15];
    const float* Wb    = (const float*)d_in[16];
    const float* bb    = (const float*)d_in[17];
    const float* emb   = (const float*)d_in[18];
    const float* sl    = (const float*)d_in[19];
    const float* hw    = (const float*)d_in[20];
    const float* Wout  = (const float*)d_in[21];
    const float* bout  = (const float*)d_in[22];
    float* out = (float*)d_out;

    float* pf = symaddr(g_feats);
    float* pp = symaddr(g_part);

    static cudaStream_t s2 = nullptr;
    static cudaEvent_t evFork = nullptr, evZ = nullptr, evS = nullptr, evP = nullptr;
    if (!s2) {
        cudaStreamCreateWithFlags(&s2, cudaStreamNonBlocking);
        cudaEventCreateWithFlags(&evFork, cudaEventDisableTiming);
        cudaEventCreateWithFlags(&evZ,    cudaEventDisableTiming);
        cudaEventCreateWithFlags(&evS,    cudaEventDisableTiming);
        cudaEventCreateWithFlags(&evP,    cudaEventDisableTiming);
        cudaFuncSetAttribute(k_pairbias, cudaFuncAttributeMaxDynamicSharedMemorySize, PB_END * (int)sizeof(float));
        cudaFuncSetAttribute(k_pairfeat, cudaFuncAttributeMaxDynamicSharedMemorySize, PF_END * (int)sizeof(float));
        cudaFuncSetAttribute(k_outv,     cudaFuncAttributeMaxDynamicSharedMemorySize, OV_END * (int)sizeof(float));
    }

    // fork: z-path (pairbias) on s2 concurrent with s-path (proj->prep) on default
    cudaEventRecord(evFork, 0);
    cudaStreamWaitEvent(s2, evFork, 0);
    k_pairbias<<<NRES, 256, PB_END * sizeof(float), s2>>>(z, trans, Wb, bb, emb, sl);
    cudaEventRecord(evZ, s2);

    k_proj<<<dim3(18,8,1), 256>>>(s, Wq,bq, Wk,bk, Wv,bv, Wqp,bqp, Wkp,bkp, Wvp,bvp);
    k_prep<<<NRES, 192>>>(rot, trans, hw);

    // join: geo RMWs attn (needs pairbias) and reads prep outputs
    cudaStreamWaitEvent(0, evZ, 0);
    k_geo<<<dim3(8,8,12), 256>>>();
    k_softmax<<<NRES, 384>>>();
    cudaEventRecord(evS, 0);

    // fork: pairfeat (z-stream) + its GEMM on s2, concurrent with outv + its GEMM
    cudaStreamWaitEvent(s2, evS, 0);
    k_pairfeat<<<NRES, 384, PF_END * sizeof(float), s2>>>(z);
    k_sgemm_sel<<<dim3(6,8,4), 256, 0, s2>>>(pf, Wout, pp, 4, 48, 128);
    cudaEventRecord(evP, s2);

    k_outv<<<128, 480, OV_END * sizeof(float)>>>(rot, trans);
    k_sgemm_sel<<<dim3(6,8,4), 256>>>(pf, Wout, pp, 0, 0, 48);

    // join before reduce (needs all 8 partials)
    cudaStreamWaitEvent(0, evP, 0);
    k_reduce<<<(NRES*CS)/256, 256>>>(bout, out);
}

// round 14
// speedup vs baseline: 3.3118x; 1.0972x over previous
#include <cuda_runtime.h>
#include <math.h>

#define NRES 512
#define CS   384
#define CZ   128
#define NH   12
#define OUTD 2112
#define HF   176
#define PROJW 1152   // 192 q | 192 k | 192 v | 144 qp | 144 kp | 288 vp
#define N2   (NRES*NRES)

// ---------------- scratch ----------------
__device__ alignas(16) float g_proj[NRES*PROJW];
__device__ alignas(16) float g_vg[NRES*288];
__device__ alignas(16) float g_gA[336*NRES];
__device__ alignas(16) float g_gB[336*NRES];
__device__ alignas(16) float g_gC[NH*NRES];
__device__ alignas(16) float g_attn[(size_t)NH*NRES*NRES];   // [h][n][m]
__device__ alignas(16) float g_feats[(size_t)NRES*OUTD];
__device__ alignas(16) float g_part[(size_t)8*NRES*CS];

// ---------------- cp.async helpers ----------------
__device__ __forceinline__ void cpa16(void* dst_smem, const void* src_gmem) {
    unsigned int d = (unsigned int)__cvta_generic_to_shared(dst_smem);
    asm volatile("cp.async.ca.shared.global [%0], [%1], 16;\n" :: "r"(d), "l"(src_gmem));
}
__device__ __forceinline__ void cpa4(void* dst_smem, const void* src_gmem) {
    unsigned int d = (unsigned int)__cvta_generic_to_shared(dst_smem);
    asm volatile("cp.async.ca.shared.global [%0], [%1], 4;\n" :: "r"(d), "l"(src_gmem));
}
#define CP_COMMIT() asm volatile("cp.async.commit_group;\n" ::: "memory")
#define CP_WAIT0()  asm volatile("cp.async.wait_group 0;\n" ::: "memory")
#define CP_WAIT1()  asm volatile("cp.async.wait_group 1;\n" ::: "memory")

// ---------------- fused projection GEMM ----------------
__global__ void k_proj(const float* __restrict__ s,
    const float* __restrict__ Wq,  const float* __restrict__ bq,
    const float* __restrict__ Wk,  const float* __restrict__ bk,
    const float* __restrict__ Wv,  const float* __restrict__ bvs,
    const float* __restrict__ Wqp, const float* __restrict__ bqp,
    const float* __restrict__ Wkp, const float* __restrict__ bkp,
    const float* __restrict__ Wvp, const float* __restrict__ bvp)
{
    __shared__ alignas(16) float As[16][64];
    __shared__ alignas(16) float Bs[16][64];
    const int tid = threadIdx.x;
    const int tx = tid & 15, ty = tid >> 4;
    const int bm = blockIdx.y * 64, bn = blockIdx.x * 64;
    const int am  = tid >> 2, akq = tid & 3;
    const int bkk = tid >> 4, bn4 = tid & 15;

    const int gc = bn + bn4 * 4;
    const float* Bp; int bst;
    if (gc < 576)      { const int sg = gc / 192;
                         const float* Ws = (sg == 0) ? Wq : (sg == 1) ? Wk : Wv;
                         Bp = Ws + (gc - sg * 192); bst = 192; }
    else if (gc < 864) { const int sg = (gc - 576) / 144;
                         Bp = ((sg == 0) ? Wqp : Wkp) + (gc - 576 - sg * 144); bst = 144; }
    else               { Bp = Wvp + (gc - 864); bst = 288; }

    float acc[4][4];
#pragma unroll
    for (int i = 0; i < 4; i++)
#pragma unroll
        for (int j = 0; j < 4; j++) acc[i][j] = 0.f;

    for (int k0 = 0; k0 < CS; k0 += 16) {
        float4 av = *(const float4*)(s + (size_t)(bm + am) * CS + k0 + akq * 4);
        As[akq*4+0][am] = av.x; As[akq*4+1][am] = av.y;
        As[akq*4+2][am] = av.z; As[akq*4+3][am] = av.w;
        float4 wv4 = *(const float4*)(Bp + (size_t)(k0 + bkk) * bst);
        *(float4*)&Bs[bkk][bn4*4] = wv4;
        __syncthreads();
#pragma unroll
        for (int kk = 0; kk < 16; kk++) {
            float4 a = *(const float4*)&As[kk][ty*4];
            float4 b = *(const float4*)&Bs[kk][tx*4];
            acc[0][0]=fmaf(a.x,b.x,acc[0][0]); acc[0][1]=fmaf(a.x,b.y,acc[0][1]);
            acc[0][2]=fmaf(a.x,b.z,acc[0][2]); acc[0][3]=fmaf(a.x,b.w,acc[0][3]);
            acc[1][0]=fmaf(a.y,b.x,acc[1][0]); acc[1][1]=fmaf(a.y,b.y,acc[1][1]);
            acc[1][2]=fmaf(a.y,b.z,acc[1][2]); acc[1][3]=fmaf(a.y,b.w,acc[1][3]);
            acc[2][0]=fmaf(a.z,b.x,acc[2][0]); acc[2][1]=fmaf(a.z,b.y,acc[2][1]);
            acc[2][2]=fmaf(a.z,b.z,acc[2][2]); acc[2][3]=fmaf(a.z,b.w,acc[2][3]);
            acc[3][0]=fmaf(a.w,b.x,acc[3][0]); acc[3][1]=fmaf(a.w,b.y,acc[3][1]);
            acc[3][2]=fmaf(a.w,b.z,acc[3][2]); acc[3][3]=fmaf(a.w,b.w,acc[3][3]);
        }
        __syncthreads();
    }
    const int gc0 = bn + tx * 4;
    const float* bptr;
    if (gc0 < 576)      { const int sg = gc0 / 192;
                          bptr = ((sg == 0) ? bq : (sg == 1) ? bk : bvs) + (gc0 - sg * 192); }
    else if (gc0 < 864) { const int sg = (gc0 - 576) / 144;
                          bptr = ((sg == 0) ? bqp : bkp) + (gc0 - 576 - sg * 144); }
    else                { bptr = bvp + (gc0 - 864); }
#pragma unroll
    for (int i = 0; i < 4; i++) {
        const int row = bm + ty * 4 + i;
#pragma unroll
        for (int j = 0; j < 4; j++)
            g_proj[(size_t)row * PROJW + gc0 + j] = acc[i][j] + bptr[j];
    }
}

// ---------------- prep: frames + GEMM operands A/B/C ----------------
__global__ void k_prep(const float* __restrict__ rot, const float* __restrict__ trans,
                       const float* __restrict__ hw)
{
    const int n = blockIdx.x;
    __shared__ float R[9], T[3];
    __shared__ float kgs[144];
    if (threadIdx.x < 9) R[threadIdx.x] = rot[n*9 + threadIdx.x];
    if (threadIdx.x < 3) T[threadIdx.x] = trans[n*3 + threadIdx.x];
    __syncthreads();
    const int t = threadIdx.x;  // 0..191
    const float* row = g_proj + (size_t)n * PROJW;
    if (t < 48) {
        const float* src = row + 576 + t*3;
        const float p0 = src[0], p1 = src[1], p2 = src[2];
        const float gx = fmaf(R[0],p0, fmaf(R[1],p1, fmaf(R[2],p2, T[0])));
        const float gy = fmaf(R[3],p0, fmaf(R[4],p1, fmaf(R[5],p2, T[1])));
        const float gz = fmaf(R[6],p0, fmaf(R[7],p1, fmaf(R[8],p2, T[2])));
        const int h = t >> 2, p = t & 3;
        const float w = hw[h];
        g_gA[(h*28+16+p*3+0)*NRES + n] = w*gx;
        g_gA[(h*28+16+p*3+1)*NRES + n] = w*gy;
        g_gA[(h*28+16+p*3+2)*NRES + n] = w*gz;
    } else if (t < 96) {
        const int u = t - 48;
        const float* src = row + 720 + u*3;
        const float p0 = src[0], p1 = src[1], p2 = src[2];
        const float gx = fmaf(R[0],p0, fmaf(R[1],p1, fmaf(R[2],p2, T[0])));
        const float gy = fmaf(R[3],p0, fmaf(R[4],p1, fmaf(R[5],p2, T[1])));
        const float gz = fmaf(R[6],p0, fmaf(R[7],p1, fmaf(R[8],p2, T[2])));
        const int h = u >> 2, p = u & 3;
        g_gB[(h*28+16+p*3+0)*NRES + n] = gx;
        g_gB[(h*28+16+p*3+1)*NRES + n] = gy;
        g_gB[(h*28+16+p*3+2)*NRES + n] = gz;
        kgs[u*3+0] = gx; kgs[u*3+1] = gy; kgs[u*3+2] = gz;
    } else {
        const int u = t - 96;
        const float* src = row + 864 + u*3;
        float* dst = g_vg + n*288 + u*3;
        const float p0 = src[0], p1 = src[1], p2 = src[2];
        dst[0] = fmaf(R[0],p0, fmaf(R[1],p1, fmaf(R[2],p2, T[0])));
        dst[1] = fmaf(R[3],p0, fmaf(R[4],p1, fmaf(R[5],p2, T[1])));
        dst[2] = fmaf(R[6],p0, fmaf(R[7],p1, fmaf(R[8],p2, T[2])));
    }
    {
        const int h = t >> 4, c = t & 15;
        g_gA[(h*28+c)*NRES + n] = 0.25f * row[h*16 + c];
        g_gB[(h*28+c)*NRES + n] = row[192 + h*16 + c];
    }
    __syncthreads();
    if (t < 12) {
        float s2 = 0.f;
#pragma unroll
        for (int j = 0; j < 12; j++) s2 = fmaf(kgs[t*12+j], kgs[t*12+j], s2);
        g_gC[t*NRES + n] = -0.5f * hw[t] * s2;
    }
}

// ---------------- pair bias stream: 2 head-groups x 6 heads, c-split pairs ----------------
#define PB_WBT 0        // 1536
#define PB_EMB 1536     // 768
#define PB_PH  2304     // 36
#define PB_BB  2340     // 12
#define PB_TN  2352     // 4
#define PB_TM0 2356     // 192
#define PB_TM1 2548     // 192
#define PB_RED 2740     // 768
#define PB_Z0  3508     // 8448
#define PB_Z1  11956    // 8448
#define PB_END 20404    // 81616 B
__global__ void k_pairbias(const float* __restrict__ z, const float* __restrict__ trans,
                           const float* __restrict__ Wb, const float* __restrict__ bb,
                           const float* __restrict__ emb, const float* __restrict__ sl)
{
    extern __shared__ float sm[];
    const int n = blockIdx.x, tid = threadIdx.x;  // 256 thr

    auto pf = [&](int buf, int mc) {
        const float4* zsrc = (const float4*)(z + ((size_t)n * NRES + mc*64) * CZ);
        float* zb = sm + (buf ? PB_Z1 : PB_Z0);
        for (int i = tid; i < 2048; i += 256)
            cpa16(zb + (i >> 5)*132 + (i & 31)*4, zsrc + i);
        if (tid < 48)
            cpa16(sm + (buf ? PB_TM1 : PB_TM0) + tid*4, trans + mc*192 + tid*4);
    };
    pf(0, 0); CP_COMMIT();
    pf(1, 1); CP_COMMIT();

    for (int i = tid; i < 1536; i += 256) {
        const int h = i >> 7, c = i & 127;
        sm[PB_WBT + i] = Wb[c*NH + h];
    }
    for (int i = tid; i < 768; i += 256) sm[PB_EMB + i] = emb[i];
    if (tid < 12) {
        sm[PB_BB + tid] = bb[tid];
        const float e0 = expf(sl[tid]), e1 = expf(sl[12+tid]), e2 = expf(sl[24+tid]);
        const float inv = 1.0f / (e0 + e1 + e2);
        sm[PB_PH + tid] = e0*inv; sm[PB_PH + 12 + tid] = e1*inv; sm[PB_PH + 24 + tid] = e2*inv;
    }
    if (tid < 3) sm[PB_TN + tid] = trans[n*3 + tid];

    const int hg = tid >> 7;            // 0..1 (6 heads each)
    const int cs = (tid >> 6) & 1;      // c4 split
    const int ml = tid & 63;
    const int hb = hg * 6;

    for (int mc = 0; mc < 8; mc++) {
        if (mc < 7) CP_WAIT1(); else CP_WAIT0();
        __syncthreads();
        const int buf = mc & 1;
        const float4* zr = (const float4*)(sm + (buf ? PB_Z1 : PB_Z0) + ml*132) + cs*16;
        const float* tm = sm + (buf ? PB_TM1 : PB_TM0);

        float a[6][4];
#pragma unroll
        for (int j = 0; j < 6; j++) { a[j][0]=0.f; a[j][1]=0.f; a[j][2]=0.f; a[j][3]=0.f; }
#pragma unroll 4
        for (int c4 = 0; c4 < 16; c4++) {
            const float4 zv = zr[c4];
#pragma unroll
            for (int j = 0; j < 6; j++) {
                const float4 w = ((const float4*)(sm + PB_WBT + (hb+j)*128))[cs*16 + c4];
                a[j][0] = fmaf(zv.x, w.x, a[j][0]);
                a[j][1] = fmaf(zv.y, w.y, a[j][1]);
                a[j][2] = fmaf(zv.z, w.z, a[j][2]);
                a[j][3] = fmaf(zv.w, w.w, a[j][3]);
            }
        }
        float p[6];
#pragma unroll
        for (int j = 0; j < 6; j++) p[j] = (a[j][0]+a[j][1]) + (a[j][2]+a[j][3]);
        if (cs == 1) {
#pragma unroll
            for (int j = 0; j < 6; j++) sm[PB_RED + hg*384 + ml*6 + j] = p[j];
        }
        __syncthreads();
        if (cs == 0) {
            const float dx = sm[PB_TN+0] - tm[ml*3+0];
            const float dy = sm[PB_TN+1] - tm[ml*3+1];
            const float dz = sm[PB_TN+2] - tm[ml*3+2];
            const float dist = __fsqrt_rn(fmaf(dx,dx, fmaf(dy,dy, dz*dz)));
            int bin = (int)ceilf(dist * 2.0f) - 1;
            bin = max(0, min(63, bin));
            const int msrow = (dist <= 5.0f) ? 0 : (dist <= 15.0f) ? 12 : -1;
            const int m = mc*64 + ml;
#pragma unroll
            for (int j = 0; j < 6; j++) {
                const int h = hb + j;
                float v = sm[PB_BB + h] + p[j] + sm[PB_RED + hg*384 + ml*6 + j];
                v += sm[PB_EMB + bin*12 + h] + sm[PB_PH + 24 + h];
                if (msrow >= 0) v += sm[PB_PH + msrow + h];
                g_attn[(size_t)h*N2 + (size_t)n*NRES + m] = v;
            }
        }
        __syncthreads();
        if (mc + 2 < 8) { pf(buf, mc + 2); CP_COMMIT(); }
    }
}

// ---------------- geometry logits as batched GEMM K=28 ----------------
__global__ void k_geo()
{
    __shared__ alignas(16) float As[28][64];
    __shared__ alignas(16) float Bs[28][64];
    __shared__ alignas(16) float Cs[64];
    const int h = blockIdx.z;
    const int n0 = blockIdx.y * 64, m0 = blockIdx.x * 64;
    const int tid = threadIdx.x;
    const int tx = tid & 15, ty = tid >> 4;

    for (int i = tid; i < 1792; i += 256) {
        const int c = i >> 6, r = i & 63;
        As[c][r] = g_gA[(size_t)(h*28+c)*NRES + n0 + r];
        Bs[c][r] = g_gB[(size_t)(h*28+c)*NRES + m0 + r];
    }
    if (tid < 64) Cs[tid] = g_gC[h*NRES + m0 + tid];
    __syncthreads();

    float acc[4][4];
#pragma unroll
    for (int i = 0; i < 4; i++)
#pragma unroll
        for (int j = 0; j < 4; j++) acc[i][j] = 0.f;

#pragma unroll
    for (int c = 0; c < 28; c++) {
        const float4 a = *(const float4*)&As[c][ty*4];
        const float4 b = *(const float4*)&Bs[c][tx*4];
        acc[0][0]=fmaf(a.x,b.x,acc[0][0]); acc[0][1]=fmaf(a.x,b.y,acc[0][1]);
        acc[0][2]=fmaf(a.x,b.z,acc[0][2]); acc[0][3]=fmaf(a.x,b.w,acc[0][3]);
        acc[1][0]=fmaf(a.y,b.x,acc[1][0]); acc[1][1]=fmaf(a.y,b.y,acc[1][1]);
        acc[1][2]=fmaf(a.y,b.z,acc[1][2]); acc[1][3]=fmaf(a.y,b.w,acc[1][3]);
        acc[2][0]=fmaf(a.z,b.x,acc[2][0]); acc[2][1]=fmaf(a.z,b.y,acc[2][1]);
        acc[2][2]=fmaf(a.z,b.z,acc[2][2]); acc[2][3]=fmaf(a.z,b.w,acc[2][3]);
        acc[3][0]=fmaf(a.w,b.x,acc[3][0]); acc[3][1]=fmaf(a.w,b.y,acc[3][1]);
        acc[3][2]=fmaf(a.w,b.z,acc[3][2]); acc[3][3]=fmaf(a.w,b.w,acc[3][3]);
    }
    const float4 cv = *(const float4*)&Cs[tx*4];
#pragma unroll
    for (int i = 0; i < 4; i++) {
        float4* gp = (float4*)(g_attn + (size_t)h*N2 + (size_t)(n0 + ty*4 + i)*NRES + m0 + tx*4);
        float4 o = *gp;
        o.x += acc[i][0] + cv.x;
        o.y += acc[i][1] + cv.y;
        o.z += acc[i][2] + cv.z;
        o.w += acc[i][3] + cv.w;
        *gp = o;
    }
}

// ---------------- softmax over m ----------------
__global__ void k_softmax()
{
    const int n = blockIdx.x;
    const int h = threadIdx.x >> 5, lane = threadIdx.x & 31;   // 384 thr
    float* p = g_attn + (size_t)h*N2 + (size_t)n*NRES;
    float v[16];
    float mx = -1e30f;
#pragma unroll
    for (int i = 0; i < 16; i++) { v[i] = p[lane + 32*i]; mx = fmaxf(mx, v[i]); }
#pragma unroll
    for (int o = 16; o; o >>= 1) mx = fmaxf(mx, __shfl_xor_sync(0xffffffffu, mx, o));
    float sum = 0.f;
#pragma unroll
    for (int i = 0; i < 16; i++) { v[i] = __expf(v[i] - mx); sum += v[i]; }
#pragma unroll
    for (int o = 16; o; o >>= 1) sum += __shfl_xor_sync(0xffffffffu, sum, o);
    const float inv = 1.0f / sum;
#pragma unroll
    for (int i = 0; i < 16; i++) p[lane + 32*i] = v[i] * inv;
}

// ---------------- pair_feat: warp = (head-group of 4, m-slice), 1 z-LDS per 16 FMA ----
#define PF_Z0 0       // 4096
#define PF_Z1 4096    // 4096
#define PF_A0 8192    // 384
#define PF_A1 8576    // 384
#define PF_PF 8960    // 1536
#define PF_END 10496  // 41984 B
__global__ void k_pairfeat(const float* __restrict__ z)
{
    extern __shared__ float sm[];
    const int n = blockIdx.x, tid = threadIdx.x;  // 384 thr = 12 warps
    const int wid = tid >> 5, lane = tid & 31;
    const int hg = wid >> 2;          // 0..2 (4 heads each)
    const int ms = wid & 3;           // m-slice

    const float4* zsrc = (const float4*)(z + (size_t)n * NRES * CZ);

    auto pfl = [&](int buf, int mc) {
        float* zb = sm + (buf ? PF_Z1 : PF_Z0);
        for (int i = tid; i < 1024; i += 384)
            cpa16(zb + i*4, zsrc + mc*1024 + i);
        {   // 384 attn scalars: [h][mm]
            const int h = tid >> 5, mm = tid & 31;
            cpa4(sm + (buf ? PF_A1 : PF_A0) + h*32 + mm,
                 g_attn + (size_t)h*N2 + (size_t)n*NRES + mc*32 + mm);
        }
    };
    pfl(0, 0); CP_COMMIT();
    pfl(1, 1); CP_COMMIT();

    float acc[4][4];
#pragma unroll
    for (int i = 0; i < 4; i++)
#pragma unroll
        for (int j = 0; j < 4; j++) acc[i][j] = 0.f;

    for (int mc = 0; mc < 16; mc++) {
        if (mc < 15) CP_WAIT1(); else CP_WAIT0();
        __syncthreads();
        const int buf = mc & 1;
        const float* zc = sm + (buf ? PF_Z1 : PF_Z0);
        const float* ac = sm + (buf ? PF_A1 : PF_A0);
#pragma unroll
        for (int j = 0; j < 8; j++) {
            const int m = ms*8 + j;
            const float4 zv = *(const float4*)(zc + m*128 + lane*4);
            const float w0 = ac[(hg*4+0)*32 + m];
            const float w1 = ac[(hg*4+1)*32 + m];
            const float w2 = ac[(hg*4+2)*32 + m];
            const float w3 = ac[(hg*4+3)*32 + m];
            acc[0][0]=fmaf(w0,zv.x,acc[0][0]); acc[0][1]=fmaf(w0,zv.y,acc[0][1]);
            acc[0][2]=fmaf(w0,zv.z,acc[0][2]); acc[0][3]=fmaf(w0,zv.w,acc[0][3]);
            acc[1][0]=fmaf(w1,zv.x,acc[1][0]); acc[1][1]=fmaf(w1,zv.y,acc[1][1]);
            acc[1][2]=fmaf(w1,zv.z,acc[1][2]); acc[1][3]=fmaf(w1,zv.w,acc[1][3]);
            acc[2][0]=fmaf(w2,zv.x,acc[2][0]); acc[2][1]=fmaf(w2,zv.y,acc[2][1]);
            acc[2][2]=fmaf(w2,zv.z,acc[2][2]); acc[2][3]=fmaf(w2,zv.w,acc[2][3]);
            acc[3][0]=fmaf(w3,zv.x,acc[3][0]); acc[3][1]=fmaf(w3,zv.y,acc[3][1]);
            acc[3][2]=fmaf(w3,zv.z,acc[3][2]); acc[3][3]=fmaf(w3,zv.w,acc[3][3]);
        }
        __syncthreads();
        if (mc + 2 < 16) { pfl(buf, mc + 2); CP_COMMIT(); }
    }

    // reduce over the 4 m-slices into PF_PF [12h][128c]
    float4* pf4 = (float4*)(sm + PF_PF);
#pragma unroll
    for (int r = 0; r < 4; r++) {
        if (ms == r) {
#pragma unroll
            for (int hh = 0; hh < 4; hh++) {
                const int fi = (hg*4 + hh)*32 + lane;
                if (r == 0) {
                    pf4[fi] = make_float4(acc[hh][0], acc[hh][1], acc[hh][2], acc[hh][3]);
                } else {
                    float4 v = pf4[fi];
                    v.x += acc[hh][0]; v.y += acc[hh][1];
                    v.z += acc[hh][2]; v.w += acc[hh][3];
                    pf4[fi] = v;
                }
            }
        }
        __syncthreads();
    }
    {   // writeout: 384 float4s
        const int h = tid >> 5, cq = tid & 31;
        *(float4*)(g_feats + (size_t)n*OUTD + h*HF + 48 + cq*4) = pf4[tid];
    }
}

// ---------------- out_scalar + out_pts(local) + norms; 4 n per block ----------------
#define OV_AT 0        // 12*128 [h][m][ni]
#define OV_V  1536     // 6144
#define OV_VG 7680     // 9216
#define OV_PG 16896    // 4*288
#define OV_END 18048
__global__ void k_outv(const float* __restrict__ rot, const float* __restrict__ trans)
{
    extern __shared__ float sm[];
    const int n0 = blockIdx.x * 4, tid = threadIdx.x;  // 480 thr, grid 128
    float acc0=0.f, acc1=0.f, acc2=0.f, acc3=0.f;

    for (int mc = 0; mc < 16; mc++) {
        const int m0 = mc * 32;
        __syncthreads();
        for (int i = tid; i < 1536; i += 480) {
            const int hh = i >> 7, r = i & 127;
            const int ni = r >> 5, mm = r & 31;
            sm[OV_AT + hh*128 + mm*4 + ni] =
                g_attn[(size_t)hh*N2 + (size_t)(n0+ni)*NRES + m0 + mm];
        }
        for (int i = tid; i < 1536; i += 480) {
            const int mm = i / 48, q = i - mm*48;
            cpa16(sm + OV_V + mm*192 + q*4, g_proj + (size_t)(m0+mm)*PROJW + 384 + q*4);
        }
        for (int i = tid; i < 2304; i += 480)
            cpa16(sm + OV_VG + i*4, g_vg + m0*288 + i*4);
        CP_COMMIT(); CP_WAIT0();
        __syncthreads();

        if (tid < 192) {
            const int hh = tid >> 4, c = tid & 15;
            const float* vs = sm + OV_V + hh*16 + c;
            const float4* at4 = (const float4*)(sm + OV_AT + hh*128);
#pragma unroll
            for (int mm = 0; mm < 32; mm++) {
                const float4 w = at4[mm];
                const float vv = vs[mm*192];
                acc0 = fmaf(w.x, vv, acc0);
                acc1 = fmaf(w.y, vv, acc1);
                acc2 = fmaf(w.z, vv, acc2);
                acc3 = fmaf(w.w, vv, acc3);
            }
        } else {
            const int idx = tid - 192, hh = idx / 24, u = idx - hh*24;
            const float* vs = sm + OV_VG + hh*24 + u;
            const float4* at4 = (const float4*)(sm + OV_AT + hh*128);
#pragma unroll
            for (int mm = 0; mm < 32; mm++) {
                const float4 w = at4[mm];
                const float vv = vs[mm*288];
                acc0 = fmaf(w.x, vv, acc0);
                acc1 = fmaf(w.y, vv, acc1);
                acc2 = fmaf(w.z, vv, acc2);
                acc3 = fmaf(w.w, vv, acc3);
            }
        }
    }
    __syncthreads();
    if (tid < 192) {
        const int hh = tid >> 4, c = tid & 15;
        g_feats[(size_t)(n0+0)*OUTD + hh*HF + c] = acc0;
        g_feats[(size_t)(n0+1)*OUTD + hh*HF + c] = acc1;
        g_feats[(size_t)(n0+2)*OUTD + hh*HF + c] = acc2;
        g_feats[(size_t)(n0+3)*OUTD + hh*HF + c] = acc3;
    } else {
        const int idx = tid - 192;
        sm[OV_PG + 0*288 + idx] = acc0;
        sm[OV_PG + 1*288 + idx] = acc1;
        sm[OV_PG + 2*288 + idx] = acc2;
        sm[OV_PG + 3*288 + idx] = acc3;
    }
    __syncthreads();
    if (tid < 384) {
        const int ni = tid / 96, r = tid - ni*96;
        const int hh = r / 8, p = r - hh*8;
        const int n = n0 + ni;
        float R[9];
#pragma unroll
        for (int i = 0; i < 9; i++) R[i] = rot[n*9 + i];
        const float gx = sm[OV_PG + ni*288 + hh*24 + p*3 + 0] - trans[n*3 + 0];
        const float gy = sm[OV_PG + ni*288 + hh*24 + p*3 + 1] - trans[n*3 + 1];
        const float gz = sm[OV_PG + ni*288 + hh*24 + p*3 + 2] - trans[n*3 + 2];
        const float lx = fmaf(R[0],gx, fmaf(R[3],gy, R[6]*gz));
        const float ly = fmaf(R[1],gx, fmaf(R[4],gy, R[7]*gz));
        const float lz = fmaf(R[2],gx, fmaf(R[5],gy, R[8]*gz));
        float* f = g_feats + (size_t)n*OUTD + hh*HF;
        f[16 + p*3 + 0] = lx; f[16 + p*3 + 1] = ly; f[16 + p*3 + 2] = lz;
        f[40 + p] = __fsqrt_rn(fmaf(lx,lx, fmaf(ly,ly, lz*lz)));
    }
}

// ---------------- selective-K GEMM over per-head column ranges ----------------
__global__ void k_sgemm_sel(const float* __restrict__ A, const float* __restrict__ B,
                            float* __restrict__ C, int pbase, int kbase, int klen)
{
    __shared__ alignas(16) float As[16][64];
    __shared__ alignas(16) float Bs[16][64];
    const int tid = threadIdx.x;
    const int tx = tid & 15, ty = tid >> 4;
    const int bm = blockIdx.y * 64, bn = blockIdx.x * 64;
    const int hb = blockIdx.z * 3;
    C += (size_t)(pbase + blockIdx.z) * NRES * CS;

    const int am  = tid >> 2, akq = tid & 3;
    const int bkk = tid >> 4, bn4 = tid & 15;

    float acc[4][4];
#pragma unroll
    for (int i = 0; i < 4; i++)
#pragma unroll
        for (int j = 0; j < 4; j++) acc[i][j] = 0.f;

    for (int hh = hb; hh < hb + 3; hh++) {
        const int kc0 = hh * HF + kbase;
        for (int kt = 0; kt < klen; kt += 16) {
            const int kc = kc0 + kt;
            float4 av = *(const float4*)(A + (size_t)(bm + am) * OUTD + kc + akq * 4);
            As[akq*4+0][am] = av.x; As[akq*4+1][am] = av.y;
            As[akq*4+2][am] = av.z; As[akq*4+3][am] = av.w;
            float4 bv = *(const float4*)(B + (size_t)(kc + bkk) * CS + bn + bn4 * 4);
            *(float4*)&Bs[bkk][bn4*4] = bv;
            __syncthreads();
#pragma unroll
            for (int kk = 0; kk < 16; kk++) {
                float4 a = *(const float4*)&As[kk][ty*4];
                float4 b = *(const float4*)&Bs[kk][tx*4];
                acc[0][0]=fmaf(a.x,b.x,acc[0][0]); acc[0][1]=fmaf(a.x,b.y,acc[0][1]);
                acc[0][2]=fmaf(a.x,b.z,acc[0][2]); acc[0][3]=fmaf(a.x,b.w,acc[0][3]);
                acc[1][0]=fmaf(a.y,b.x,acc[1][0]); acc[1][1]=fmaf(a.y,b.y,acc[1][1]);
                acc[1][2]=fmaf(a.y,b.z,acc[1][2]); acc[1][3]=fmaf(a.y,b.w,acc[1][3]);
                acc[2][0]=fmaf(a.z,b.x,acc[2][0]); acc[2][1]=fmaf(a.z,b.y,acc[2][1]);
                acc[2][2]=fmaf(a.z,b.z,acc[2][2]); acc[2][3]=fmaf(a.z,b.w,acc[2][3]);
                acc[3][0]=fmaf(a.w,b.x,acc[3][0]); acc[3][1]=fmaf(a.w,b.y,acc[3][1]);
                acc[3][2]=fmaf(a.w,b.z,acc[3][2]); acc[3][3]=fmaf(a.w,b.w,acc[3][3]);
            }
            __syncthreads();
        }
    }
#pragma unroll
    for (int i = 0; i < 4; i++) {
        const int row = bm + ty * 4 + i;
#pragma unroll
        for (int j = 0; j < 4; j++)
            C[(size_t)row * CS + bn + tx * 4 + j] = acc[i][j];
    }
}

// ---------------- reduce 8 partials + bias ----------------
__global__ void k_reduce(const float* __restrict__ bout, float* __restrict__ out)
{
    const int i = blockIdx.x * 256 + threadIdx.x;
    const int NE = NRES * CS;
    float v = 0.f;
#pragma unroll
    for (int p = 0; p < 8; p++) v += g_part[(size_t)p*NE + i];
    out[i] = v + bout[i % CS];
}

// ---------------- launch ----------------
static float* symaddr(const void* sym) {
    void* p = nullptr;
    cudaGetSymbolAddress(&p, sym);
    return (float*)p;
}

extern "C" void kernel_launch(void* const* d_in, const int* in_sizes, int n_in,
                              void* d_out, int out_size) {
    const float* s     = (const float*)d_in[0];
    const float* z     = (const float*)d_in[1];
    const float* trans = (const float*)d_in[2];
    const float* rot   = (const float*)d_in[3];
    const float* Wq    = (const float*)d_in[4];
    const float* bq    = (const float*)d_in[5];
    const float* Wk    = (const float*)d_in[6];
    const float* bk    = (const float*)d_in[7];
    const float* Wv    = (const float*)d_in[8];
    const float* bv    = (const float*)d_in[9];
    const float* Wqp   = (const float*)d_in[10];
    const float* bqp   = (const float*)d_in[11];
    const float* Wkp   = (const float*)d_in[12];
    const float* bkp   = (const float*)d_in[13];
    const float* Wvp   = (const float*)d_in[14];
    const float* bvp   = (const float*)d_in[15];
    const float* Wb    = (const float*)d_in[16];
    const float* bb    = (const float*)d_in[17];
    const float* emb   = (const float*)d_in[18];
    const float* sl    = (const float*)d_in[19];
    const float* hw    = (const float*)d_in[20];
    const float* Wout  = (const float*)d_in[21];
    const float* bout  = (const float*)d_in[22];
    float* out = (float*)d_out;

    float* pf = symaddr(g_feats);
    float* pp = symaddr(g_part);

    static cudaStream_t s2 = nullptr;
    static cudaEvent_t evFork = nullptr, evZ = nullptr, evS = nullptr, evP = nullptr;
    if (!s2) {
        cudaStreamCreateWithFlags(&s2, cudaStreamNonBlocking);
        cudaEventCreateWithFlags(&evFork, cudaEventDisableTiming);
        cudaEventCreateWithFlags(&evZ,    cudaEventDisableTiming);
        cudaEventCreateWithFlags(&evS,    cudaEventDisableTiming);
        cudaEventCreateWithFlags(&evP,    cudaEventDisableTiming);
        cudaFuncSetAttribute(k_pairbias, cudaFuncAttributeMaxDynamicSharedMemorySize, PB_END * (int)sizeof(float));
        cudaFuncSetAttribute(k_pairfeat, cudaFuncAttributeMaxDynamicSharedMemorySize, PF_END * (int)sizeof(float));
        cudaFuncSetAttribute(k_outv,     cudaFuncAttributeMaxDynamicSharedMemorySize, OV_END * (int)sizeof(float));
    }

    // fork: z-path (pairbias) on s2 concurrent with s-path (proj->prep) on default
    cudaEventRecord(evFork, 0);
    cudaStreamWaitEvent(s2, evFork, 0);
    k_pairbias<<<NRES, 256, PB_END * sizeof(float), s2>>>(z, trans, Wb, bb, emb, sl);
    cudaEventRecord(evZ, s2);

    k_proj<<<dim3(18,8,1), 256>>>(s, Wq,bq, Wk,bk, Wv,bv, Wqp,bqp, Wkp,bkp, Wvp,bvp);
    k_prep<<<NRES, 192>>>(rot, trans, hw);

    // join: geo RMWs attn (needs pairbias) and reads prep outputs
    cudaStreamWaitEvent(0, evZ, 0);
    k_geo<<<dim3(8,8,12), 256>>>();
    k_softmax<<<NRES, 384>>>();
    cudaEventRecord(evS, 0);

    // fork: pairfeat (z-stream) + its GEMM on s2, concurrent with outv + its GEMM
    cudaStreamWaitEvent(s2, evS, 0);
    k_pairfeat<<<NRES, 384, PF_END * sizeof(float), s2>>>(z);
    k_sgemm_sel<<<dim3(6,8,4), 256, 0, s2>>>(pf, Wout, pp, 4, 48, 128);
    cudaEventRecord(evP, s2);

    k_outv<<<128, 480, OV_END * sizeof(float)>>>(rot, trans);
    k_sgemm_sel<<<dim3(6,8,4), 256>>>(pf, Wout, pp, 0, 0, 48);

    // join before reduce (needs all 8 partials)
    cudaStreamWaitEvent(0, evP, 0);
    k_reduce<<<(NRES*CS)/256, 256>>>(bout, out);
}